// round 8
// baseline (speedup 1.0000x reference)
#include <cuda_runtime.h>
#include <cuda_bf16.h>
#include <math.h>
#include <stdint.h>

#define B_  4
#define T_  2048
#define D_  1024
#define NH_ 16
#define HS_ 64
#define NBIAS (2*T_ - 1)   // 4095
#define M_  (B_*T_)        // 8192
#define K2_ 2048           // split-bf16 storage: [hi | lo]

// ---------------- scratch (device globals: no allocation allowed) ----------
__device__ __nv_bfloat16 g_A2 [M_*(size_t)K2_];    // queries split [hi|lo]
__device__ __nv_bfloat16 g_AO2[M_*(size_t)K2_];    // attn-out split [hi|lo]
__device__ __nv_bfloat16 g_W2 [4*(size_t)D_*K2_];  // weights split [hi|lo]
__device__ __nv_bfloat16 g_QKV2[3*(size_t)NH_*B_*T_*2*HS_];  // [z][bh][t][seg][hs]
__device__ float g_bias[NH_*NBIAS];

#define TQOFF ((size_t)NH_*B_*T_*2*HS_)    // per-tensor offset in g_QKV2

// ============================ PTX helpers ==================================
__device__ __forceinline__ uint32_t smem_u32(const void* p) {
    uint32_t a;
    asm("{ .reg .u64 t; cvta.to.shared.u64 t, %1; cvt.u32.u64 %0, t; }" : "=r"(a) : "l"(p));
    return a;
}
#define CP_ASYNC16(dst, src) \
    asm volatile("cp.async.cg.shared.global [%0], [%1], 16;" :: "r"(dst), "l"(src) : "memory")
#define CP_COMMIT() asm volatile("cp.async.commit_group;" ::: "memory")
#define CP_WAIT1()  asm volatile("cp.async.wait_group 1;" ::: "memory")

#define LDMATRIX_X4(r0, r1, r2, r3, addr) \
    asm volatile("ldmatrix.sync.aligned.m8n8.x4.shared.b16 {%0,%1,%2,%3}, [%4];" \
                 : "=r"(r0), "=r"(r1), "=r"(r2), "=r"(r3) : "r"(addr))
#define LDMATRIX_X4_T(r0, r1, r2, r3, addr) \
    asm volatile("ldmatrix.sync.aligned.m8n8.x4.trans.shared.b16 {%0,%1,%2,%3}, [%4];" \
                 : "=r"(r0), "=r"(r1), "=r"(r2), "=r"(r3) : "r"(addr))

#define MMA_BF16(c, a, b0, b1) \
    asm volatile("mma.sync.aligned.m16n8k16.row.col.f32.bf16.bf16.f32 " \
                 "{%0,%1,%2,%3}, {%4,%5,%6,%7}, {%8,%9}, {%0,%1,%2,%3};" \
                 : "+f"((c)[0]), "+f"((c)[1]), "+f"((c)[2]), "+f"((c)[3]) \
                 : "r"((a)[0]), "r"((a)[1]), "r"((a)[2]), "r"((a)[3]), "r"(b0), "r"(b1))

__device__ __forceinline__ void split2(float a, float b, uint32_t& hi, uint32_t& lo) {
    __nv_bfloat16 ha = __float2bfloat16_rn(a), hb = __float2bfloat16_rn(b);
    float la = a - __bfloat162float(ha), lb = b - __bfloat162float(hb);
    __nv_bfloat162 hv = __halves2bfloat162(ha, hb);
    __nv_bfloat162 lv = __halves2bfloat162(__float2bfloat16_rn(la), __float2bfloat16_rn(lb));
    hi = *(uint32_t*)&hv;
    lo = *(uint32_t*)&lv;
}

// ================== bias table =============================================
__device__ __forceinline__ int bucket_of(int rp) {
    int b = (rp > 0) ? 16 : 0;
    int a = rp < 0 ? -rp : rp;
    if (a < 8) return b + a;
    double v = 7.0 + (log((double)a / 7.0) / log(128.0 / 7.0)) * 8.0;
    int large = (int)v;
    if (large > 15) large = 15;
    return b + large;
}
__global__ void bias_kernel(const float* __restrict__ rel_emb, float* __restrict__ btab) {
    int idx = blockIdx.x * blockDim.x + threadIdx.x;
    if (idx >= NH_ * NBIAS) return;
    int h = idx / NBIAS;
    int x = idx % NBIAS;
    btab[idx] = rel_emb[bucket_of(x - (T_ - 1)) * NH_ + h];
}

// ================== fp32 -> [hi | lo] split-bf16 ===========================
__global__ void split2_kernel(const float* __restrict__ in, __nv_bfloat16* __restrict__ out,
                              int nrows) {
    int i = blockIdx.x * blockDim.x + threadIdx.x;
    if (i >= nrows * (D_ / 4)) return;
    int r = i / (D_ / 4);
    int c = (i % (D_ / 4)) * 4;
    float4 v = *(const float4*)(in + (size_t)r * D_ + c);
    uint32_t h0, l0, h1, l1;
    split2(v.x, v.y, h0, l0);
    split2(v.z, v.w, h1, l1);
    uint32_t* sh = (uint32_t*)(out + (size_t)r * K2_ + c);
    sh[0] = h0; sh[1] = h1;
    uint32_t* sl = (uint32_t*)(out + (size_t)r * K2_ + D_ + c);
    sl[0] = l0; sl[1] = l1;
}

// ================== HMMA bf16 GEMM v4 (operand reuse) ======================
// out[m,n] = sum_{k<1024} Ah*Bh + Ah*Bl + Al*Bh  (each bf16 pair from [hi|lo])
// SPLITOUT=1: write split-bf16 [z][bh][t][seg][hs] (Q scaled by 1/8).
// SPLITOUT=0: write fp32 row-major [m, n].
#define GS4 3
#define TB4 8192
#define ST4 (4 * TB4)               // 32KB per stage
#define GEMM4_SMEM (GS4 * ST4)      // 96KB
#define GIT4 32
#define WOFF2 ((size_t)D_ * K2_)

template <int SPLITOUT>
__global__ __launch_bounds__(256, 2)
void gemm_hmma4(const __nv_bfloat16* __restrict__ A, const __nv_bfloat16* __restrict__ W0,
                float* __restrict__ outf, __nv_bfloat16* __restrict__ outq) {
    extern __shared__ char sm4[];
    const uint32_t sb = smem_u32(sm4);

    const int tid  = threadIdx.x;
    const int w    = tid >> 5;
    const int lane = tid & 31;
    const int wm   = w & 1;            // 64-row half
    const int wn   = w >> 1;           // 32-col quarter
    const int m0   = blockIdx.y * 128;
    const int n0   = blockIdx.x * 128;
    const int z    = blockIdx.z;
    const __nv_bfloat16* W = W0 + (size_t)z * WOFF2;

    float acc[4][4][4];
#pragma unroll
    for (int i = 0; i < 4; i++)
#pragma unroll
        for (int j = 0; j < 4; j++)
#pragma unroll
            for (int q = 0; q < 4; q++) acc[i][j][q] = 0.f;

    auto load_stage = [&](int it) {
        const uint32_t st = sb + (uint32_t)(it % GS4) * ST4;
        const int kb = it * 32;
#pragma unroll
        for (int j = 0; j < 2; j++) {
            int idx = tid * 2 + j;
            int row = idx >> 2, u = idx & 3;
            uint32_t off = row * 64 + ((u ^ ((row >> 1) & 3)) << 4);
            const __nv_bfloat16* ar = A + (size_t)(m0 + row) * K2_ + kb + u * 8;
            const __nv_bfloat16* wr = W + (size_t)(n0 + row) * K2_ + kb + u * 8;
            CP_ASYNC16(st + off,           (const void*)ar);          // Ah
            CP_ASYNC16(st + TB4 + off,     (const void*)(ar + D_));   // Al
            CP_ASYNC16(st + 2 * TB4 + off, (const void*)wr);          // Bh
            CP_ASYNC16(st + 3 * TB4 + off, (const void*)(wr + D_));   // Bl
        }
        CP_COMMIT();
    };

    load_stage(0);
    load_stage(1);

    for (int it = 0; it < GIT4; it++) {
        CP_WAIT1();
        __syncthreads();
        if (it + 2 < GIT4) load_stage(it + 2);
        else CP_COMMIT();

        const uint32_t aH = sb + (uint32_t)(it % GS4) * ST4;
        const uint32_t aL = aH + TB4;
        const uint32_t bH = aH + 2 * TB4;
        const uint32_t bL = aH + 3 * TB4;

#pragma unroll
        for (int ks = 0; ks < 2; ks++) {
            uint32_t ah[4][4], al[4][4];
#pragma unroll
            for (int fm = 0; fm < 4; fm++) {
                int row = wm * 64 + fm * 16 + (lane & 15);
                int u = ks * 2 + (lane >> 4);
                uint32_t off = row * 64 + ((u ^ ((row >> 1) & 3)) << 4);
                LDMATRIX_X4(ah[fm][0], ah[fm][1], ah[fm][2], ah[fm][3], aH + off);
                LDMATRIX_X4(al[fm][0], al[fm][1], al[fm][2], al[fm][3], aL + off);
            }
            uint32_t bh[2][4], bl[2][4];
#pragma unroll
            for (int fp = 0; fp < 2; fp++) {
                int n = wn * 32 + fp * 16 + (lane & 7) + ((lane >> 4) << 3);
                int u = ks * 2 + ((lane >> 3) & 1);
                uint32_t off = n * 64 + ((u ^ ((n >> 1) & 3)) << 4);
                LDMATRIX_X4(bh[fp][0], bh[fp][1], bh[fp][2], bh[fp][3], bH + off);
                LDMATRIX_X4(bl[fp][0], bl[fp][1], bl[fp][2], bl[fp][3], bL + off);
            }
#pragma unroll
            for (int fm = 0; fm < 4; fm++)
#pragma unroll
                for (int fp = 0; fp < 2; fp++) {
                    MMA_BF16(acc[fm][fp * 2 + 0], ah[fm], bh[fp][0], bh[fp][1]);
                    MMA_BF16(acc[fm][fp * 2 + 1], ah[fm], bh[fp][2], bh[fp][3]);
                    MMA_BF16(acc[fm][fp * 2 + 0], ah[fm], bl[fp][0], bl[fp][1]);
                    MMA_BF16(acc[fm][fp * 2 + 1], ah[fm], bl[fp][2], bl[fp][3]);
                    MMA_BF16(acc[fm][fp * 2 + 0], al[fm], bh[fp][0], bh[fp][1]);
                    MMA_BF16(acc[fm][fp * 2 + 1], al[fm], bh[fp][2], bh[fp][3]);
                }
        }
    }

    const int cr = lane >> 2;
    const int cc = 2 * (lane & 3);
    const float sc = (SPLITOUT && z == 0) ? 0.125f : 1.f;   // pre-scale Q by 1/sqrt(64)
#pragma unroll
    for (int fm = 0; fm < 4; fm++) {
        int r = m0 + wm * 64 + fm * 16 + cr;
#pragma unroll
        for (int fn = 0; fn < 4; fn++) {
            int col = n0 + wn * 32 + fn * 8 + cc;
            if (SPLITOUT) {
                int bb = r >> 11, t = r & (T_ - 1);
                int hh = col >> 6, hs = col & 63;
                size_t base = (((size_t)z * 64 + bb * NH_ + hh) * T_ + t) * 128 + hs;
                uint32_t hi, lo;
                split2(acc[fm][fn][0] * sc, acc[fm][fn][1] * sc, hi, lo);
                *(uint32_t*)(outq + base)        = hi;     // seg0 (hi)
                *(uint32_t*)(outq + base + 64)   = lo;     // seg1 (lo)
                split2(acc[fm][fn][2] * sc, acc[fm][fn][3] * sc, hi, lo);
                *(uint32_t*)(outq + base + 1024)      = hi;  // row t+8
                *(uint32_t*)(outq + base + 1024 + 64) = lo;
            } else {
                *(float2*)(outf + (size_t)r * D_ + col) =
                    make_float2(acc[fm][fn][0], acc[fm][fn][1]);
                *(float2*)(outf + (size_t)(r + 8) * D_ + col) =
                    make_float2(acc[fm][fn][2], acc[fm][fn][3]);
            }
        }
    }
}

// ================== HMMA flash attention (cp.async pipelined) ==============
// Q/K/V already split-bf16 in gmem: [bh][t][seg][hs].
// SMEM: Q 32KB @0; K+V double buffer: stage s @ 32768 + s*32768
//       (K: 64 rows x 256B; V: 128 rows x 128B [seg*64+key]).
#define QT 128
#define KT 64
#define ASM_Q 0u
#define ASM_KV 32768u
#define KVST 32768u
#define ATTN_SMEM (32768 + 2 * 32768)   // 96KB
#define NKT (T_ / KT)                   // 32

__global__ __launch_bounds__(256, 2)
void attn_hmma(const __nv_bfloat16* __restrict__ QKV, const float* __restrict__ btab,
               __nv_bfloat16* __restrict__ out2) {
    extern __shared__ char sm[];
    const uint32_t sb = smem_u32(sm);

    const int tid  = threadIdx.x;
    const int w    = tid >> 5;
    const int lane = tid & 31;
    const int bh = blockIdx.y;
    const int h  = bh & (NH_ - 1);
    const int b  = bh >> 4;
    const int q0 = blockIdx.x * QT;

    const __nv_bfloat16* Qq = QKV + (size_t)bh * T_ * 128;
    const __nv_bfloat16* Kq = QKV + TQOFF + (size_t)bh * T_ * 128;
    const __nv_bfloat16* Vq = QKV + 2 * TQOFF + (size_t)bh * T_ * 128;
    const float* bias_h = btab + h * NBIAS + (T_ - 1);

    // ---- Q preload (group 1) ----
#pragma unroll
    for (int j = 0; j < 8; j++) {
        int idx = tid * 8 + j;                    // 0..2047
        int row = idx >> 4, rem = idx & 15, seg = rem >> 3, u = rem & 7;
        uint32_t dst = sb + ASM_Q + row * 256 + seg * 128 + (((u ^ row) & 7) << 4);
        CP_ASYNC16(dst, (const void*)(Qq + (size_t)(q0 + row) * 128 + seg * 64 + u * 8));
    }
    CP_COMMIT();

    // ---- K/V stage loader ----
    auto load_kv = [&](int t) {
        const uint32_t st = sb + ASM_KV + (uint32_t)(t & 1) * KVST;
        const int k0 = t * KT;
#pragma unroll
        for (int j = 0; j < 4; j++) {
            int idx = tid * 4 + j;                // 0..1023
            int row = idx >> 4, rem = idx & 15, seg = rem >> 3, u = rem & 7;
            const size_t goff = (size_t)(k0 + row) * 128 + seg * 64 + u * 8;
            uint32_t kd = st + row * 256 + seg * 128 + (((u ^ row) & 7) << 4);
            CP_ASYNC16(kd, (const void*)(Kq + goff));
            uint32_t vd = st + 16384 + (seg * 64 + row) * 128 + (((u ^ (row & 7)) & 7) << 4);
            CP_ASYNC16(vd, (const void*)(Vq + goff));
        }
        CP_COMMIT();
    };

    load_kv(0);
    load_kv(1);

    float ofr[8][4];
    float mrow[2] = {-1e30f, -1e30f};
    float lrow[2] = {0.f, 0.f};
#pragma unroll
    for (int j = 0; j < 8; j++)
#pragma unroll
        for (int q = 0; q < 4; q++) ofr[j][q] = 0.f;

    for (int t = 0; t < NKT; t++) {
        CP_WAIT1();                    // Q + stage t complete (stage t+1 may be pending)
        __syncthreads();

        const uint32_t kB = sb + ASM_KV + (uint32_t)(t & 1) * KVST;
        const uint32_t vB = kB + 16384;
        const int k0 = t * KT;

        // ---- S = (Q/8) K^T via 3-term split ----
        float sf[8][4];
#pragma unroll
        for (int j = 0; j < 8; j++)
#pragma unroll
            for (int q = 0; q < 4; q++) sf[j][q] = 0.f;

#pragma unroll
        for (int u = 0; u < 4; u++) {
            uint32_t ah[4], al[4];
            {
                int row = w * 16 + (lane & 15);
                int uh = 2 * u + (lane >> 4);
                uint32_t adh = sb + ASM_Q + row * 256 + (((uh ^ row) & 7) << 4);
                LDMATRIX_X4(ah[0], ah[1], ah[2], ah[3], adh);
                int ul = 8 + 2 * u + (lane >> 4);
                uint32_t adl = sb + ASM_Q + row * 256 + ((8 | ((ul ^ row) & 7)) << 4);
                LDMATRIX_X4(al[0], al[1], al[2], al[3], adl);
            }
#pragma unroll
            for (int fp = 0; fp < 4; fp++) {
                int n = fp * 16 + (lane & 7) + ((lane >> 4) << 3);
                int uh = 2 * u + ((lane >> 3) & 1);
                uint32_t bh_[4], bl_[4];
                uint32_t bdh = kB + n * 256 + (((uh ^ n) & 7) << 4);
                LDMATRIX_X4(bh_[0], bh_[1], bh_[2], bh_[3], bdh);
                int ul = 8 + 2 * u + ((lane >> 3) & 1);
                uint32_t bdl = kB + n * 256 + ((8 | ((ul ^ n) & 7)) << 4);
                LDMATRIX_X4(bl_[0], bl_[1], bl_[2], bl_[3], bdl);
                MMA_BF16(sf[2 * fp + 0], ah, bh_[0], bh_[1]);
                MMA_BF16(sf[2 * fp + 1], ah, bh_[2], bh_[3]);
                MMA_BF16(sf[2 * fp + 0], ah, bl_[0], bl_[1]);
                MMA_BF16(sf[2 * fp + 1], ah, bl_[2], bl_[3]);
                MMA_BF16(sf[2 * fp + 0], al, bh_[0], bh_[1]);
                MMA_BF16(sf[2 * fp + 1], al, bh_[2], bh_[3]);
            }
        }

        // ---- + bias ----
        const int r0g = q0 + w * 16 + (lane >> 2);
#pragma unroll
        for (int j = 0; j < 8; j++) {
            int dk = k0 + 8 * j + 2 * (lane & 3) - r0g;
            sf[j][0] += bias_h[dk];
            sf[j][1] += bias_h[dk + 1];
            sf[j][2] += bias_h[dk - 8];
            sf[j][3] += bias_h[dk - 7];
        }

        // ---- online softmax ----
        float mt0 = -1e30f, mt1 = -1e30f;
#pragma unroll
        for (int j = 0; j < 8; j++) {
            mt0 = fmaxf(mt0, fmaxf(sf[j][0], sf[j][1]));
            mt1 = fmaxf(mt1, fmaxf(sf[j][2], sf[j][3]));
        }
        mt0 = fmaxf(mt0, __shfl_xor_sync(0xffffffffu, mt0, 1));
        mt0 = fmaxf(mt0, __shfl_xor_sync(0xffffffffu, mt0, 2));
        mt1 = fmaxf(mt1, __shfl_xor_sync(0xffffffffu, mt1, 1));
        mt1 = fmaxf(mt1, __shfl_xor_sync(0xffffffffu, mt1, 2));

        float mn0 = fmaxf(mrow[0], mt0), mn1 = fmaxf(mrow[1], mt1);
        float alpha0 = __expf(mrow[0] - mn0), alpha1 = __expf(mrow[1] - mn1);
        mrow[0] = mn0; mrow[1] = mn1;

        float ls0 = 0.f, ls1 = 0.f;
#pragma unroll
        for (int j = 0; j < 8; j++) {
            sf[j][0] = __expf(sf[j][0] - mn0);
            sf[j][1] = __expf(sf[j][1] - mn0);
            sf[j][2] = __expf(sf[j][2] - mn1);
            sf[j][3] = __expf(sf[j][3] - mn1);
            ls0 += sf[j][0] + sf[j][1];
            ls1 += sf[j][2] + sf[j][3];
        }
        ls0 += __shfl_xor_sync(0xffffffffu, ls0, 1);
        ls0 += __shfl_xor_sync(0xffffffffu, ls0, 2);
        ls1 += __shfl_xor_sync(0xffffffffu, ls1, 1);
        ls1 += __shfl_xor_sync(0xffffffffu, ls1, 2);
        lrow[0] = lrow[0] * alpha0 + ls0;
        lrow[1] = lrow[1] * alpha1 + ls1;
#pragma unroll
        for (int j = 0; j < 8; j++) {
            ofr[j][0] *= alpha0; ofr[j][1] *= alpha0;
            ofr[j][2] *= alpha1; ofr[j][3] *= alpha1;
        }

        // ---- O += P * V via 3-term split ----
#pragma unroll
        for (int kk = 0; kk < 4; kk++) {
            uint32_t ph[4], pl[4];
            split2(sf[2 * kk][0],     sf[2 * kk][1],     ph[0], pl[0]);
            split2(sf[2 * kk][2],     sf[2 * kk][3],     ph[1], pl[1]);
            split2(sf[2 * kk + 1][0], sf[2 * kk + 1][1], ph[2], pl[2]);
            split2(sf[2 * kk + 1][2], sf[2 * kk + 1][3], ph[3], pl[3]);
            const int g = lane >> 3;
            const int rowh = kk * 16 + ((g & 1) << 3) + (lane & 7);
            const int rowl = 64 + rowh;
#pragma unroll
            for (int fb = 0; fb < 4; fb++) {
                int unit = fb * 2 + (g >> 1);
                uint32_t bvh[4], bvl[4];
                uint32_t avh = vB + rowh * 128 + ((unit ^ (rowh & 7)) << 4);
                LDMATRIX_X4_T(bvh[0], bvh[1], bvh[2], bvh[3], avh);
                uint32_t avl = vB + rowl * 128 + ((unit ^ (rowl & 7)) << 4);
                LDMATRIX_X4_T(bvl[0], bvl[1], bvl[2], bvl[3], avl);
                MMA_BF16(ofr[2 * fb + 0], ph, bvh[0], bvh[1]);
                MMA_BF16(ofr[2 * fb + 1], ph, bvh[2], bvh[3]);
                MMA_BF16(ofr[2 * fb + 0], ph, bvl[0], bvl[1]);
                MMA_BF16(ofr[2 * fb + 1], ph, bvl[2], bvl[3]);
                MMA_BF16(ofr[2 * fb + 0], pl, bvh[0], bvh[1]);
                MMA_BF16(ofr[2 * fb + 1], pl, bvh[2], bvh[3]);
            }
        }

        __syncthreads();                  // everyone done reading stage t
        if (t + 2 < NKT) load_kv(t + 2);  // refill buffer (t&1)
        else CP_COMMIT();
    }

    // ---- epilogue: write split-bf16 AO2 directly ([hi | lo]) ----
    const float inv0 = 1.f / lrow[0], inv1 = 1.f / lrow[1];
    const int r0 = q0 + w * 16 + (lane >> 2), r1 = r0 + 8;
    __nv_bfloat16* row0 = out2 + (size_t)(b * T_ + r0) * K2_;
    __nv_bfloat16* row1 = out2 + (size_t)(b * T_ + r1) * K2_;
#pragma unroll
    for (int j = 0; j < 8; j++) {
        int col = h * HS_ + 8 * j + 2 * (lane & 3);
        uint32_t hi, lo;
        split2(ofr[j][0] * inv0, ofr[j][1] * inv0, hi, lo);
        *(uint32_t*)(row0 + col)      = hi;
        *(uint32_t*)(row0 + D_ + col) = lo;
        split2(ofr[j][2] * inv1, ofr[j][3] * inv1, hi, lo);
        *(uint32_t*)(row1 + col)      = hi;
        *(uint32_t*)(row1 + D_ + col) = lo;
    }
}

// ================== launch ==================================================
extern "C" void kernel_launch(void* const* d_in, const int* in_sizes, int n_in,
                              void* d_out, int out_size) {
    const float* queries = (const float*)d_in[0];
    const float* Wq      = (const float*)d_in[1];
    const float* Wk      = (const float*)d_in[2];
    const float* Wv      = (const float*)d_in[3];
    const float* Wo      = (const float*)d_in[4];
    const float* rel_emb = (const float*)d_in[5];
    float* out = (float*)d_out;

    __nv_bfloat16 *gA2, *gAO2, *gW2, *gQKV2;
    float *gB;
    cudaGetSymbolAddress((void**)&gA2,   g_A2);
    cudaGetSymbolAddress((void**)&gAO2,  g_AO2);
    cudaGetSymbolAddress((void**)&gW2,   g_W2);
    cudaGetSymbolAddress((void**)&gQKV2, g_QKV2);
    cudaGetSymbolAddress((void**)&gB,    g_bias);

    cudaFuncSetAttribute(attn_hmma,     cudaFuncAttributeMaxDynamicSharedMemorySize, ATTN_SMEM);
    cudaFuncSetAttribute(gemm_hmma4<0>, cudaFuncAttributeMaxDynamicSharedMemorySize, GEMM4_SMEM);
    cudaFuncSetAttribute(gemm_hmma4<1>, cudaFuncAttributeMaxDynamicSharedMemorySize, GEMM4_SMEM);

    split2_kernel<<<(M_ * (D_ / 4) + 255) / 256, 256>>>(queries, gA2, M_);
    split2_kernel<<<(D_ * (D_ / 4) + 255) / 256, 256>>>(Wq, gW2 + 0 * WOFF2, D_);
    split2_kernel<<<(D_ * (D_ / 4) + 255) / 256, 256>>>(Wk, gW2 + 1 * WOFF2, D_);
    split2_kernel<<<(D_ * (D_ / 4) + 255) / 256, 256>>>(Wv, gW2 + 2 * WOFF2, D_);
    split2_kernel<<<(D_ * (D_ / 4) + 255) / 256, 256>>>(Wo, gW2 + 3 * WOFF2, D_);

    // fused Q/K/V projections -> split-bf16 [z][bh][t][seg][hs]
    dim3 gGrid(D_ / 128, M_ / 128, 3);
    gemm_hmma4<1><<<gGrid, 256, GEMM4_SMEM>>>(gA2, gW2, nullptr, gQKV2);

    bias_kernel<<<(NH_ * NBIAS + 255) / 256, 256>>>(rel_emb, gB);

    // attention -> split AO2 directly
    dim3 aGrid(T_ / QT, B_ * NH_);
    attn_hmma<<<aGrid, 256, ATTN_SMEM>>>(gQKV2, gB, gAO2);

    // output projection (fp32 out)
    dim3 oGrid(D_ / 128, M_ / 128, 1);
    gemm_hmma4<0><<<oGrid, 256, GEMM4_SMEM>>>(gAO2, gW2 + 3 * WOFF2, out, nullptr);
}

// round 9
// speedup vs baseline: 1.2932x; 1.2932x over previous
#include <cuda_runtime.h>
#include <cuda_bf16.h>
#include <cuda_fp16.h>
#include <math.h>
#include <stdint.h>

#define B_  4
#define T_  2048
#define D_  1024
#define NH_ 16
#define HS_ 64
#define NBIAS (2*T_ - 1)   // 4095
#define M_  (B_*T_)        // 8192
#define K2_ 2048           // split-bf16 storage: [hi | lo]

// ---------------- scratch (device globals: no allocation allowed) ----------
__device__ __nv_bfloat16 g_A2 [M_*(size_t)K2_];    // queries split [hi|lo]
__device__ __nv_bfloat16 g_AO2[M_*(size_t)K2_];    // attn-out split [hi|lo]
__device__ __nv_bfloat16 g_W2 [4*(size_t)D_*K2_];  // weights split [hi|lo]
__device__ __half g_QKV1[3*(size_t)NH_*B_*T_*HS_]; // fp16 [z][bh][t][hs]
__device__ float g_bias[NH_*NBIAS];

#define TQ1 ((size_t)NH_*B_*T_*HS_)    // per-tensor offset in g_QKV1

// ============================ PTX helpers ==================================
__device__ __forceinline__ uint32_t smem_u32(const void* p) {
    uint32_t a;
    asm("{ .reg .u64 t; cvta.to.shared.u64 t, %1; cvt.u32.u64 %0, t; }" : "=r"(a) : "l"(p));
    return a;
}
#define CP_ASYNC16(dst, src) \
    asm volatile("cp.async.cg.shared.global [%0], [%1], 16;" :: "r"(dst), "l"(src) : "memory")
#define CP_COMMIT() asm volatile("cp.async.commit_group;" ::: "memory")
#define CP_WAIT1()  asm volatile("cp.async.wait_group 1;" ::: "memory")
#define CP_WAIT2()  asm volatile("cp.async.wait_group 2;" ::: "memory")

#define LDMATRIX_X4(r0, r1, r2, r3, addr) \
    asm volatile("ldmatrix.sync.aligned.m8n8.x4.shared.b16 {%0,%1,%2,%3}, [%4];" \
                 : "=r"(r0), "=r"(r1), "=r"(r2), "=r"(r3) : "r"(addr))
#define LDMATRIX_X4_T(r0, r1, r2, r3, addr) \
    asm volatile("ldmatrix.sync.aligned.m8n8.x4.trans.shared.b16 {%0,%1,%2,%3}, [%4];" \
                 : "=r"(r0), "=r"(r1), "=r"(r2), "=r"(r3) : "r"(addr))

#define MMA_BF16(c, a, b0, b1) \
    asm volatile("mma.sync.aligned.m16n8k16.row.col.f32.bf16.bf16.f32 " \
                 "{%0,%1,%2,%3}, {%4,%5,%6,%7}, {%8,%9}, {%0,%1,%2,%3};" \
                 : "+f"((c)[0]), "+f"((c)[1]), "+f"((c)[2]), "+f"((c)[3]) \
                 : "r"((a)[0]), "r"((a)[1]), "r"((a)[2]), "r"((a)[3]), "r"(b0), "r"(b1))
#define MMA_F16(c, a, b0, b1) \
    asm volatile("mma.sync.aligned.m16n8k16.row.col.f32.f16.f16.f32 " \
                 "{%0,%1,%2,%3}, {%4,%5,%6,%7}, {%8,%9}, {%0,%1,%2,%3};" \
                 : "+f"((c)[0]), "+f"((c)[1]), "+f"((c)[2]), "+f"((c)[3]) \
                 : "r"((a)[0]), "r"((a)[1]), "r"((a)[2]), "r"((a)[3]), "r"(b0), "r"(b1))

__device__ __forceinline__ void split2(float a, float b, uint32_t& hi, uint32_t& lo) {
    __nv_bfloat16 ha = __float2bfloat16_rn(a), hb = __float2bfloat16_rn(b);
    float la = a - __bfloat162float(ha), lb = b - __bfloat162float(hb);
    __nv_bfloat162 hv = __halves2bfloat162(ha, hb);
    __nv_bfloat162 lv = __halves2bfloat162(__float2bfloat16_rn(la), __float2bfloat16_rn(lb));
    hi = *(uint32_t*)&hv;
    lo = *(uint32_t*)&lv;
}
// fp16 split (for P in attention)
__device__ __forceinline__ void splith(float a, float b, uint32_t& hi, uint32_t& lo) {
    __half ha = __float2half_rn(a), hb = __float2half_rn(b);
    float la = a - __half2float(ha), lb = b - __half2float(hb);
    __half2 hv = __halves2half2(ha, hb);
    __half2 lv = __halves2half2(__float2half_rn(la), __float2half_rn(lb));
    hi = *(uint32_t*)&hv;
    lo = *(uint32_t*)&lv;
}

// ================== bias table =============================================
__device__ __forceinline__ int bucket_of(int rp) {
    int b = (rp > 0) ? 16 : 0;
    int a = rp < 0 ? -rp : rp;
    if (a < 8) return b + a;
    double v = 7.0 + (log((double)a / 7.0) / log(128.0 / 7.0)) * 8.0;
    int large = (int)v;
    if (large > 15) large = 15;
    return b + large;
}
__global__ void bias_kernel(const float* __restrict__ rel_emb, float* __restrict__ btab) {
    int idx = blockIdx.x * blockDim.x + threadIdx.x;
    if (idx >= NH_ * NBIAS) return;
    int h = idx / NBIAS;
    int x = idx % NBIAS;
    btab[idx] = rel_emb[bucket_of(x - (T_ - 1)) * NH_ + h];
}

// ================== fp32 -> [hi | lo] split-bf16 ===========================
__global__ void split2_kernel(const float* __restrict__ in, __nv_bfloat16* __restrict__ out,
                              int nrows) {
    int i = blockIdx.x * blockDim.x + threadIdx.x;
    if (i >= nrows * (D_ / 4)) return;
    int r = i / (D_ / 4);
    int c = (i % (D_ / 4)) * 4;
    float4 v = *(const float4*)(in + (size_t)r * D_ + c);
    uint32_t h0, l0, h1, l1;
    split2(v.x, v.y, h0, l0);
    split2(v.z, v.w, h1, l1);
    uint32_t* sh = (uint32_t*)(out + (size_t)r * K2_ + c);
    sh[0] = h0; sh[1] = h1;
    uint32_t* sl = (uint32_t*)(out + (size_t)r * K2_ + D_ + c);
    sl[0] = l0; sl[1] = l1;
}

// ================== HMMA bf16 GEMM v4 (operand reuse) ======================
// out[m,n] = sum_{k<1024} Ah*Bh + Ah*Bl + Al*Bh  (each bf16 pair from [hi|lo])
// SPLITOUT=1: write fp16 [z][bh][t][hs] (Q scaled by 1/8).
// SPLITOUT=0: write fp32 row-major [m, n].
#define GS4 3
#define TB4 8192
#define ST4 (4 * TB4)               // 32KB per stage
#define GEMM4_SMEM (GS4 * ST4)      // 96KB
#define GIT4 32
#define WOFF2 ((size_t)D_ * K2_)

template <int SPLITOUT>
__global__ __launch_bounds__(256, 2)
void gemm_hmma4(const __nv_bfloat16* __restrict__ A, const __nv_bfloat16* __restrict__ W0,
                float* __restrict__ outf, __half* __restrict__ outq) {
    extern __shared__ char sm4[];
    const uint32_t sb = smem_u32(sm4);

    const int tid  = threadIdx.x;
    const int w    = tid >> 5;
    const int lane = tid & 31;
    const int wm   = w & 1;            // 64-row half
    const int wn   = w >> 1;           // 32-col quarter
    const int m0   = blockIdx.y * 128;
    const int n0   = blockIdx.x * 128;
    const int z    = blockIdx.z;
    const __nv_bfloat16* W = W0 + (size_t)z * WOFF2;

    float acc[4][4][4];
#pragma unroll
    for (int i = 0; i < 4; i++)
#pragma unroll
        for (int j = 0; j < 4; j++)
#pragma unroll
            for (int q = 0; q < 4; q++) acc[i][j][q] = 0.f;

    auto load_stage = [&](int it) {
        const uint32_t st = sb + (uint32_t)(it % GS4) * ST4;
        const int kb = it * 32;
#pragma unroll
        for (int j = 0; j < 2; j++) {
            int idx = tid * 2 + j;
            int row = idx >> 2, u = idx & 3;
            uint32_t off = row * 64 + ((u ^ ((row >> 1) & 3)) << 4);
            const __nv_bfloat16* ar = A + (size_t)(m0 + row) * K2_ + kb + u * 8;
            const __nv_bfloat16* wr = W + (size_t)(n0 + row) * K2_ + kb + u * 8;
            CP_ASYNC16(st + off,           (const void*)ar);          // Ah
            CP_ASYNC16(st + TB4 + off,     (const void*)(ar + D_));   // Al
            CP_ASYNC16(st + 2 * TB4 + off, (const void*)wr);          // Bh
            CP_ASYNC16(st + 3 * TB4 + off, (const void*)(wr + D_));   // Bl
        }
        CP_COMMIT();
    };

    load_stage(0);
    load_stage(1);

    for (int it = 0; it < GIT4; it++) {
        CP_WAIT1();
        __syncthreads();
        if (it + 2 < GIT4) load_stage(it + 2);
        else CP_COMMIT();

        const uint32_t aH = sb + (uint32_t)(it % GS4) * ST4;
        const uint32_t aL = aH + TB4;
        const uint32_t bH = aH + 2 * TB4;
        const uint32_t bL = aH + 3 * TB4;

#pragma unroll
        for (int ks = 0; ks < 2; ks++) {
            uint32_t ah[4][4], al[4][4];
#pragma unroll
            for (int fm = 0; fm < 4; fm++) {
                int row = wm * 64 + fm * 16 + (lane & 15);
                int u = ks * 2 + (lane >> 4);
                uint32_t off = row * 64 + ((u ^ ((row >> 1) & 3)) << 4);
                LDMATRIX_X4(ah[fm][0], ah[fm][1], ah[fm][2], ah[fm][3], aH + off);
                LDMATRIX_X4(al[fm][0], al[fm][1], al[fm][2], al[fm][3], aL + off);
            }
            uint32_t bh[2][4], bl[2][4];
#pragma unroll
            for (int fp = 0; fp < 2; fp++) {
                int n = wn * 32 + fp * 16 + (lane & 7) + ((lane >> 4) << 3);
                int u = ks * 2 + ((lane >> 3) & 1);
                uint32_t off = n * 64 + ((u ^ ((n >> 1) & 3)) << 4);
                LDMATRIX_X4(bh[fp][0], bh[fp][1], bh[fp][2], bh[fp][3], bH + off);
                LDMATRIX_X4(bl[fp][0], bl[fp][1], bl[fp][2], bl[fp][3], bL + off);
            }
#pragma unroll
            for (int fm = 0; fm < 4; fm++)
#pragma unroll
                for (int fp = 0; fp < 2; fp++) {
                    MMA_BF16(acc[fm][fp * 2 + 0], ah[fm], bh[fp][0], bh[fp][1]);
                    MMA_BF16(acc[fm][fp * 2 + 1], ah[fm], bh[fp][2], bh[fp][3]);
                    MMA_BF16(acc[fm][fp * 2 + 0], ah[fm], bl[fp][0], bl[fp][1]);
                    MMA_BF16(acc[fm][fp * 2 + 1], ah[fm], bl[fp][2], bl[fp][3]);
                    MMA_BF16(acc[fm][fp * 2 + 0], al[fm], bh[fp][0], bh[fp][1]);
                    MMA_BF16(acc[fm][fp * 2 + 1], al[fm], bh[fp][2], bh[fp][3]);
                }
        }
    }

    const int cr = lane >> 2;
    const int cc = 2 * (lane & 3);
    const float sc = (SPLITOUT && blockIdx.z == 0) ? 0.125f : 1.f;
#pragma unroll
    for (int fm = 0; fm < 4; fm++) {
        int r = m0 + wm * 64 + fm * 16 + cr;
#pragma unroll
        for (int fn = 0; fn < 4; fn++) {
            int col = n0 + wn * 32 + fn * 8 + cc;
            if (SPLITOUT) {
                int bb = r >> 11, t = r & (T_ - 1);
                int hh = col >> 6, hs = col & 63;
                size_t base = (((size_t)z * (B_ * NH_) + bb * NH_ + hh) * T_ + t) * HS_ + hs;
                *(__half2*)(outq + base) =
                    __floats2half2_rn(acc[fm][fn][0] * sc, acc[fm][fn][1] * sc);
                *(__half2*)(outq + base + 8 * HS_) =
                    __floats2half2_rn(acc[fm][fn][2] * sc, acc[fm][fn][3] * sc);
            } else {
                *(float2*)(outf + (size_t)r * D_ + col) =
                    make_float2(acc[fm][fn][0], acc[fm][fn][1]);
                *(float2*)(outf + (size_t)(r + 8) * D_ + col) =
                    make_float2(acc[fm][fn][2], acc[fm][fn][3]);
            }
        }
    }
}

// ================== fp16 flash attention ===================================
// S = q16 k16 (1 MMA term); O += (p_hi + p_lo)16 * v16 (2 terms).
// SMEM: Q 16KB @0 (128 rows x 128B); KV 3-stage ring @16384, stage 16KB
//       (K: 64 rows x 128B; V: 64 rows x 128B). Swizzle: u ^ (row&7).
#define QT 128
#define KT 64
#define ASM_Q 0u
#define ASM_KV 16384u
#define KVST 16384u
#define ATTN_SMEM (16384 + 3 * 16384)   // 64KB
#define NKT (T_ / KT)                   // 32

__global__ __launch_bounds__(256, 2)
void attn_hmma(const __half* __restrict__ QKV, const float* __restrict__ btab,
               __nv_bfloat16* __restrict__ out2) {
    extern __shared__ char sm[];
    const uint32_t sb = smem_u32(sm);

    const int tid  = threadIdx.x;
    const int w    = tid >> 5;
    const int lane = tid & 31;
    const int bh = blockIdx.y;
    const int h  = bh & (NH_ - 1);
    const int b  = bh >> 4;
    const int q0 = blockIdx.x * QT;

    const __half* Qq = QKV + (size_t)bh * T_ * HS_;
    const __half* Kq = QKV + TQ1 + (size_t)bh * T_ * HS_;
    const __half* Vq = QKV + 2 * TQ1 + (size_t)bh * T_ * HS_;
    const float* bias_h = btab + h * NBIAS + (T_ - 1);

    // ---- Q preload (1 group): 1024 16B-units ----
#pragma unroll
    for (int j = 0; j < 4; j++) {
        int idx = tid * 4 + j;
        int row = idx >> 3, u = idx & 7;
        uint32_t dst = sb + ASM_Q + row * 128 + ((u ^ (row & 7)) << 4);
        CP_ASYNC16(dst, (const void*)(Qq + (size_t)(q0 + row) * HS_ + u * 8));
    }
    CP_COMMIT();

    // ---- K/V stage loader: 1024 units per stage ----
    auto load_kv = [&](int t) {
        const uint32_t st = sb + ASM_KV + (uint32_t)(t % 3) * KVST;
        const int k0 = t * KT;
#pragma unroll
        for (int j = 0; j < 2; j++) {
            int idx = tid * 2 + j;                 // 0..511
            int row = idx >> 3, u = idx & 7;
            uint32_t off = row * 128 + ((u ^ (row & 7)) << 4);
            const size_t goff = (size_t)(k0 + row) * HS_ + u * 8;
            CP_ASYNC16(st + off,        (const void*)(Kq + goff));
            CP_ASYNC16(st + 8192 + off, (const void*)(Vq + goff));
        }
        CP_COMMIT();
    };

    load_kv(0);
    load_kv(1);
    load_kv(2);

    float ofr[8][4];
    float mrow[2] = {-1e30f, -1e30f};
    float lrow[2] = {0.f, 0.f};
#pragma unroll
    for (int j = 0; j < 8; j++)
#pragma unroll
        for (int q = 0; q < 4; q++) ofr[j][q] = 0.f;

    for (int t = 0; t < NKT; t++) {
        CP_WAIT2();                    // Q + stage t done (t+1, t+2 may be pending)
        __syncthreads();

        const uint32_t kB = sb + ASM_KV + (uint32_t)(t % 3) * KVST;
        const uint32_t vB = kB + 8192;
        const int k0 = t * KT;

        // ---- S = q k^T (single fp16 term) ----
        float sf[8][4];
#pragma unroll
        for (int j = 0; j < 8; j++)
#pragma unroll
            for (int q = 0; q < 4; q++) sf[j][q] = 0.f;

#pragma unroll
        for (int u = 0; u < 4; u++) {
            uint32_t a[4];
            {
                int row = w * 16 + (lane & 15);
                int un = 2 * u + (lane >> 4);
                uint32_t ad = sb + ASM_Q + row * 128 + ((un ^ (row & 7)) << 4);
                LDMATRIX_X4(a[0], a[1], a[2], a[3], ad);
            }
#pragma unroll
            for (int fp = 0; fp < 4; fp++) {
                int n = fp * 16 + (lane & 7) + ((lane >> 4) << 3);
                int un = 2 * u + ((lane >> 3) & 1);
                uint32_t b0, b1, b2, b3;
                uint32_t bd = kB + n * 128 + ((un ^ (n & 7)) << 4);
                LDMATRIX_X4(b0, b1, b2, b3, bd);
                MMA_F16(sf[2 * fp + 0], a, b0, b1);
                MMA_F16(sf[2 * fp + 1], a, b2, b3);
            }
        }

        // ---- + bias ----
        const int r0g = q0 + w * 16 + (lane >> 2);
#pragma unroll
        for (int j = 0; j < 8; j++) {
            int dk = k0 + 8 * j + 2 * (lane & 3) - r0g;
            sf[j][0] += bias_h[dk];
            sf[j][1] += bias_h[dk + 1];
            sf[j][2] += bias_h[dk - 8];
            sf[j][3] += bias_h[dk - 7];
        }

        // ---- online softmax ----
        float mt0 = -1e30f, mt1 = -1e30f;
#pragma unroll
        for (int j = 0; j < 8; j++) {
            mt0 = fmaxf(mt0, fmaxf(sf[j][0], sf[j][1]));
            mt1 = fmaxf(mt1, fmaxf(sf[j][2], sf[j][3]));
        }
        mt0 = fmaxf(mt0, __shfl_xor_sync(0xffffffffu, mt0, 1));
        mt0 = fmaxf(mt0, __shfl_xor_sync(0xffffffffu, mt0, 2));
        mt1 = fmaxf(mt1, __shfl_xor_sync(0xffffffffu, mt1, 1));
        mt1 = fmaxf(mt1, __shfl_xor_sync(0xffffffffu, mt1, 2));

        float mn0 = fmaxf(mrow[0], mt0), mn1 = fmaxf(mrow[1], mt1);
        float alpha0 = __expf(mrow[0] - mn0), alpha1 = __expf(mrow[1] - mn1);
        mrow[0] = mn0; mrow[1] = mn1;

        float ls0 = 0.f, ls1 = 0.f;
#pragma unroll
        for (int j = 0; j < 8; j++) {
            sf[j][0] = __expf(sf[j][0] - mn0);
            sf[j][1] = __expf(sf[j][1] - mn0);
            sf[j][2] = __expf(sf[j][2] - mn1);
            sf[j][3] = __expf(sf[j][3] - mn1);
            ls0 += sf[j][0] + sf[j][1];
            ls1 += sf[j][2] + sf[j][3];
        }
        ls0 += __shfl_xor_sync(0xffffffffu, ls0, 1);
        ls0 += __shfl_xor_sync(0xffffffffu, ls0, 2);
        ls1 += __shfl_xor_sync(0xffffffffu, ls1, 1);
        ls1 += __shfl_xor_sync(0xffffffffu, ls1, 2);
        lrow[0] = lrow[0] * alpha0 + ls0;
        lrow[1] = lrow[1] * alpha1 + ls1;
#pragma unroll
        for (int j = 0; j < 8; j++) {
            ofr[j][0] *= alpha0; ofr[j][1] *= alpha0;
            ofr[j][2] *= alpha1; ofr[j][3] *= alpha1;
        }

        // ---- O += (p_hi + p_lo) * v  (fp16 split of exact P; v single) ----
#pragma unroll
        for (int kk = 0; kk < 4; kk++) {
            uint32_t ph[4], pl[4];
            splith(sf[2 * kk][0],     sf[2 * kk][1],     ph[0], pl[0]);
            splith(sf[2 * kk][2],     sf[2 * kk][3],     ph[1], pl[1]);
            splith(sf[2 * kk + 1][0], sf[2 * kk + 1][1], ph[2], pl[2]);
            splith(sf[2 * kk + 1][2], sf[2 * kk + 1][3], ph[3], pl[3]);
            const int g = lane >> 3;
            const int rowv = kk * 16 + ((g & 1) << 3) + (lane & 7);
#pragma unroll
            for (int fb = 0; fb < 4; fb++) {
                int unit = fb * 2 + (g >> 1);
                uint32_t v0, v1, v2, v3;
                uint32_t av = vB + rowv * 128 + ((unit ^ (rowv & 7)) << 4);
                LDMATRIX_X4_T(v0, v1, v2, v3, av);
                MMA_F16(ofr[2 * fb + 0], ph, v0, v1);
                MMA_F16(ofr[2 * fb + 1], ph, v2, v3);
                MMA_F16(ofr[2 * fb + 0], pl, v0, v1);
                MMA_F16(ofr[2 * fb + 1], pl, v2, v3);
            }
        }

        __syncthreads();                  // all reads of stage t done
        if (t + 3 < NKT) load_kv(t + 3);  // refill slot (t%3)
        else CP_COMMIT();
    }

    // ---- epilogue: write split-bf16 AO2 ([hi | lo]) for the out-proj ----
    const float inv0 = 1.f / lrow[0], inv1 = 1.f / lrow[1];
    const int r0 = q0 + w * 16 + (lane >> 2), r1 = r0 + 8;
    __nv_bfloat16* row0 = out2 + (size_t)(b * T_ + r0) * K2_;
    __nv_bfloat16* row1 = out2 + (size_t)(b * T_ + r1) * K2_;
#pragma unroll
    for (int j = 0; j < 8; j++) {
        int col = h * HS_ + 8 * j + 2 * (lane & 3);
        uint32_t hi, lo;
        split2(ofr[j][0] * inv0, ofr[j][1] * inv0, hi, lo);
        *(uint32_t*)(row0 + col)      = hi;
        *(uint32_t*)(row0 + D_ + col) = lo;
        split2(ofr[j][2] * inv1, ofr[j][3] * inv1, hi, lo);
        *(uint32_t*)(row1 + col)      = hi;
        *(uint32_t*)(row1 + D_ + col) = lo;
    }
}

// ================== launch ==================================================
extern "C" void kernel_launch(void* const* d_in, const int* in_sizes, int n_in,
                              void* d_out, int out_size) {
    const float* queries = (const float*)d_in[0];
    const float* Wq      = (const float*)d_in[1];
    const float* Wk      = (const float*)d_in[2];
    const float* Wv      = (const float*)d_in[3];
    const float* Wo      = (const float*)d_in[4];
    const float* rel_emb = (const float*)d_in[5];
    float* out = (float*)d_out;

    __nv_bfloat16 *gA2, *gAO2, *gW2;
    __half *gQKV1;
    float *gB;
    cudaGetSymbolAddress((void**)&gA2,   g_A2);
    cudaGetSymbolAddress((void**)&gAO2,  g_AO2);
    cudaGetSymbolAddress((void**)&gW2,   g_W2);
    cudaGetSymbolAddress((void**)&gQKV1, g_QKV1);
    cudaGetSymbolAddress((void**)&gB,    g_bias);

    cudaFuncSetAttribute(attn_hmma,     cudaFuncAttributeMaxDynamicSharedMemorySize, ATTN_SMEM);
    cudaFuncSetAttribute(gemm_hmma4<0>, cudaFuncAttributeMaxDynamicSharedMemorySize, GEMM4_SMEM);
    cudaFuncSetAttribute(gemm_hmma4<1>, cudaFuncAttributeMaxDynamicSharedMemorySize, GEMM4_SMEM);

    split2_kernel<<<(M_ * (D_ / 4) + 255) / 256, 256>>>(queries, gA2, M_);
    split2_kernel<<<(D_ * (D_ / 4) + 255) / 256, 256>>>(Wq, gW2 + 0 * WOFF2, D_);
    split2_kernel<<<(D_ * (D_ / 4) + 255) / 256, 256>>>(Wk, gW2 + 1 * WOFF2, D_);
    split2_kernel<<<(D_ * (D_ / 4) + 255) / 256, 256>>>(Wv, gW2 + 2 * WOFF2, D_);
    split2_kernel<<<(D_ * (D_ / 4) + 255) / 256, 256>>>(Wo, gW2 + 3 * WOFF2, D_);

    // fused Q/K/V projections -> fp16 [z][bh][t][hs] (Q pre-scaled by 1/8)
    dim3 gGrid(D_ / 128, M_ / 128, 3);
    gemm_hmma4<1><<<gGrid, 256, GEMM4_SMEM>>>(gA2, gW2, nullptr, gQKV1);

    bias_kernel<<<(NH_ * NBIAS + 255) / 256, 256>>>(rel_emb, gB);

    // fp16 attention -> split-bf16 AO2
    dim3 aGrid(T_ / QT, B_ * NH_);
    attn_hmma<<<aGrid, 256, ATTN_SMEM>>>(gQKV1, gB, gAO2);

    // output projection (bf16 3-term, fp32 out)
    dim3 oGrid(D_ / 128, M_ / 128, 1);
    gemm_hmma4<0><<<oGrid, 256, GEMM4_SMEM>>>(gAO2, gW2 + 3 * WOFF2, out, nullptr);
}

// round 10
// speedup vs baseline: 1.5659x; 1.2109x over previous
#include <cuda_runtime.h>
#include <cuda_bf16.h>
#include <cuda_fp16.h>
#include <math.h>
#include <stdint.h>

#define B_  4
#define T_  2048
#define D_  1024
#define NH_ 16
#define HS_ 64
#define NBIAS (2*T_ - 1)   // 4095
#define M_  (B_*T_)        // 8192
#define K2_ 2048           // split-fp16 activation storage: [hi | lo]

// ---------------- scratch (device globals: no allocation allowed) ----------
__device__ __half g_A2h [M_*(size_t)K2_];    // queries split fp16 [hi|lo]
__device__ __half g_AO2h[M_*(size_t)K2_];    // attn-out split fp16 [hi|lo]
__device__ __half g_W1  [4*(size_t)D_*D_];   // weights single fp16
__device__ __half g_QKV1[3*(size_t)NH_*B_*T_*HS_]; // fp16 [z][bh][t][hs]
__device__ float g_bias[NH_*NBIAS];

#define TQ1 ((size_t)NH_*B_*T_*HS_)    // per-tensor offset in g_QKV1
#define WOFF1 ((size_t)D_*D_)          // per-weight offset in g_W1

// ============================ PTX helpers ==================================
__device__ __forceinline__ uint32_t smem_u32(const void* p) {
    uint32_t a;
    asm("{ .reg .u64 t; cvta.to.shared.u64 t, %1; cvt.u32.u64 %0, t; }" : "=r"(a) : "l"(p));
    return a;
}
#define CP_ASYNC16(dst, src) \
    asm volatile("cp.async.cg.shared.global [%0], [%1], 16;" :: "r"(dst), "l"(src) : "memory")
#define CP_COMMIT() asm volatile("cp.async.commit_group;" ::: "memory")
#define CP_WAIT1()  asm volatile("cp.async.wait_group 1;" ::: "memory")
#define CP_WAIT2()  asm volatile("cp.async.wait_group 2;" ::: "memory")

#define LDMATRIX_X4(r0, r1, r2, r3, addr) \
    asm volatile("ldmatrix.sync.aligned.m8n8.x4.shared.b16 {%0,%1,%2,%3}, [%4];" \
                 : "=r"(r0), "=r"(r1), "=r"(r2), "=r"(r3) : "r"(addr))
#define LDMATRIX_X4_T(r0, r1, r2, r3, addr) \
    asm volatile("ldmatrix.sync.aligned.m8n8.x4.trans.shared.b16 {%0,%1,%2,%3}, [%4];" \
                 : "=r"(r0), "=r"(r1), "=r"(r2), "=r"(r3) : "r"(addr))

#define MMA_F16(c, a, b0, b1) \
    asm volatile("mma.sync.aligned.m16n8k16.row.col.f32.f16.f16.f32 " \
                 "{%0,%1,%2,%3}, {%4,%5,%6,%7}, {%8,%9}, {%0,%1,%2,%3};" \
                 : "+f"((c)[0]), "+f"((c)[1]), "+f"((c)[2]), "+f"((c)[3]) \
                 : "r"((a)[0]), "r"((a)[1]), "r"((a)[2]), "r"((a)[3]), "r"(b0), "r"(b1))

// fp16 split of a pair of floats: hi + lo packed half2
__device__ __forceinline__ void splith(float a, float b, uint32_t& hi, uint32_t& lo) {
    __half ha = __float2half_rn(a), hb = __float2half_rn(b);
    float la = a - __half2float(ha), lb = b - __half2float(hb);
    __half2 hv = __halves2half2(ha, hb);
    __half2 lv = __halves2half2(__float2half_rn(la), __float2half_rn(lb));
    hi = *(uint32_t*)&hv;
    lo = *(uint32_t*)&lv;
}

// ================== bias table =============================================
__device__ __forceinline__ int bucket_of(int rp) {
    int b = (rp > 0) ? 16 : 0;
    int a = rp < 0 ? -rp : rp;
    if (a < 8) return b + a;
    double v = 7.0 + (log((double)a / 7.0) / log(128.0 / 7.0)) * 8.0;
    int large = (int)v;
    if (large > 15) large = 15;
    return b + large;
}
__global__ void bias_kernel(const float* __restrict__ rel_emb, float* __restrict__ btab) {
    int idx = blockIdx.x * blockDim.x + threadIdx.x;
    if (idx >= NH_ * NBIAS) return;
    int h = idx / NBIAS;
    int x = idx % NBIAS;
    btab[idx] = rel_emb[bucket_of(x - (T_ - 1)) * NH_ + h];
}

// ================== fp32 -> fp16 [hi | lo] split (activations) =============
__global__ void splitA_f16(const float* __restrict__ in, __half* __restrict__ out,
                           int nrows) {
    int i = blockIdx.x * blockDim.x + threadIdx.x;
    if (i >= nrows * (D_ / 4)) return;
    int r = i / (D_ / 4);
    int c = (i % (D_ / 4)) * 4;
    float4 v = *(const float4*)(in + (size_t)r * D_ + c);
    uint32_t h0, l0, h1, l1;
    splith(v.x, v.y, h0, l0);
    splith(v.z, v.w, h1, l1);
    uint32_t* sh = (uint32_t*)(out + (size_t)r * K2_ + c);
    sh[0] = h0; sh[1] = h1;
    uint32_t* sl = (uint32_t*)(out + (size_t)r * K2_ + D_ + c);
    sl[0] = l0; sl[1] = l1;
}

// ================== fp32 -> fp16 (weights, single) =========================
__global__ void convW_f16(const float* __restrict__ in, __half* __restrict__ out) {
    int i = blockIdx.x * blockDim.x + threadIdx.x;
    if (i >= D_ * (D_ / 4)) return;
    float4 v = *(const float4*)(in + (size_t)i * 4);
    __half2* o = (__half2*)(out + (size_t)i * 4);
    o[0] = __floats2half2_rn(v.x, v.y);
    o[1] = __floats2half2_rn(v.z, v.w);
}

// ================== fp16 GEMM v5 (A 2-term split, W single) ================
// out[m,n] = sum_{k<1024} (Ah + Al)[m,k] * W[n,k]   (2 MMA terms)
// CTA 128x128, BK=32, 8 warps (warp tile 64x32), 3-stage cp.async, 2 CTA/SM.
// Stage = {Ah, Al, W} tiles (3 x 8KB = 24KB); 3 stages = 72KB.
// SPLITOUT=1: write fp16 [z][bh][t][hs] (Q scaled by 1/8); 0: fp32 [m,n].
#define GS5 3
#define TB5 8192
#define ST5 (3 * TB5)               // 24KB per stage
#define GEMM5_SMEM (GS5 * ST5)      // 72KB
#define GIT5 32

template <int SPLITOUT>
__global__ __launch_bounds__(256, 2)
void gemm_hmma5(const __half* __restrict__ A, const __half* __restrict__ W0,
                float* __restrict__ outf, __half* __restrict__ outq) {
    extern __shared__ char sm5[];
    const uint32_t sb = smem_u32(sm5);

    const int tid  = threadIdx.x;
    const int w    = tid >> 5;
    const int lane = tid & 31;
    const int wm   = w & 1;            // 64-row half
    const int wn   = w >> 1;           // 32-col quarter
    const int m0   = blockIdx.y * 128;
    const int n0   = blockIdx.x * 128;
    const int z    = blockIdx.z;
    const __half* W = W0 + (size_t)z * WOFF1;

    float acc[4][4][4];
#pragma unroll
    for (int i = 0; i < 4; i++)
#pragma unroll
        for (int j = 0; j < 4; j++)
#pragma unroll
            for (int q = 0; q < 4; q++) acc[i][j][q] = 0.f;

    // loader: stage it -> slot it%3; 512 16B-units per tile, 2 per thread
    auto load_stage = [&](int it) {
        const uint32_t st = sb + (uint32_t)(it % GS5) * ST5;
        const int kb = it * 32;
#pragma unroll
        for (int j = 0; j < 2; j++) {
            int idx = tid * 2 + j;
            int row = idx >> 2, u = idx & 3;
            uint32_t off = row * 64 + ((u ^ ((row >> 1) & 3)) << 4);
            const __half* ar = A + (size_t)(m0 + row) * K2_ + kb + u * 8;
            const __half* wr = W + (size_t)(n0 + row) * D_ + kb + u * 8;
            CP_ASYNC16(st + off,           (const void*)ar);          // Ah
            CP_ASYNC16(st + TB5 + off,     (const void*)(ar + D_));   // Al
            CP_ASYNC16(st + 2 * TB5 + off, (const void*)wr);          // W
        }
        CP_COMMIT();
    };

    load_stage(0);
    load_stage(1);

    for (int it = 0; it < GIT5; it++) {
        CP_WAIT1();
        __syncthreads();
        if (it + 2 < GIT5) load_stage(it + 2);
        else CP_COMMIT();

        const uint32_t aH = sb + (uint32_t)(it % GS5) * ST5;
        const uint32_t aL = aH + TB5;
        const uint32_t wB = aH + 2 * TB5;

#pragma unroll
        for (int ks = 0; ks < 2; ks++) {
            uint32_t ah[4][4], al[4][4];
#pragma unroll
            for (int fm = 0; fm < 4; fm++) {
                int row = wm * 64 + fm * 16 + (lane & 15);
                int u = ks * 2 + (lane >> 4);
                uint32_t off = row * 64 + ((u ^ ((row >> 1) & 3)) << 4);
                LDMATRIX_X4(ah[fm][0], ah[fm][1], ah[fm][2], ah[fm][3], aH + off);
                LDMATRIX_X4(al[fm][0], al[fm][1], al[fm][2], al[fm][3], aL + off);
            }
            uint32_t b[2][4];
#pragma unroll
            for (int fp = 0; fp < 2; fp++) {
                int n = wn * 32 + fp * 16 + (lane & 7) + ((lane >> 4) << 3);
                int u = ks * 2 + ((lane >> 3) & 1);
                uint32_t off = n * 64 + ((u ^ ((n >> 1) & 3)) << 4);
                LDMATRIX_X4(b[fp][0], b[fp][1], b[fp][2], b[fp][3], wB + off);
            }
#pragma unroll
            for (int fm = 0; fm < 4; fm++)
#pragma unroll
                for (int fp = 0; fp < 2; fp++) {
                    MMA_F16(acc[fm][fp * 2 + 0], ah[fm], b[fp][0], b[fp][1]);
                    MMA_F16(acc[fm][fp * 2 + 1], ah[fm], b[fp][2], b[fp][3]);
                    MMA_F16(acc[fm][fp * 2 + 0], al[fm], b[fp][0], b[fp][1]);
                    MMA_F16(acc[fm][fp * 2 + 1], al[fm], b[fp][2], b[fp][3]);
                }
        }
    }

    const int cr = lane >> 2;
    const int cc = 2 * (lane & 3);
    const float sc = (SPLITOUT && blockIdx.z == 0) ? 0.125f : 1.f;
#pragma unroll
    for (int fm = 0; fm < 4; fm++) {
        int r = m0 + wm * 64 + fm * 16 + cr;
#pragma unroll
        for (int fn = 0; fn < 4; fn++) {
            int col = n0 + wn * 32 + fn * 8 + cc;
            if (SPLITOUT) {
                int bb = r >> 11, t = r & (T_ - 1);
                int hh = col >> 6, hs = col & 63;
                size_t base = (((size_t)z * (B_ * NH_) + bb * NH_ + hh) * T_ + t) * HS_ + hs;
                *(__half2*)(outq + base) =
                    __floats2half2_rn(acc[fm][fn][0] * sc, acc[fm][fn][1] * sc);
                *(__half2*)(outq + base + 8 * HS_) =
                    __floats2half2_rn(acc[fm][fn][2] * sc, acc[fm][fn][3] * sc);
            } else {
                *(float2*)(outf + (size_t)r * D_ + col) =
                    make_float2(acc[fm][fn][0], acc[fm][fn][1]);
                *(float2*)(outf + (size_t)(r + 8) * D_ + col) =
                    make_float2(acc[fm][fn][2], acc[fm][fn][3]);
            }
        }
    }
}

// ================== fp16 flash attention ===================================
// S = q16 k16 (1 term); O += (p_hi + p_lo)16 * v16 (2 terms).
// SMEM: Q 16KB @0 (128 rows x 128B); KV 3-stage ring @16384, stage 16KB.
#define QT 128
#define KT 64
#define ASM_Q 0u
#define ASM_KV 16384u
#define KVST 16384u
#define ATTN_SMEM (16384 + 3 * 16384)   // 64KB
#define NKT (T_ / KT)                   // 32

__global__ __launch_bounds__(256, 2)
void attn_hmma(const __half* __restrict__ QKV, const float* __restrict__ btab,
               __half* __restrict__ out2) {
    extern __shared__ char sm[];
    const uint32_t sb = smem_u32(sm);

    const int tid  = threadIdx.x;
    const int w    = tid >> 5;
    const int lane = tid & 31;
    const int bh = blockIdx.y;
    const int h  = bh & (NH_ - 1);
    const int b  = bh >> 4;
    const int q0 = blockIdx.x * QT;

    const __half* Qq = QKV + (size_t)bh * T_ * HS_;
    const __half* Kq = QKV + TQ1 + (size_t)bh * T_ * HS_;
    const __half* Vq = QKV + 2 * TQ1 + (size_t)bh * T_ * HS_;
    const float* bias_h = btab + h * NBIAS + (T_ - 1);

    // ---- Q preload (1 group) ----
#pragma unroll
    for (int j = 0; j < 4; j++) {
        int idx = tid * 4 + j;
        int row = idx >> 3, u = idx & 7;
        uint32_t dst = sb + ASM_Q + row * 128 + ((u ^ (row & 7)) << 4);
        CP_ASYNC16(dst, (const void*)(Qq + (size_t)(q0 + row) * HS_ + u * 8));
    }
    CP_COMMIT();

    auto load_kv = [&](int t) {
        const uint32_t st = sb + ASM_KV + (uint32_t)(t % 3) * KVST;
        const int k0 = t * KT;
#pragma unroll
        for (int j = 0; j < 2; j++) {
            int idx = tid * 2 + j;
            int row = idx >> 3, u = idx & 7;
            uint32_t off = row * 128 + ((u ^ (row & 7)) << 4);
            const size_t goff = (size_t)(k0 + row) * HS_ + u * 8;
            CP_ASYNC16(st + off,        (const void*)(Kq + goff));
            CP_ASYNC16(st + 8192 + off, (const void*)(Vq + goff));
        }
        CP_COMMIT();
    };

    load_kv(0);
    load_kv(1);
    load_kv(2);

    float ofr[8][4];
    float mrow[2] = {-1e30f, -1e30f};
    float lrow[2] = {0.f, 0.f};
#pragma unroll
    for (int j = 0; j < 8; j++)
#pragma unroll
        for (int q = 0; q < 4; q++) ofr[j][q] = 0.f;

    for (int t = 0; t < NKT; t++) {
        CP_WAIT2();
        __syncthreads();

        const uint32_t kB = sb + ASM_KV + (uint32_t)(t % 3) * KVST;
        const uint32_t vB = kB + 8192;
        const int k0 = t * KT;

        float sf[8][4];
#pragma unroll
        for (int j = 0; j < 8; j++)
#pragma unroll
            for (int q = 0; q < 4; q++) sf[j][q] = 0.f;

#pragma unroll
        for (int u = 0; u < 4; u++) {
            uint32_t a[4];
            {
                int row = w * 16 + (lane & 15);
                int un = 2 * u + (lane >> 4);
                uint32_t ad = sb + ASM_Q + row * 128 + ((un ^ (row & 7)) << 4);
                LDMATRIX_X4(a[0], a[1], a[2], a[3], ad);
            }
#pragma unroll
            for (int fp = 0; fp < 4; fp++) {
                int n = fp * 16 + (lane & 7) + ((lane >> 4) << 3);
                int un = 2 * u + ((lane >> 3) & 1);
                uint32_t b0, b1, b2, b3;
                uint32_t bd = kB + n * 128 + ((un ^ (n & 7)) << 4);
                LDMATRIX_X4(b0, b1, b2, b3, bd);
                MMA_F16(sf[2 * fp + 0], a, b0, b1);
                MMA_F16(sf[2 * fp + 1], a, b2, b3);
            }
        }

        const int r0g = q0 + w * 16 + (lane >> 2);
#pragma unroll
        for (int j = 0; j < 8; j++) {
            int dk = k0 + 8 * j + 2 * (lane & 3) - r0g;
            sf[j][0] += bias_h[dk];
            sf[j][1] += bias_h[dk + 1];
            sf[j][2] += bias_h[dk - 8];
            sf[j][3] += bias_h[dk - 7];
        }

        float mt0 = -1e30f, mt1 = -1e30f;
#pragma unroll
        for (int j = 0; j < 8; j++) {
            mt0 = fmaxf(mt0, fmaxf(sf[j][0], sf[j][1]));
            mt1 = fmaxf(mt1, fmaxf(sf[j][2], sf[j][3]));
        }
        mt0 = fmaxf(mt0, __shfl_xor_sync(0xffffffffu, mt0, 1));
        mt0 = fmaxf(mt0, __shfl_xor_sync(0xffffffffu, mt0, 2));
        mt1 = fmaxf(mt1, __shfl_xor_sync(0xffffffffu, mt1, 1));
        mt1 = fmaxf(mt1, __shfl_xor_sync(0xffffffffu, mt1, 2));

        float mn0 = fmaxf(mrow[0], mt0), mn1 = fmaxf(mrow[1], mt1);
        float alpha0 = __expf(mrow[0] - mn0), alpha1 = __expf(mrow[1] - mn1);
        mrow[0] = mn0; mrow[1] = mn1;

        float ls0 = 0.f, ls1 = 0.f;
#pragma unroll
        for (int j = 0; j < 8; j++) {
            sf[j][0] = __expf(sf[j][0] - mn0);
            sf[j][1] = __expf(sf[j][1] - mn0);
            sf[j][2] = __expf(sf[j][2] - mn1);
            sf[j][3] = __expf(sf[j][3] - mn1);
            ls0 += sf[j][0] + sf[j][1];
            ls1 += sf[j][2] + sf[j][3];
        }
        ls0 += __shfl_xor_sync(0xffffffffu, ls0, 1);
        ls0 += __shfl_xor_sync(0xffffffffu, ls0, 2);
        ls1 += __shfl_xor_sync(0xffffffffu, ls1, 1);
        ls1 += __shfl_xor_sync(0xffffffffu, ls1, 2);
        lrow[0] = lrow[0] * alpha0 + ls0;
        lrow[1] = lrow[1] * alpha1 + ls1;
#pragma unroll
        for (int j = 0; j < 8; j++) {
            ofr[j][0] *= alpha0; ofr[j][1] *= alpha0;
            ofr[j][2] *= alpha1; ofr[j][3] *= alpha1;
        }

#pragma unroll
        for (int kk = 0; kk < 4; kk++) {
            uint32_t ph[4], pl[4];
            splith(sf[2 * kk][0],     sf[2 * kk][1],     ph[0], pl[0]);
            splith(sf[2 * kk][2],     sf[2 * kk][3],     ph[1], pl[1]);
            splith(sf[2 * kk + 1][0], sf[2 * kk + 1][1], ph[2], pl[2]);
            splith(sf[2 * kk + 1][2], sf[2 * kk + 1][3], ph[3], pl[3]);
            const int g = lane >> 3;
            const int rowv = kk * 16 + ((g & 1) << 3) + (lane & 7);
#pragma unroll
            for (int fb = 0; fb < 4; fb++) {
                int unit = fb * 2 + (g >> 1);
                uint32_t v0, v1, v2, v3;
                uint32_t av = vB + rowv * 128 + ((unit ^ (rowv & 7)) << 4);
                LDMATRIX_X4_T(v0, v1, v2, v3, av);
                MMA_F16(ofr[2 * fb + 0], ph, v0, v1);
                MMA_F16(ofr[2 * fb + 1], ph, v2, v3);
                MMA_F16(ofr[2 * fb + 0], pl, v0, v1);
                MMA_F16(ofr[2 * fb + 1], pl, v2, v3);
            }
        }

        __syncthreads();
        if (t + 3 < NKT) load_kv(t + 3);
        else CP_COMMIT();
    }

    // ---- epilogue: write fp16 [hi | lo] AO for the out-proj ----
    const float inv0 = 1.f / lrow[0], inv1 = 1.f / lrow[1];
    const int r0 = q0 + w * 16 + (lane >> 2), r1 = r0 + 8;
    __half* row0 = out2 + (size_t)(b * T_ + r0) * K2_;
    __half* row1 = out2 + (size_t)(b * T_ + r1) * K2_;
#pragma unroll
    for (int j = 0; j < 8; j++) {
        int col = h * HS_ + 8 * j + 2 * (lane & 3);
        uint32_t hi, lo;
        splith(ofr[j][0] * inv0, ofr[j][1] * inv0, hi, lo);
        *(uint32_t*)(row0 + col)      = hi;
        *(uint32_t*)(row0 + D_ + col) = lo;
        splith(ofr[j][2] * inv1, ofr[j][3] * inv1, hi, lo);
        *(uint32_t*)(row1 + col)      = hi;
        *(uint32_t*)(row1 + D_ + col) = lo;
    }
}

// ================== launch ==================================================
extern "C" void kernel_launch(void* const* d_in, const int* in_sizes, int n_in,
                              void* d_out, int out_size) {
    const float* queries = (const float*)d_in[0];
    const float* Wq      = (const float*)d_in[1];
    const float* Wk      = (const float*)d_in[2];
    const float* Wv      = (const float*)d_in[3];
    const float* Wo      = (const float*)d_in[4];
    const float* rel_emb = (const float*)d_in[5];
    float* out = (float*)d_out;

    __half *gA2h, *gAO2h, *gW1, *gQKV1;
    float *gB;
    cudaGetSymbolAddress((void**)&gA2h,  g_A2h);
    cudaGetSymbolAddress((void**)&gAO2h, g_AO2h);
    cudaGetSymbolAddress((void**)&gW1,   g_W1);
    cudaGetSymbolAddress((void**)&gQKV1, g_QKV1);
    cudaGetSymbolAddress((void**)&gB,    g_bias);

    cudaFuncSetAttribute(attn_hmma,     cudaFuncAttributeMaxDynamicSharedMemorySize, ATTN_SMEM);
    cudaFuncSetAttribute(gemm_hmma5<0>, cudaFuncAttributeMaxDynamicSharedMemorySize, GEMM5_SMEM);
    cudaFuncSetAttribute(gemm_hmma5<1>, cudaFuncAttributeMaxDynamicSharedMemorySize, GEMM5_SMEM);

    // operand prep
    splitA_f16<<<(M_ * (D_ / 4) + 255) / 256, 256>>>(queries, gA2h, M_);
    convW_f16<<<(D_ * (D_ / 4) + 255) / 256, 256>>>(Wq, gW1 + 0 * WOFF1);
    convW_f16<<<(D_ * (D_ / 4) + 255) / 256, 256>>>(Wk, gW1 + 1 * WOFF1);
    convW_f16<<<(D_ * (D_ / 4) + 255) / 256, 256>>>(Wv, gW1 + 2 * WOFF1);
    convW_f16<<<(D_ * (D_ / 4) + 255) / 256, 256>>>(Wo, gW1 + 3 * WOFF1);

    // fused Q/K/V projections -> fp16 [z][bh][t][hs] (Q pre-scaled by 1/8)
    dim3 gGrid(D_ / 128, M_ / 128, 3);
    gemm_hmma5<1><<<gGrid, 256, GEMM5_SMEM>>>(gA2h, gW1, nullptr, gQKV1);

    bias_kernel<<<(NH_ * NBIAS + 255) / 256, 256>>>(rel_emb, gB);

    // fp16 attention -> fp16 [hi|lo] AO
    dim3 aGrid(T_ / QT, B_ * NH_);
    attn_hmma<<<aGrid, 256, ATTN_SMEM>>>(gQKV1, gB, gAO2h);

    // output projection (fp32 out)
    dim3 oGrid(D_ / 128, M_ / 128, 1);
    gemm_hmma5<0><<<oGrid, 256, GEMM5_SMEM>>>(gAO2h, gW1 + 3 * WOFF1, out, nullptr);
}

// round 11
// speedup vs baseline: 2.0714x; 1.3228x over previous
#include <cuda_runtime.h>
#include <cuda_bf16.h>
#include <cuda_fp16.h>
#include <math.h>
#include <stdint.h>

#define B_  4
#define T_  2048
#define D_  1024
#define NH_ 16
#define HS_ 64
#define NBIAS (2*T_ - 1)   // 4095
#define M_  (B_*T_)        // 8192
#define K2_ 2048           // split-fp16 storage stride: [hi | lo]

// ---------------- scratch (device globals: no allocation allowed) ----------
__device__ __half g_A1h [M_*(size_t)D_];     // queries fp16 (single)
__device__ __half g_AO2h[M_*(size_t)K2_];    // attn-out split fp16 [hi|lo]
__device__ __half g_W1  [4*(size_t)D_*D_];   // weights single fp16
__device__ __half g_QKV1[3*(size_t)NH_*B_*T_*HS_]; // fp16 [z][bh][t][hs]
__device__ float g_bias[NH_*NBIAS];

#define TQ1 ((size_t)NH_*B_*T_*HS_)    // per-tensor offset in g_QKV1
#define WOFF1 ((size_t)D_*D_)          // per-weight offset in g_W1

// ============================ PTX helpers ==================================
__device__ __forceinline__ uint32_t smem_u32(const void* p) {
    uint32_t a;
    asm("{ .reg .u64 t; cvta.to.shared.u64 t, %1; cvt.u32.u64 %0, t; }" : "=r"(a) : "l"(p));
    return a;
}
#define CP_ASYNC16(dst, src) \
    asm volatile("cp.async.cg.shared.global [%0], [%1], 16;" :: "r"(dst), "l"(src) : "memory")
#define CP_COMMIT() asm volatile("cp.async.commit_group;" ::: "memory")
#define CP_WAIT1()  asm volatile("cp.async.wait_group 1;" ::: "memory")
#define CP_WAIT2()  asm volatile("cp.async.wait_group 2;" ::: "memory")

#define LDMATRIX_X4(r0, r1, r2, r3, addr) \
    asm volatile("ldmatrix.sync.aligned.m8n8.x4.shared.b16 {%0,%1,%2,%3}, [%4];" \
                 : "=r"(r0), "=r"(r1), "=r"(r2), "=r"(r3) : "r"(addr))
#define LDMATRIX_X4_T(r0, r1, r2, r3, addr) \
    asm volatile("ldmatrix.sync.aligned.m8n8.x4.trans.shared.b16 {%0,%1,%2,%3}, [%4];" \
                 : "=r"(r0), "=r"(r1), "=r"(r2), "=r"(r3) : "r"(addr))

#define MMA_F16(c, a, b0, b1) \
    asm volatile("mma.sync.aligned.m16n8k16.row.col.f32.f16.f16.f32 " \
                 "{%0,%1,%2,%3}, {%4,%5,%6,%7}, {%8,%9}, {%0,%1,%2,%3};" \
                 : "+f"((c)[0]), "+f"((c)[1]), "+f"((c)[2]), "+f"((c)[3]) \
                 : "r"((a)[0]), "r"((a)[1]), "r"((a)[2]), "r"((a)[3]), "r"(b0), "r"(b1))

// fp16 split of a pair of floats: hi + lo packed half2
__device__ __forceinline__ void splith(float a, float b, uint32_t& hi, uint32_t& lo) {
    __half ha = __float2half_rn(a), hb = __float2half_rn(b);
    float la = a - __half2float(ha), lb = b - __half2float(hb);
    __half2 hv = __halves2half2(ha, hb);
    __half2 lv = __halves2half2(__float2half_rn(la), __float2half_rn(lb));
    hi = *(uint32_t*)&hv;
    lo = *(uint32_t*)&lv;
}
__device__ __forceinline__ uint32_t packh(float a, float b) {
    __half2 v = __floats2half2_rn(a, b);
    return *(uint32_t*)&v;
}

// ================== bias table =============================================
__device__ __forceinline__ int bucket_of(int rp) {
    int b = (rp > 0) ? 16 : 0;
    int a = rp < 0 ? -rp : rp;
    if (a < 8) return b + a;
    double v = 7.0 + (log((double)a / 7.0) / log(128.0 / 7.0)) * 8.0;
    int large = (int)v;
    if (large > 15) large = 15;
    return b + large;
}
__global__ void bias_kernel(const float* __restrict__ rel_emb, float* __restrict__ btab) {
    int idx = blockIdx.x * blockDim.x + threadIdx.x;
    if (idx >= NH_ * NBIAS) return;
    int h = idx / NBIAS;
    int x = idx % NBIAS;
    btab[idx] = rel_emb[bucket_of(x - (T_ - 1)) * NH_ + h];
}

// ================== fp32 -> fp16 converts ==================================
__global__ void convA_f16(const float* __restrict__ in, __half* __restrict__ out, int n4) {
    int i = blockIdx.x * blockDim.x + threadIdx.x;
    if (i >= n4) return;
    float4 v = *(const float4*)(in + (size_t)i * 4);
    __half2* o = (__half2*)(out + (size_t)i * 4);
    o[0] = __floats2half2_rn(v.x, v.y);
    o[1] = __floats2half2_rn(v.z, v.w);
}

// ================== fp16 GEMM v6 (templated A-split) =======================
// ASPLIT=0: out = A*W^T (single-term, A stride D_)
// ASPLIT=1: out = (Ah+Al)*W^T (2-term, A stride K2_, lo at +D_)
// CTA 128x128, BK=32, 8 warps (64x32 warp tile), 3-stage cp.async, 2 CTA/SM.
// SPLITOUT=1: fp16 [z][bh][t][hs] (Q scaled 1/8); 0: fp32 [m,n].
#define GS6 3
#define TB6 8192
#define GIT6 32

template <int ASPLIT, int SPLITOUT>
__global__ __launch_bounds__(256, 2)
void gemm_hmma6(const __half* __restrict__ A, const __half* __restrict__ W0,
                float* __restrict__ outf, __half* __restrict__ outq) {
    constexpr int NT = 2 + ASPLIT;                // tiles per stage
    constexpr uint32_t STB = (uint32_t)NT * TB6;  // stage bytes
    constexpr int AK = ASPLIT ? K2_ : D_;         // A row stride
    extern __shared__ char sm6[];
    const uint32_t sb = smem_u32(sm6);

    const int tid  = threadIdx.x;
    const int w    = tid >> 5;
    const int lane = tid & 31;
    const int wm   = w & 1;            // 64-row half
    const int wn   = w >> 1;           // 32-col quarter
    const int m0   = blockIdx.y * 128;
    const int n0   = blockIdx.x * 128;
    const int z    = blockIdx.z;
    const __half* W = W0 + (size_t)z * WOFF1;

    float acc[4][4][4];
#pragma unroll
    for (int i = 0; i < 4; i++)
#pragma unroll
        for (int j = 0; j < 4; j++)
#pragma unroll
            for (int q = 0; q < 4; q++) acc[i][j][q] = 0.f;

    auto load_stage = [&](int it) {
        const uint32_t st = sb + (uint32_t)(it % GS6) * STB;
        const int kb = it * 32;
#pragma unroll
        for (int j = 0; j < 2; j++) {
            int idx = tid * 2 + j;
            int row = idx >> 2, u = idx & 3;
            uint32_t off = row * 64 + ((u ^ ((row >> 1) & 3)) << 4);
            const __half* ar = A + (size_t)(m0 + row) * AK + kb + u * 8;
            const __half* wr = W + (size_t)(n0 + row) * D_ + kb + u * 8;
            CP_ASYNC16(st + off, (const void*)ar);                       // A hi
            if (ASPLIT)
                CP_ASYNC16(st + TB6 + off, (const void*)(ar + D_));      // A lo
            CP_ASYNC16(st + (NT - 1) * TB6 + off, (const void*)wr);      // W
        }
        CP_COMMIT();
    };

    load_stage(0);
    load_stage(1);

    for (int it = 0; it < GIT6; it++) {
        CP_WAIT1();
        __syncthreads();
        if (it + 2 < GIT6) load_stage(it + 2);
        else CP_COMMIT();

        const uint32_t aH = sb + (uint32_t)(it % GS6) * STB;
        const uint32_t aL = aH + TB6;
        const uint32_t wB = aH + (NT - 1) * TB6;

#pragma unroll
        for (int ks = 0; ks < 2; ks++) {
            uint32_t ah[4][4], al[4][4];
#pragma unroll
            for (int fm = 0; fm < 4; fm++) {
                int row = wm * 64 + fm * 16 + (lane & 15);
                int u = ks * 2 + (lane >> 4);
                uint32_t off = row * 64 + ((u ^ ((row >> 1) & 3)) << 4);
                LDMATRIX_X4(ah[fm][0], ah[fm][1], ah[fm][2], ah[fm][3], aH + off);
                if (ASPLIT)
                    LDMATRIX_X4(al[fm][0], al[fm][1], al[fm][2], al[fm][3], aL + off);
            }
            uint32_t b[2][4];
#pragma unroll
            for (int fp = 0; fp < 2; fp++) {
                int n = wn * 32 + fp * 16 + (lane & 7) + ((lane >> 4) << 3);
                int u = ks * 2 + ((lane >> 3) & 1);
                uint32_t off = n * 64 + ((u ^ ((n >> 1) & 3)) << 4);
                LDMATRIX_X4(b[fp][0], b[fp][1], b[fp][2], b[fp][3], wB + off);
            }
#pragma unroll
            for (int fm = 0; fm < 4; fm++)
#pragma unroll
                for (int fp = 0; fp < 2; fp++) {
                    MMA_F16(acc[fm][fp * 2 + 0], ah[fm], b[fp][0], b[fp][1]);
                    MMA_F16(acc[fm][fp * 2 + 1], ah[fm], b[fp][2], b[fp][3]);
                    if (ASPLIT) {
                        MMA_F16(acc[fm][fp * 2 + 0], al[fm], b[fp][0], b[fp][1]);
                        MMA_F16(acc[fm][fp * 2 + 1], al[fm], b[fp][2], b[fp][3]);
                    }
                }
        }
    }

    const int cr = lane >> 2;
    const int cc = 2 * (lane & 3);
    const float sc = (SPLITOUT && blockIdx.z == 0) ? 0.125f : 1.f;
#pragma unroll
    for (int fm = 0; fm < 4; fm++) {
        int r = m0 + wm * 64 + fm * 16 + cr;
#pragma unroll
        for (int fn = 0; fn < 4; fn++) {
            int col = n0 + wn * 32 + fn * 8 + cc;
            if (SPLITOUT) {
                int bb = r >> 11, t = r & (T_ - 1);
                int hh = col >> 6, hs = col & 63;
                size_t base = (((size_t)z * (B_ * NH_) + bb * NH_ + hh) * T_ + t) * HS_ + hs;
                *(__half2*)(outq + base) =
                    __floats2half2_rn(acc[fm][fn][0] * sc, acc[fm][fn][1] * sc);
                *(__half2*)(outq + base + 8 * HS_) =
                    __floats2half2_rn(acc[fm][fn][2] * sc, acc[fm][fn][3] * sc);
            } else {
                *(float2*)(outf + (size_t)r * D_ + col) =
                    make_float2(acc[fm][fn][0], acc[fm][fn][1]);
                *(float2*)(outf + (size_t)(r + 8) * D_ + col) =
                    make_float2(acc[fm][fn][2], acc[fm][fn][3]);
            }
        }
    }
}
#define GEMM6_SMEM_A0 (GS6 * 2 * TB6)   // 48KB
#define GEMM6_SMEM_A1 (GS6 * 3 * TB6)   // 72KB

// ================== fp16 flash attention ===================================
// S = q16 k16 (1 term); O += p16 * v16 (1 term, P fp16-rounded).
// SMEM: Q 16KB @0; KV 3-stage ring @16384, stage 16KB. Swizzle: u ^ (row&7).
#define QT 128
#define KT 64
#define ASM_Q 0u
#define ASM_KV 16384u
#define KVST 16384u
#define ATTN_SMEM (16384 + 3 * 16384)   // 64KB
#define NKT (T_ / KT)                   // 32

__global__ __launch_bounds__(256, 2)
void attn_hmma(const __half* __restrict__ QKV, const float* __restrict__ btab,
               __half* __restrict__ out2) {
    extern __shared__ char sm[];
    const uint32_t sb = smem_u32(sm);

    const int tid  = threadIdx.x;
    const int w    = tid >> 5;
    const int lane = tid & 31;
    const int bh = blockIdx.y;
    const int h  = bh & (NH_ - 1);
    const int b  = bh >> 4;
    const int q0 = blockIdx.x * QT;

    const __half* Qq = QKV + (size_t)bh * T_ * HS_;
    const __half* Kq = QKV + TQ1 + (size_t)bh * T_ * HS_;
    const __half* Vq = QKV + 2 * TQ1 + (size_t)bh * T_ * HS_;
    const float* bias_h = btab + h * NBIAS + (T_ - 1);

    // ---- Q preload (1 group) ----
#pragma unroll
    for (int j = 0; j < 4; j++) {
        int idx = tid * 4 + j;
        int row = idx >> 3, u = idx & 7;
        uint32_t dst = sb + ASM_Q + row * 128 + ((u ^ (row & 7)) << 4);
        CP_ASYNC16(dst, (const void*)(Qq + (size_t)(q0 + row) * HS_ + u * 8));
    }
    CP_COMMIT();

    auto load_kv = [&](int t) {
        const uint32_t st = sb + ASM_KV + (uint32_t)(t % 3) * KVST;
        const int k0 = t * KT;
#pragma unroll
        for (int j = 0; j < 2; j++) {
            int idx = tid * 2 + j;
            int row = idx >> 3, u = idx & 7;
            uint32_t off = row * 128 + ((u ^ (row & 7)) << 4);
            const size_t goff = (size_t)(k0 + row) * HS_ + u * 8;
            CP_ASYNC16(st + off,        (const void*)(Kq + goff));
            CP_ASYNC16(st + 8192 + off, (const void*)(Vq + goff));
        }
        CP_COMMIT();
    };

    load_kv(0);
    load_kv(1);
    load_kv(2);

    float ofr[8][4];
    float mrow[2] = {-1e30f, -1e30f};
    float lrow[2] = {0.f, 0.f};
#pragma unroll
    for (int j = 0; j < 8; j++)
#pragma unroll
        for (int q = 0; q < 4; q++) ofr[j][q] = 0.f;

    for (int t = 0; t < NKT; t++) {
        CP_WAIT2();
        __syncthreads();

        const uint32_t kB = sb + ASM_KV + (uint32_t)(t % 3) * KVST;
        const uint32_t vB = kB + 8192;
        const int k0 = t * KT;

        // ---- S = q k^T (single fp16 term) ----
        float sf[8][4];
#pragma unroll
        for (int j = 0; j < 8; j++)
#pragma unroll
            for (int q = 0; q < 4; q++) sf[j][q] = 0.f;

#pragma unroll
        for (int u = 0; u < 4; u++) {
            uint32_t a[4];
            {
                int row = w * 16 + (lane & 15);
                int un = 2 * u + (lane >> 4);
                uint32_t ad = sb + ASM_Q + row * 128 + ((un ^ (row & 7)) << 4);
                LDMATRIX_X4(a[0], a[1], a[2], a[3], ad);
            }
#pragma unroll
            for (int fp = 0; fp < 4; fp++) {
                int n = fp * 16 + (lane & 7) + ((lane >> 4) << 3);
                int un = 2 * u + ((lane >> 3) & 1);
                uint32_t b0, b1, b2, b3;
                uint32_t bd = kB + n * 128 + ((un ^ (n & 7)) << 4);
                LDMATRIX_X4(b0, b1, b2, b3, bd);
                MMA_F16(sf[2 * fp + 0], a, b0, b1);
                MMA_F16(sf[2 * fp + 1], a, b2, b3);
            }
        }

        // ---- + bias ----
        const int r0g = q0 + w * 16 + (lane >> 2);
#pragma unroll
        for (int j = 0; j < 8; j++) {
            int dk = k0 + 8 * j + 2 * (lane & 3) - r0g;
            sf[j][0] += bias_h[dk];
            sf[j][1] += bias_h[dk + 1];
            sf[j][2] += bias_h[dk - 8];
            sf[j][3] += bias_h[dk - 7];
        }

        // ---- online softmax ----
        float mt0 = -1e30f, mt1 = -1e30f;
#pragma unroll
        for (int j = 0; j < 8; j++) {
            mt0 = fmaxf(mt0, fmaxf(sf[j][0], sf[j][1]));
            mt1 = fmaxf(mt1, fmaxf(sf[j][2], sf[j][3]));
        }
        mt0 = fmaxf(mt0, __shfl_xor_sync(0xffffffffu, mt0, 1));
        mt0 = fmaxf(mt0, __shfl_xor_sync(0xffffffffu, mt0, 2));
        mt1 = fmaxf(mt1, __shfl_xor_sync(0xffffffffu, mt1, 1));
        mt1 = fmaxf(mt1, __shfl_xor_sync(0xffffffffu, mt1, 2));

        float mn0 = fmaxf(mrow[0], mt0), mn1 = fmaxf(mrow[1], mt1);
        float alpha0 = __expf(mrow[0] - mn0), alpha1 = __expf(mrow[1] - mn1);
        mrow[0] = mn0; mrow[1] = mn1;

        float ls0 = 0.f, ls1 = 0.f;
#pragma unroll
        for (int j = 0; j < 8; j++) {
            sf[j][0] = __expf(sf[j][0] - mn0);
            sf[j][1] = __expf(sf[j][1] - mn0);
            sf[j][2] = __expf(sf[j][2] - mn1);
            sf[j][3] = __expf(sf[j][3] - mn1);
            ls0 += sf[j][0] + sf[j][1];
            ls1 += sf[j][2] + sf[j][3];
        }
        ls0 += __shfl_xor_sync(0xffffffffu, ls0, 1);
        ls0 += __shfl_xor_sync(0xffffffffu, ls0, 2);
        ls1 += __shfl_xor_sync(0xffffffffu, ls1, 1);
        ls1 += __shfl_xor_sync(0xffffffffu, ls1, 2);
        lrow[0] = lrow[0] * alpha0 + ls0;
        lrow[1] = lrow[1] * alpha1 + ls1;
#pragma unroll
        for (int j = 0; j < 8; j++) {
            ofr[j][0] *= alpha0; ofr[j][1] *= alpha0;
            ofr[j][2] *= alpha1; ofr[j][3] *= alpha1;
        }

        // ---- O += p16 * v16 (single term) ----
#pragma unroll
        for (int kk = 0; kk < 4; kk++) {
            uint32_t ph[4];
            ph[0] = packh(sf[2 * kk][0],     sf[2 * kk][1]);
            ph[1] = packh(sf[2 * kk][2],     sf[2 * kk][3]);
            ph[2] = packh(sf[2 * kk + 1][0], sf[2 * kk + 1][1]);
            ph[3] = packh(sf[2 * kk + 1][2], sf[2 * kk + 1][3]);
            const int g = lane >> 3;
            const int rowv = kk * 16 + ((g & 1) << 3) + (lane & 7);
#pragma unroll
            for (int fb = 0; fb < 4; fb++) {
                int unit = fb * 2 + (g >> 1);
                uint32_t v0, v1, v2, v3;
                uint32_t av = vB + rowv * 128 + ((unit ^ (rowv & 7)) << 4);
                LDMATRIX_X4_T(v0, v1, v2, v3, av);
                MMA_F16(ofr[2 * fb + 0], ph, v0, v1);
                MMA_F16(ofr[2 * fb + 1], ph, v2, v3);
            }
        }

        __syncthreads();
        if (t + 3 < NKT) load_kv(t + 3);
        else CP_COMMIT();
    }

    // ---- epilogue: write fp16 [hi | lo] AO for the 2-term out-proj ----
    const float inv0 = 1.f / lrow[0], inv1 = 1.f / lrow[1];
    const int r0 = q0 + w * 16 + (lane >> 2), r1 = r0 + 8;
    __half* row0 = out2 + (size_t)(b * T_ + r0) * K2_;
    __half* row1 = out2 + (size_t)(b * T_ + r1) * K2_;
#pragma unroll
    for (int j = 0; j < 8; j++) {
        int col = h * HS_ + 8 * j + 2 * (lane & 3);
        uint32_t hi, lo;
        splith(ofr[j][0] * inv0, ofr[j][1] * inv0, hi, lo);
        *(uint32_t*)(row0 + col)      = hi;
        *(uint32_t*)(row0 + D_ + col) = lo;
        splith(ofr[j][2] * inv1, ofr[j][3] * inv1, hi, lo);
        *(uint32_t*)(row1 + col)      = hi;
        *(uint32_t*)(row1 + D_ + col) = lo;
    }
}

// ================== launch ==================================================
extern "C" void kernel_launch(void* const* d_in, const int* in_sizes, int n_in,
                              void* d_out, int out_size) {
    const float* queries = (const float*)d_in[0];
    const float* Wq      = (const float*)d_in[1];
    const float* Wk      = (const float*)d_in[2];
    const float* Wv      = (const float*)d_in[3];
    const float* Wo      = (const float*)d_in[4];
    const float* rel_emb = (const float*)d_in[5];
    float* out = (float*)d_out;

    __half *gA1h, *gAO2h, *gW1, *gQKV1;
    float *gB;
    cudaGetSymbolAddress((void**)&gA1h,  g_A1h);
    cudaGetSymbolAddress((void**)&gAO2h, g_AO2h);
    cudaGetSymbolAddress((void**)&gW1,   g_W1);
    cudaGetSymbolAddress((void**)&gQKV1, g_QKV1);
    cudaGetSymbolAddress((void**)&gB,    g_bias);

    cudaFuncSetAttribute(attn_hmma, cudaFuncAttributeMaxDynamicSharedMemorySize, ATTN_SMEM);
    cudaFuncSetAttribute(gemm_hmma6<0, 1>, cudaFuncAttributeMaxDynamicSharedMemorySize, GEMM6_SMEM_A0);
    cudaFuncSetAttribute(gemm_hmma6<1, 0>, cudaFuncAttributeMaxDynamicSharedMemorySize, GEMM6_SMEM_A1);

    // operand prep (all fp16; queries single-term now)
    convA_f16<<<(M_ * (D_ / 4) + 255) / 256, 256>>>(queries, gA1h, M_ * (D_ / 4));
    convA_f16<<<(D_ * (D_ / 4) + 255) / 256, 256>>>(Wq, gW1 + 0 * WOFF1, D_ * (D_ / 4));
    convA_f16<<<(D_ * (D_ / 4) + 255) / 256, 256>>>(Wk, gW1 + 1 * WOFF1, D_ * (D_ / 4));
    convA_f16<<<(D_ * (D_ / 4) + 255) / 256, 256>>>(Wv, gW1 + 2 * WOFF1, D_ * (D_ / 4));
    convA_f16<<<(D_ * (D_ / 4) + 255) / 256, 256>>>(Wo, gW1 + 3 * WOFF1, D_ * (D_ / 4));

    // fused Q/K/V projections (single-term) -> fp16 [z][bh][t][hs]
    dim3 gGrid(D_ / 128, M_ / 128, 3);
    gemm_hmma6<0, 1><<<gGrid, 256, GEMM6_SMEM_A0>>>(gA1h, gW1, nullptr, gQKV1);

    bias_kernel<<<(NH_ * NBIAS + 255) / 256, 256>>>(rel_emb, gB);

    // fp16 attention -> fp16 [hi|lo] AO
    dim3 aGrid(T_ / QT, B_ * NH_);
    attn_hmma<<<aGrid, 256, ATTN_SMEM>>>(gQKV1, gB, gAO2h);

    // output projection (2-term A for accuracy insurance, fp32 out)
    dim3 oGrid(D_ / 128, M_ / 128, 1);
    gemm_hmma6<1, 0><<<oGrid, 256, GEMM6_SMEM_A1>>>(gAO2h, gW1 + 3 * WOFF1, out, nullptr);
}

// round 12
// speedup vs baseline: 2.3059x; 1.1132x over previous
#include <cuda_runtime.h>
#include <cuda_bf16.h>
#include <cuda_fp16.h>
#include <math.h>
#include <stdint.h>

#define B_  4
#define T_  2048
#define D_  1024
#define NH_ 16
#define HS_ 64
#define NBIAS (2*T_ - 1)   // 4095
#define M_  (B_*T_)        // 8192

// ---------------- scratch (device globals: no allocation allowed) ----------
__device__ __half g_A1h [M_*(size_t)D_];     // queries fp16
__device__ __half g_AO1h[M_*(size_t)D_];     // attn-out fp16
__device__ __half g_W1  [4*(size_t)D_*D_];   // weights fp16
__device__ __half g_QKV1[3*(size_t)NH_*B_*T_*HS_]; // fp16 [z][bh][t][hs]
__device__ float g_bias[NH_*NBIAS];

#define TQ1 ((size_t)NH_*B_*T_*HS_)    // per-tensor offset in g_QKV1
#define WOFF1 ((size_t)D_*D_)          // per-weight offset in g_W1

// ============================ PTX helpers ==================================
__device__ __forceinline__ uint32_t smem_u32(const void* p) {
    uint32_t a;
    asm("{ .reg .u64 t; cvta.to.shared.u64 t, %1; cvt.u32.u64 %0, t; }" : "=r"(a) : "l"(p));
    return a;
}
#define CP_ASYNC16(dst, src) \
    asm volatile("cp.async.cg.shared.global [%0], [%1], 16;" :: "r"(dst), "l"(src) : "memory")
#define CP_COMMIT() asm volatile("cp.async.commit_group;" ::: "memory")
#define CP_WAIT1()  asm volatile("cp.async.wait_group 1;" ::: "memory")
#define CP_WAIT2()  asm volatile("cp.async.wait_group 2;" ::: "memory")

#define LDMATRIX_X4(r0, r1, r2, r3, addr) \
    asm volatile("ldmatrix.sync.aligned.m8n8.x4.shared.b16 {%0,%1,%2,%3}, [%4];" \
                 : "=r"(r0), "=r"(r1), "=r"(r2), "=r"(r3) : "r"(addr))
#define LDMATRIX_X4_T(r0, r1, r2, r3, addr) \
    asm volatile("ldmatrix.sync.aligned.m8n8.x4.trans.shared.b16 {%0,%1,%2,%3}, [%4];" \
                 : "=r"(r0), "=r"(r1), "=r"(r2), "=r"(r3) : "r"(addr))

#define MMA_F16(c, a, b0, b1) \
    asm volatile("mma.sync.aligned.m16n8k16.row.col.f32.f16.f16.f32 " \
                 "{%0,%1,%2,%3}, {%4,%5,%6,%7}, {%8,%9}, {%0,%1,%2,%3};" \
                 : "+f"((c)[0]), "+f"((c)[1]), "+f"((c)[2]), "+f"((c)[3]) \
                 : "r"((a)[0]), "r"((a)[1]), "r"((a)[2]), "r"((a)[3]), "r"(b0), "r"(b1))

__device__ __forceinline__ uint32_t packh(float a, float b) {
    __half2 v = __floats2half2_rn(a, b);
    return *(uint32_t*)&v;
}

// ================== bias table =============================================
__device__ __forceinline__ int bucket_of(int rp) {
    int b = (rp > 0) ? 16 : 0;
    int a = rp < 0 ? -rp : rp;
    if (a < 8) return b + a;
    double v = 7.0 + (log((double)a / 7.0) / log(128.0 / 7.0)) * 8.0;
    int large = (int)v;
    if (large > 15) large = 15;
    return b + large;
}
__global__ void bias_kernel(const float* __restrict__ rel_emb, float* __restrict__ btab) {
    int idx = blockIdx.x * blockDim.x + threadIdx.x;
    if (idx >= NH_ * NBIAS) return;
    int h = idx / NBIAS;
    int x = idx % NBIAS;
    btab[idx] = rel_emb[bucket_of(x - (T_ - 1)) * NH_ + h];
}

// ================== fused fp32 -> fp16 conversion (queries + 4 weights) ====
#define NQ4 (M_ * (D_ / 4))          // 2,097,152 float4s for queries
#define NW4 (D_ * (D_ / 4))          // 262,144 per weight
#define NCONV (NQ4 + 4 * NW4)

__global__ void conv_fused(const float* __restrict__ q,
                           const float* __restrict__ w0, const float* __restrict__ w1,
                           const float* __restrict__ w2, const float* __restrict__ w3,
                           __half* __restrict__ outA, __half* __restrict__ outW) {
    int i = blockIdx.x * blockDim.x + threadIdx.x;
    if (i >= NCONV) return;
    const float* src;
    __half* dst;
    if (i < NQ4) { src = q + (size_t)i * 4; dst = outA + (size_t)i * 4; }
    else {
        int j = i - NQ4;
        int wsel = j / NW4, off = j % NW4;
        const float* ws = (wsel == 0) ? w0 : (wsel == 1) ? w1 : (wsel == 2) ? w2 : w3;
        src = ws + (size_t)off * 4;
        dst = outW + (size_t)wsel * WOFF1 + (size_t)off * 4;
    }
    float4 v = *(const float4*)src;
    __half2* o = (__half2*)dst;
    o[0] = __floats2half2_rn(v.x, v.y);
    o[1] = __floats2half2_rn(v.z, v.w);
}

// ================== fp16 GEMM (single-term) ================================
// out[m,n] = sum_k A[m,k] * W[n,k].  CTA 128x128, BK=32, 8 warps (64x32),
// 3-stage cp.async (stage = A 8KB + W 8KB), 2 CTA/SM.
// SPLITOUT=1: fp16 [z][bh][t][hs] (Q scaled 1/8); 0: fp32 [m,n].
#define GS6 3
#define TB6 8192
#define GIT6 32
#define GEMM6_SMEM (GS6 * 2 * TB6)   // 48KB

template <int SPLITOUT>
__global__ __launch_bounds__(256, 2)
void gemm_hmma6(const __half* __restrict__ A, const __half* __restrict__ W0,
                float* __restrict__ outf, __half* __restrict__ outq) {
    extern __shared__ char sm6[];
    const uint32_t sb = smem_u32(sm6);

    const int tid  = threadIdx.x;
    const int w    = tid >> 5;
    const int lane = tid & 31;
    const int wm   = w & 1;            // 64-row half
    const int wn   = w >> 1;           // 32-col quarter
    const int m0   = blockIdx.y * 128;
    const int n0   = blockIdx.x * 128;
    const int z    = blockIdx.z;
    const __half* W = W0 + (size_t)z * WOFF1;

    float acc[4][4][4];
#pragma unroll
    for (int i = 0; i < 4; i++)
#pragma unroll
        for (int j = 0; j < 4; j++)
#pragma unroll
            for (int q = 0; q < 4; q++) acc[i][j][q] = 0.f;

    auto load_stage = [&](int it) {
        const uint32_t st = sb + (uint32_t)(it % GS6) * (2 * TB6);
        const int kb = it * 32;
#pragma unroll
        for (int j = 0; j < 2; j++) {
            int idx = tid * 2 + j;
            int row = idx >> 2, u = idx & 3;
            uint32_t off = row * 64 + ((u ^ ((row >> 1) & 3)) << 4);
            CP_ASYNC16(st + off,       (const void*)(A + (size_t)(m0 + row) * D_ + kb + u * 8));
            CP_ASYNC16(st + TB6 + off, (const void*)(W + (size_t)(n0 + row) * D_ + kb + u * 8));
        }
        CP_COMMIT();
    };

    load_stage(0);
    load_stage(1);

    for (int it = 0; it < GIT6; it++) {
        CP_WAIT1();
        __syncthreads();
        if (it + 2 < GIT6) load_stage(it + 2);
        else CP_COMMIT();

        const uint32_t aB = sb + (uint32_t)(it % GS6) * (2 * TB6);
        const uint32_t wB = aB + TB6;

#pragma unroll
        for (int ks = 0; ks < 2; ks++) {
            uint32_t a[4][4];
#pragma unroll
            for (int fm = 0; fm < 4; fm++) {
                int row = wm * 64 + fm * 16 + (lane & 15);
                int u = ks * 2 + (lane >> 4);
                uint32_t off = row * 64 + ((u ^ ((row >> 1) & 3)) << 4);
                LDMATRIX_X4(a[fm][0], a[fm][1], a[fm][2], a[fm][3], aB + off);
            }
            uint32_t b[2][4];
#pragma unroll
            for (int fp = 0; fp < 2; fp++) {
                int n = wn * 32 + fp * 16 + (lane & 7) + ((lane >> 4) << 3);
                int u = ks * 2 + ((lane >> 3) & 1);
                uint32_t off = n * 64 + ((u ^ ((n >> 1) & 3)) << 4);
                LDMATRIX_X4(b[fp][0], b[fp][1], b[fp][2], b[fp][3], wB + off);
            }
#pragma unroll
            for (int fm = 0; fm < 4; fm++)
#pragma unroll
                for (int fp = 0; fp < 2; fp++) {
                    MMA_F16(acc[fm][fp * 2 + 0], a[fm], b[fp][0], b[fp][1]);
                    MMA_F16(acc[fm][fp * 2 + 1], a[fm], b[fp][2], b[fp][3]);
                }
        }
    }

    const int cr = lane >> 2;
    const int cc = 2 * (lane & 3);
    const float sc = (SPLITOUT && blockIdx.z == 0) ? 0.125f : 1.f;
#pragma unroll
    for (int fm = 0; fm < 4; fm++) {
        int r = m0 + wm * 64 + fm * 16 + cr;
#pragma unroll
        for (int fn = 0; fn < 4; fn++) {
            int col = n0 + wn * 32 + fn * 8 + cc;
            if (SPLITOUT) {
                int bb = r >> 11, t = r & (T_ - 1);
                int hh = col >> 6, hs = col & 63;
                size_t base = (((size_t)z * (B_ * NH_) + bb * NH_ + hh) * T_ + t) * HS_ + hs;
                *(__half2*)(outq + base) =
                    __floats2half2_rn(acc[fm][fn][0] * sc, acc[fm][fn][1] * sc);
                *(__half2*)(outq + base + 8 * HS_) =
                    __floats2half2_rn(acc[fm][fn][2] * sc, acc[fm][fn][3] * sc);
            } else {
                *(float2*)(outf + (size_t)r * D_ + col) =
                    make_float2(acc[fm][fn][0], acc[fm][fn][1]);
                *(float2*)(outf + (size_t)(r + 8) * D_ + col) =
                    make_float2(acc[fm][fn][2], acc[fm][fn][3]);
            }
        }
    }
}

// ================== fp16 flash attention ===================================
// S = q16 k16 (1 term); O += p16 * v16 (1 term).
// SMEM: Q 16KB @0; KV 3-stage ring @16384, stage 16KB. Swizzle: u ^ (row&7).
#define QT 128
#define KT 64
#define ASM_Q 0u
#define ASM_KV 16384u
#define KVST 16384u
#define ATTN_SMEM (16384 + 3 * 16384)   // 64KB
#define NKT (T_ / KT)                   // 32

__global__ __launch_bounds__(256, 2)
void attn_hmma(const __half* __restrict__ QKV, const float* __restrict__ btab,
               __half* __restrict__ out1) {
    extern __shared__ char sm[];
    const uint32_t sb = smem_u32(sm);

    const int tid  = threadIdx.x;
    const int w    = tid >> 5;
    const int lane = tid & 31;
    const int bh = blockIdx.y;
    const int h  = bh & (NH_ - 1);
    const int b  = bh >> 4;
    const int q0 = blockIdx.x * QT;

    const __half* Qq = QKV + (size_t)bh * T_ * HS_;
    const __half* Kq = QKV + TQ1 + (size_t)bh * T_ * HS_;
    const __half* Vq = QKV + 2 * TQ1 + (size_t)bh * T_ * HS_;
    const float* bias_h = btab + h * NBIAS + (T_ - 1);

    // ---- Q preload (1 group) ----
#pragma unroll
    for (int j = 0; j < 4; j++) {
        int idx = tid * 4 + j;
        int row = idx >> 3, u = idx & 7;
        uint32_t dst = sb + ASM_Q + row * 128 + ((u ^ (row & 7)) << 4);
        CP_ASYNC16(dst, (const void*)(Qq + (size_t)(q0 + row) * HS_ + u * 8));
    }
    CP_COMMIT();

    auto load_kv = [&](int t) {
        const uint32_t st = sb + ASM_KV + (uint32_t)(t % 3) * KVST;
        const int k0 = t * KT;
#pragma unroll
        for (int j = 0; j < 2; j++) {
            int idx = tid * 2 + j;
            int row = idx >> 3, u = idx & 7;
            uint32_t off = row * 128 + ((u ^ (row & 7)) << 4);
            const size_t goff = (size_t)(k0 + row) * HS_ + u * 8;
            CP_ASYNC16(st + off,        (const void*)(Kq + goff));
            CP_ASYNC16(st + 8192 + off, (const void*)(Vq + goff));
        }
        CP_COMMIT();
    };

    load_kv(0);
    load_kv(1);
    load_kv(2);

    float ofr[8][4];
    float mrow[2] = {-1e30f, -1e30f};
    float lrow[2] = {0.f, 0.f};
#pragma unroll
    for (int j = 0; j < 8; j++)
#pragma unroll
        for (int q = 0; q < 4; q++) ofr[j][q] = 0.f;

    for (int t = 0; t < NKT; t++) {
        CP_WAIT2();
        __syncthreads();

        const uint32_t kB = sb + ASM_KV + (uint32_t)(t % 3) * KVST;
        const uint32_t vB = kB + 8192;
        const int k0 = t * KT;

        // ---- S = q k^T ----
        float sf[8][4];
#pragma unroll
        for (int j = 0; j < 8; j++)
#pragma unroll
            for (int q = 0; q < 4; q++) sf[j][q] = 0.f;

#pragma unroll
        for (int u = 0; u < 4; u++) {
            uint32_t a[4];
            {
                int row = w * 16 + (lane & 15);
                int un = 2 * u + (lane >> 4);
                uint32_t ad = sb + ASM_Q + row * 128 + ((un ^ (row & 7)) << 4);
                LDMATRIX_X4(a[0], a[1], a[2], a[3], ad);
            }
#pragma unroll
            for (int fp = 0; fp < 4; fp++) {
                int n = fp * 16 + (lane & 7) + ((lane >> 4) << 3);
                int un = 2 * u + ((lane >> 3) & 1);
                uint32_t b0, b1, b2, b3;
                uint32_t bd = kB + n * 128 + ((un ^ (n & 7)) << 4);
                LDMATRIX_X4(b0, b1, b2, b3, bd);
                MMA_F16(sf[2 * fp + 0], a, b0, b1);
                MMA_F16(sf[2 * fp + 1], a, b2, b3);
            }
        }

        // ---- + bias ----
        const int r0g = q0 + w * 16 + (lane >> 2);
#pragma unroll
        for (int j = 0; j < 8; j++) {
            int dk = k0 + 8 * j + 2 * (lane & 3) - r0g;
            sf[j][0] += bias_h[dk];
            sf[j][1] += bias_h[dk + 1];
            sf[j][2] += bias_h[dk - 8];
            sf[j][3] += bias_h[dk - 7];
        }

        // ---- online softmax ----
        float mt0 = -1e30f, mt1 = -1e30f;
#pragma unroll
        for (int j = 0; j < 8; j++) {
            mt0 = fmaxf(mt0, fmaxf(sf[j][0], sf[j][1]));
            mt1 = fmaxf(mt1, fmaxf(sf[j][2], sf[j][3]));
        }
        mt0 = fmaxf(mt0, __shfl_xor_sync(0xffffffffu, mt0, 1));
        mt0 = fmaxf(mt0, __shfl_xor_sync(0xffffffffu, mt0, 2));
        mt1 = fmaxf(mt1, __shfl_xor_sync(0xffffffffu, mt1, 1));
        mt1 = fmaxf(mt1, __shfl_xor_sync(0xffffffffu, mt1, 2));

        float mn0 = fmaxf(mrow[0], mt0), mn1 = fmaxf(mrow[1], mt1);
        float alpha0 = __expf(mrow[0] - mn0), alpha1 = __expf(mrow[1] - mn1);
        mrow[0] = mn0; mrow[1] = mn1;

        float ls0 = 0.f, ls1 = 0.f;
#pragma unroll
        for (int j = 0; j < 8; j++) {
            sf[j][0] = __expf(sf[j][0] - mn0);
            sf[j][1] = __expf(sf[j][1] - mn0);
            sf[j][2] = __expf(sf[j][2] - mn1);
            sf[j][3] = __expf(sf[j][3] - mn1);
            ls0 += sf[j][0] + sf[j][1];
            ls1 += sf[j][2] + sf[j][3];
        }
        ls0 += __shfl_xor_sync(0xffffffffu, ls0, 1);
        ls0 += __shfl_xor_sync(0xffffffffu, ls0, 2);
        ls1 += __shfl_xor_sync(0xffffffffu, ls1, 1);
        ls1 += __shfl_xor_sync(0xffffffffu, ls1, 2);
        lrow[0] = lrow[0] * alpha0 + ls0;
        lrow[1] = lrow[1] * alpha1 + ls1;
#pragma unroll
        for (int j = 0; j < 8; j++) {
            ofr[j][0] *= alpha0; ofr[j][1] *= alpha0;
            ofr[j][2] *= alpha1; ofr[j][3] *= alpha1;
        }

        // ---- O += p16 * v16 ----
#pragma unroll
        for (int kk = 0; kk < 4; kk++) {
            uint32_t ph[4];
            ph[0] = packh(sf[2 * kk][0],     sf[2 * kk][1]);
            ph[1] = packh(sf[2 * kk][2],     sf[2 * kk][3]);
            ph[2] = packh(sf[2 * kk + 1][0], sf[2 * kk + 1][1]);
            ph[3] = packh(sf[2 * kk + 1][2], sf[2 * kk + 1][3]);
            const int g = lane >> 3;
            const int rowv = kk * 16 + ((g & 1) << 3) + (lane & 7);
#pragma unroll
            for (int fb = 0; fb < 4; fb++) {
                int unit = fb * 2 + (g >> 1);
                uint32_t v0, v1, v2, v3;
                uint32_t av = vB + rowv * 128 + ((unit ^ (rowv & 7)) << 4);
                LDMATRIX_X4_T(v0, v1, v2, v3, av);
                MMA_F16(ofr[2 * fb + 0], ph, v0, v1);
                MMA_F16(ofr[2 * fb + 1], ph, v2, v3);
            }
        }

        __syncthreads();
        if (t + 3 < NKT) load_kv(t + 3);
        else CP_COMMIT();
    }

    // ---- epilogue: write fp16 AO (single) for the out-proj ----
    const float inv0 = 1.f / lrow[0], inv1 = 1.f / lrow[1];
    const int r0 = q0 + w * 16 + (lane >> 2), r1 = r0 + 8;
    __half* row0 = out1 + (size_t)(b * T_ + r0) * D_;
    __half* row1 = out1 + (size_t)(b * T_ + r1) * D_;
#pragma unroll
    for (int j = 0; j < 8; j++) {
        int col = h * HS_ + 8 * j + 2 * (lane & 3);
        *(uint32_t*)(row0 + col) = packh(ofr[j][0] * inv0, ofr[j][1] * inv0);
        *(uint32_t*)(row1 + col) = packh(ofr[j][2] * inv1, ofr[j][3] * inv1);
    }
}

// ================== launch ==================================================
extern "C" void kernel_launch(void* const* d_in, const int* in_sizes, int n_in,
                              void* d_out, int out_size) {
    const float* queries = (const float*)d_in[0];
    const float* Wq      = (const float*)d_in[1];
    const float* Wk      = (const float*)d_in[2];
    const float* Wv      = (const float*)d_in[3];
    const float* Wo      = (const float*)d_in[4];
    const float* rel_emb = (const float*)d_in[5];
    float* out = (float*)d_out;

    __half *gA1h, *gAO1h, *gW1, *gQKV1;
    float *gB;
    cudaGetSymbolAddress((void**)&gA1h,  g_A1h);
    cudaGetSymbolAddress((void**)&gAO1h, g_AO1h);
    cudaGetSymbolAddress((void**)&gW1,   g_W1);
    cudaGetSymbolAddress((void**)&gQKV1, g_QKV1);
    cudaGetSymbolAddress((void**)&gB,    g_bias);

    cudaFuncSetAttribute(attn_hmma, cudaFuncAttributeMaxDynamicSharedMemorySize, ATTN_SMEM);
    cudaFuncSetAttribute(gemm_hmma6<0>, cudaFuncAttributeMaxDynamicSharedMemorySize, GEMM6_SMEM);
    cudaFuncSetAttribute(gemm_hmma6<1>, cudaFuncAttributeMaxDynamicSharedMemorySize, GEMM6_SMEM);

    // 1) fused fp16 conversion (queries + 4 weights in one launch)
    conv_fused<<<(NCONV + 255) / 256, 256>>>(queries, Wq, Wk, Wv, Wo, gA1h, gW1);

    // 2) fused Q/K/V projections -> fp16 [z][bh][t][hs] (Q pre-scaled by 1/8)
    dim3 gGrid(D_ / 128, M_ / 128, 3);
    gemm_hmma6<1><<<gGrid, 256, GEMM6_SMEM>>>(gA1h, gW1, nullptr, gQKV1);

    // 3) bias table
    bias_kernel<<<(NH_ * NBIAS + 255) / 256, 256>>>(rel_emb, gB);

    // 4) fp16 attention -> fp16 AO
    dim3 aGrid(T_ / QT, B_ * NH_);
    attn_hmma<<<aGrid, 256, ATTN_SMEM>>>(gQKV1, gB, gAO1h);

    // 5) output projection (single-term, fp32 out)
    dim3 oGrid(D_ / 128, M_ / 128, 1);
    gemm_hmma6<0><<<oGrid, 256, GEMM6_SMEM>>>(gAO1h, gW1 + 3 * WOFF1, out, nullptr);
}

// round 13
// speedup vs baseline: 2.3102x; 1.0019x over previous
#include <cuda_runtime.h>
#include <cuda_bf16.h>
#include <cuda_fp16.h>
#include <math.h>
#include <stdint.h>

#define B_  4
#define T_  2048
#define D_  1024
#define NH_ 16
#define HS_ 64
#define NBIAS (2*T_ - 1)   // 4095
#define M_  (B_*T_)        // 8192
#define LOG2E 1.4426950408889634f

// ---------------- scratch (device globals: no allocation allowed) ----------
__device__ __half g_A1h [M_*(size_t)D_];     // queries fp16
__device__ __half g_AO1h[M_*(size_t)D_];     // attn-out fp16
__device__ __half g_W1  [4*(size_t)D_*D_];   // weights fp16
__device__ __half g_QKV1[3*(size_t)NH_*B_*T_*HS_]; // fp16 [z][bh][t][hs]
__device__ float g_bias[NH_*NBIAS];          // bias table, pre-scaled by log2(e)

#define TQ1 ((size_t)NH_*B_*T_*HS_)
#define WOFF1 ((size_t)D_*D_)

// ============================ PTX helpers ==================================
__device__ __forceinline__ uint32_t smem_u32(const void* p) {
    uint32_t a;
    asm("{ .reg .u64 t; cvta.to.shared.u64 t, %1; cvt.u32.u64 %0, t; }" : "=r"(a) : "l"(p));
    return a;
}
#define CP_ASYNC16(dst, src) \
    asm volatile("cp.async.cg.shared.global [%0], [%1], 16;" :: "r"(dst), "l"(src) : "memory")
#define CP_COMMIT() asm volatile("cp.async.commit_group;" ::: "memory")
#define CP_WAIT1()  asm volatile("cp.async.wait_group 1;" ::: "memory")
#define CP_WAIT2()  asm volatile("cp.async.wait_group 2;" ::: "memory")

#define LDMATRIX_X4(r0, r1, r2, r3, addr) \
    asm volatile("ldmatrix.sync.aligned.m8n8.x4.shared.b16 {%0,%1,%2,%3}, [%4];" \
                 : "=r"(r0), "=r"(r1), "=r"(r2), "=r"(r3) : "r"(addr))
#define LDMATRIX_X4_T(r0, r1, r2, r3, addr) \
    asm volatile("ldmatrix.sync.aligned.m8n8.x4.trans.shared.b16 {%0,%1,%2,%3}, [%4];" \
                 : "=r"(r0), "=r"(r1), "=r"(r2), "=r"(r3) : "r"(addr))

#define MMA_F16(c, a, b0, b1) \
    asm volatile("mma.sync.aligned.m16n8k16.row.col.f32.f16.f16.f32 " \
                 "{%0,%1,%2,%3}, {%4,%5,%6,%7}, {%8,%9}, {%0,%1,%2,%3};" \
                 : "+f"((c)[0]), "+f"((c)[1]), "+f"((c)[2]), "+f"((c)[3]) \
                 : "r"((a)[0]), "r"((a)[1]), "r"((a)[2]), "r"((a)[3]), "r"(b0), "r"(b1))

__device__ __forceinline__ uint32_t packh(float a, float b) {
    __half2 v = __floats2half2_rn(a, b);
    return *(uint32_t*)&v;
}
__device__ __forceinline__ float ex2a(float x) {
    float y;
    asm("ex2.approx.f32 %0, %1;" : "=f"(y) : "f"(x));
    return y;
}

// ================== bias bucketing =========================================
__device__ __forceinline__ int bucket_of(int rp) {
    int b = (rp > 0) ? 16 : 0;
    int a = rp < 0 ? -rp : rp;
    if (a < 8) return b + a;
    double v = 7.0 + (log((double)a / 7.0) / log(128.0 / 7.0)) * 8.0;
    int large = (int)v;
    if (large > 15) large = 15;
    return b + large;
}

// ========= fused prep: fp16 converts (queries + 4 weights) + bias table ====
#define NQ4 (M_ * (D_ / 4))
#define NW4 (D_ * (D_ / 4))
#define NCONV (NQ4 + 4 * NW4)
#define NB1 (NH_ * NBIAS)
#define NPREP (NCONV + NB1)

__global__ void prep_fused(const float* __restrict__ q,
                           const float* __restrict__ w0, const float* __restrict__ w1,
                           const float* __restrict__ w2, const float* __restrict__ w3,
                           const float* __restrict__ rel_emb,
                           __half* __restrict__ outA, __half* __restrict__ outW,
                           float* __restrict__ btab) {
    int i = blockIdx.x * blockDim.x + threadIdx.x;
    if (i >= NPREP) return;
    if (i >= NCONV) {               // bias-table element (log2-domain)
        int idx = i - NCONV;
        int h = idx / NBIAS, x = idx % NBIAS;
        btab[idx] = rel_emb[bucket_of(x - (T_ - 1)) * NH_ + h] * LOG2E;
        return;
    }
    const float* src;
    __half* dst;
    if (i < NQ4) { src = q + (size_t)i * 4; dst = outA + (size_t)i * 4; }
    else {
        int j = i - NQ4;
        int wsel = j / NW4, off = j % NW4;
        const float* ws = (wsel == 0) ? w0 : (wsel == 1) ? w1 : (wsel == 2) ? w2 : w3;
        src = ws + (size_t)off * 4;
        dst = outW + (size_t)wsel * WOFF1 + (size_t)off * 4;
    }
    float4 v = *(const float4*)src;
    __half2* o = (__half2*)dst;
    o[0] = __floats2half2_rn(v.x, v.y);
    o[1] = __floats2half2_rn(v.z, v.w);
}

// ================== fp16 GEMM (single-term) ================================
#define GS6 3
#define TB6 8192
#define GIT6 32
#define GEMM6_SMEM (GS6 * 2 * TB6)   // 48KB

template <int SPLITOUT>
__global__ __launch_bounds__(256, 2)
void gemm_hmma6(const __half* __restrict__ A, const __half* __restrict__ W0,
                float* __restrict__ outf, __half* __restrict__ outq) {
    extern __shared__ char sm6[];
    const uint32_t sb = smem_u32(sm6);

    const int tid  = threadIdx.x;
    const int w    = tid >> 5;
    const int lane = tid & 31;
    const int wm   = w & 1;
    const int wn   = w >> 1;
    const int m0   = blockIdx.y * 128;
    const int n0   = blockIdx.x * 128;
    const int z    = blockIdx.z;
    const __half* W = W0 + (size_t)z * WOFF1;

    float acc[4][4][4];
#pragma unroll
    for (int i = 0; i < 4; i++)
#pragma unroll
        for (int j = 0; j < 4; j++)
#pragma unroll
            for (int q = 0; q < 4; q++) acc[i][j][q] = 0.f;

    auto load_stage = [&](int it) {
        const uint32_t st = sb + (uint32_t)(it % GS6) * (2 * TB6);
        const int kb = it * 32;
#pragma unroll
        for (int j = 0; j < 2; j++) {
            int idx = tid * 2 + j;
            int row = idx >> 2, u = idx & 3;
            uint32_t off = row * 64 + ((u ^ ((row >> 1) & 3)) << 4);
            CP_ASYNC16(st + off,       (const void*)(A + (size_t)(m0 + row) * D_ + kb + u * 8));
            CP_ASYNC16(st + TB6 + off, (const void*)(W + (size_t)(n0 + row) * D_ + kb + u * 8));
        }
        CP_COMMIT();
    };

    load_stage(0);
    load_stage(1);

    for (int it = 0; it < GIT6; it++) {
        CP_WAIT1();
        __syncthreads();
        if (it + 2 < GIT6) load_stage(it + 2);
        else CP_COMMIT();

        const uint32_t aB = sb + (uint32_t)(it % GS6) * (2 * TB6);
        const uint32_t wB = aB + TB6;

#pragma unroll
        for (int ks = 0; ks < 2; ks++) {
            uint32_t a[4][4];
#pragma unroll
            for (int fm = 0; fm < 4; fm++) {
                int row = wm * 64 + fm * 16 + (lane & 15);
                int u = ks * 2 + (lane >> 4);
                uint32_t off = row * 64 + ((u ^ ((row >> 1) & 3)) << 4);
                LDMATRIX_X4(a[fm][0], a[fm][1], a[fm][2], a[fm][3], aB + off);
            }
            uint32_t b[2][4];
#pragma unroll
            for (int fp = 0; fp < 2; fp++) {
                int n = wn * 32 + fp * 16 + (lane & 7) + ((lane >> 4) << 3);
                int u = ks * 2 + ((lane >> 3) & 1);
                uint32_t off = n * 64 + ((u ^ ((n >> 1) & 3)) << 4);
                LDMATRIX_X4(b[fp][0], b[fp][1], b[fp][2], b[fp][3], wB + off);
            }
#pragma unroll
            for (int fm = 0; fm < 4; fm++)
#pragma unroll
                for (int fp = 0; fp < 2; fp++) {
                    MMA_F16(acc[fm][fp * 2 + 0], a[fm], b[fp][0], b[fp][1]);
                    MMA_F16(acc[fm][fp * 2 + 1], a[fm], b[fp][2], b[fp][3]);
                }
        }
    }

    const int cr = lane >> 2;
    const int cc = 2 * (lane & 3);
    // Q gets 1/sqrt(64) * log2(e) folded in (softmax runs in exp2 domain)
    const float sc = (SPLITOUT && blockIdx.z == 0) ? (0.125f * LOG2E) : 1.f;
#pragma unroll
    for (int fm = 0; fm < 4; fm++) {
        int r = m0 + wm * 64 + fm * 16 + cr;
#pragma unroll
        for (int fn = 0; fn < 4; fn++) {
            int col = n0 + wn * 32 + fn * 8 + cc;
            if (SPLITOUT) {
                int bb = r >> 11, t = r & (T_ - 1);
                int hh = col >> 6, hs = col & 63;
                size_t base = (((size_t)z * (B_ * NH_) + bb * NH_ + hh) * T_ + t) * HS_ + hs;
                *(__half2*)(outq + base) =
                    __floats2half2_rn(acc[fm][fn][0] * sc, acc[fm][fn][1] * sc);
                *(__half2*)(outq + base + 8 * HS_) =
                    __floats2half2_rn(acc[fm][fn][2] * sc, acc[fm][fn][3] * sc);
            } else {
                *(float2*)(outf + (size_t)r * D_ + col) =
                    make_float2(acc[fm][fn][0], acc[fm][fn][1]);
                *(float2*)(outf + (size_t)(r + 8) * D_ + col) =
                    make_float2(acc[fm][fn][2], acc[fm][fn][3]);
            }
        }
    }
}

// ================== fp16 flash attention (exp2 domain) =====================
// S = q16 k16; O += p16 v16. Bias: warp-uniform constant for saturated
// bucket zones (|dk| >= 128), table gather only near the diagonal.
#define QT 128
#define KT 64
#define ASM_Q 0u
#define ASM_KV 16384u
#define KVST 16384u
#define ATTN_SMEM (16384 + 3 * 16384)   // 64KB
#define NKT (T_ / KT)                   // 32

__global__ __launch_bounds__(256, 2)
void attn_hmma(const __half* __restrict__ QKV, const float* __restrict__ btab,
               __half* __restrict__ out1) {
    extern __shared__ char sm[];
    const uint32_t sb = smem_u32(sm);

    const int tid  = threadIdx.x;
    const int w    = tid >> 5;
    const int lane = tid & 31;
    const int bh = blockIdx.y;
    const int h  = bh & (NH_ - 1);
    const int b  = bh >> 4;
    const int q0 = blockIdx.x * QT;

    const __half* Qq = QKV + (size_t)bh * T_ * HS_;
    const __half* Kq = QKV + TQ1 + (size_t)bh * T_ * HS_;
    const __half* Vq = QKV + 2 * TQ1 + (size_t)bh * T_ * HS_;
    const float* bias_h = btab + h * NBIAS + (T_ - 1);
    const float bias_lo = btab[h * NBIAS];              // bucket 15 (dk <= -128)
    const float bias_hi = btab[h * NBIAS + NBIAS - 1];  // bucket 31 (dk >= +128)
    const int wr0 = q0 + w * 16;                        // warp's first q row

    // ---- Q preload ----
#pragma unroll
    for (int j = 0; j < 4; j++) {
        int idx = tid * 4 + j;
        int row = idx >> 3, u = idx & 7;
        uint32_t dst = sb + ASM_Q + row * 128 + ((u ^ (row & 7)) << 4);
        CP_ASYNC16(dst, (const void*)(Qq + (size_t)(q0 + row) * HS_ + u * 8));
    }
    CP_COMMIT();

    auto load_kv = [&](int t) {
        const uint32_t st = sb + ASM_KV + (uint32_t)(t % 3) * KVST;
        const int k0 = t * KT;
#pragma unroll
        for (int j = 0; j < 2; j++) {
            int idx = tid * 2 + j;
            int row = idx >> 3, u = idx & 7;
            uint32_t off = row * 128 + ((u ^ (row & 7)) << 4);
            const size_t goff = (size_t)(k0 + row) * HS_ + u * 8;
            CP_ASYNC16(st + off,        (const void*)(Kq + goff));
            CP_ASYNC16(st + 8192 + off, (const void*)(Vq + goff));
        }
        CP_COMMIT();
    };

    load_kv(0);
    load_kv(1);
    load_kv(2);

    float ofr[8][4];
    float mrow[2] = {-1e30f, -1e30f};
    float lrow[2] = {0.f, 0.f};
#pragma unroll
    for (int j = 0; j < 8; j++)
#pragma unroll
        for (int q = 0; q < 4; q++) ofr[j][q] = 0.f;

    for (int t = 0; t < NKT; t++) {
        CP_WAIT2();
        __syncthreads();

        const uint32_t kB = sb + ASM_KV + (uint32_t)(t % 3) * KVST;
        const uint32_t vB = kB + 8192;
        const int k0 = t * KT;

        // ---- S = q k^T ----
        float sf[8][4];
#pragma unroll
        for (int j = 0; j < 8; j++)
#pragma unroll
            for (int q = 0; q < 4; q++) sf[j][q] = 0.f;

#pragma unroll
        for (int u = 0; u < 4; u++) {
            uint32_t a[4];
            {
                int row = w * 16 + (lane & 15);
                int un = 2 * u + (lane >> 4);
                uint32_t ad = sb + ASM_Q + row * 128 + ((un ^ (row & 7)) << 4);
                LDMATRIX_X4(a[0], a[1], a[2], a[3], ad);
            }
#pragma unroll
            for (int fp = 0; fp < 4; fp++) {
                int n = fp * 16 + (lane & 7) + ((lane >> 4) << 3);
                int un = 2 * u + ((lane >> 3) & 1);
                uint32_t b0, b1, b2, b3;
                uint32_t bd = kB + n * 128 + ((un ^ (n & 7)) << 4);
                LDMATRIX_X4(b0, b1, b2, b3, bd);
                MMA_F16(sf[2 * fp + 0], a, b0, b1);
                MMA_F16(sf[2 * fp + 1], a, b2, b3);
            }
        }

        // ---- + bias (constant in saturated zones, gather near diagonal) ----
        // warp dk range: [k0 - wr0 - 15, k0 + KT-1 - wr0]
        if (k0 + KT - 1 - wr0 <= -128) {
#pragma unroll
            for (int j = 0; j < 8; j++) {
                sf[j][0] += bias_lo; sf[j][1] += bias_lo;
                sf[j][2] += bias_lo; sf[j][3] += bias_lo;
            }
        } else if (k0 - wr0 - 15 >= 128) {
#pragma unroll
            for (int j = 0; j < 8; j++) {
                sf[j][0] += bias_hi; sf[j][1] += bias_hi;
                sf[j][2] += bias_hi; sf[j][3] += bias_hi;
            }
        } else {
            const int r0g = q0 + w * 16 + (lane >> 2);
#pragma unroll
            for (int j = 0; j < 8; j++) {
                int dk = k0 + 8 * j + 2 * (lane & 3) - r0g;
                sf[j][0] += bias_h[dk];
                sf[j][1] += bias_h[dk + 1];
                sf[j][2] += bias_h[dk - 8];
                sf[j][3] += bias_h[dk - 7];
            }
        }

        // ---- online softmax (exp2 domain) ----
        float mt0 = -1e30f, mt1 = -1e30f;
#pragma unroll
        for (int j = 0; j < 8; j++) {
            mt0 = fmaxf(mt0, fmaxf(sf[j][0], sf[j][1]));
            mt1 = fmaxf(mt1, fmaxf(sf[j][2], sf[j][3]));
        }
        mt0 = fmaxf(mt0, __shfl_xor_sync(0xffffffffu, mt0, 1));
        mt0 = fmaxf(mt0, __shfl_xor_sync(0xffffffffu, mt0, 2));
        mt1 = fmaxf(mt1, __shfl_xor_sync(0xffffffffu, mt1, 1));
        mt1 = fmaxf(mt1, __shfl_xor_sync(0xffffffffu, mt1, 2));

        float mn0 = fmaxf(mrow[0], mt0), mn1 = fmaxf(mrow[1], mt1);
        float alpha0 = ex2a(mrow[0] - mn0), alpha1 = ex2a(mrow[1] - mn1);
        mrow[0] = mn0; mrow[1] = mn1;

        float ls0 = 0.f, ls1 = 0.f;
#pragma unroll
        for (int j = 0; j < 8; j++) {
            sf[j][0] = ex2a(sf[j][0] - mn0);
            sf[j][1] = ex2a(sf[j][1] - mn0);
            sf[j][2] = ex2a(sf[j][2] - mn1);
            sf[j][3] = ex2a(sf[j][3] - mn1);
            ls0 += sf[j][0] + sf[j][1];
            ls1 += sf[j][2] + sf[j][3];
        }
        ls0 += __shfl_xor_sync(0xffffffffu, ls0, 1);
        ls0 += __shfl_xor_sync(0xffffffffu, ls0, 2);
        ls1 += __shfl_xor_sync(0xffffffffu, ls1, 1);
        ls1 += __shfl_xor_sync(0xffffffffu, ls1, 2);
        lrow[0] = lrow[0] * alpha0 + ls0;
        lrow[1] = lrow[1] * alpha1 + ls1;
#pragma unroll
        for (int j = 0; j < 8; j++) {
            ofr[j][0] *= alpha0; ofr[j][1] *= alpha0;
            ofr[j][2] *= alpha1; ofr[j][3] *= alpha1;
        }

        // ---- O += p16 * v16 ----
#pragma unroll
        for (int kk = 0; kk < 4; kk++) {
            uint32_t ph[4];
            ph[0] = packh(sf[2 * kk][0],     sf[2 * kk][1]);
            ph[1] = packh(sf[2 * kk][2],     sf[2 * kk][3]);
            ph[2] = packh(sf[2 * kk + 1][0], sf[2 * kk + 1][1]);
            ph[3] = packh(sf[2 * kk + 1][2], sf[2 * kk + 1][3]);
            const int g = lane >> 3;
            const int rowv = kk * 16 + ((g & 1) << 3) + (lane & 7);
#pragma unroll
            for (int fb = 0; fb < 4; fb++) {
                int unit = fb * 2 + (g >> 1);
                uint32_t v0, v1, v2, v3;
                uint32_t av = vB + rowv * 128 + ((unit ^ (rowv & 7)) << 4);
                LDMATRIX_X4_T(v0, v1, v2, v3, av);
                MMA_F16(ofr[2 * fb + 0], ph, v0, v1);
                MMA_F16(ofr[2 * fb + 1], ph, v2, v3);
            }
        }

        __syncthreads();
        if (t + 3 < NKT) load_kv(t + 3);
        else CP_COMMIT();
    }

    // ---- epilogue: fp16 AO ----
    const float inv0 = 1.f / lrow[0], inv1 = 1.f / lrow[1];
    const int r0 = q0 + w * 16 + (lane >> 2), r1 = r0 + 8;
    __half* row0 = out1 + (size_t)(b * T_ + r0) * D_;
    __half* row1 = out1 + (size_t)(b * T_ + r1) * D_;
#pragma unroll
    for (int j = 0; j < 8; j++) {
        int col = h * HS_ + 8 * j + 2 * (lane & 3);
        *(uint32_t*)(row0 + col) = packh(ofr[j][0] * inv0, ofr[j][1] * inv0);
        *(uint32_t*)(row1 + col) = packh(ofr[j][2] * inv1, ofr[j][3] * inv1);
    }
}

// ================== launch ==================================================
extern "C" void kernel_launch(void* const* d_in, const int* in_sizes, int n_in,
                              void* d_out, int out_size) {
    const float* queries = (const float*)d_in[0];
    const float* Wq      = (const float*)d_in[1];
    const float* Wk      = (const float*)d_in[2];
    const float* Wv      = (const float*)d_in[3];
    const float* Wo      = (const float*)d_in[4];
    const float* rel_emb = (const float*)d_in[5];
    float* out = (float*)d_out;

    __half *gA1h, *gAO1h, *gW1, *gQKV1;
    float *gB;
    cudaGetSymbolAddress((void**)&gA1h,  g_A1h);
    cudaGetSymbolAddress((void**)&gAO1h, g_AO1h);
    cudaGetSymbolAddress((void**)&gW1,   g_W1);
    cudaGetSymbolAddress((void**)&gQKV1, g_QKV1);
    cudaGetSymbolAddress((void**)&gB,    g_bias);

    cudaFuncSetAttribute(attn_hmma, cudaFuncAttributeMaxDynamicSharedMemorySize, ATTN_SMEM);
    cudaFuncSetAttribute(gemm_hmma6<0>, cudaFuncAttributeMaxDynamicSharedMemorySize, GEMM6_SMEM);
    cudaFuncSetAttribute(gemm_hmma6<1>, cudaFuncAttributeMaxDynamicSharedMemorySize, GEMM6_SMEM);

    // 1) fused prep: fp16 converts + log2-domain bias table
    prep_fused<<<(NPREP + 255) / 256, 256>>>(queries, Wq, Wk, Wv, Wo, rel_emb,
                                             gA1h, gW1, gB);

    // 2) fused Q/K/V projections -> fp16 [z][bh][t][hs] (Q scaled by log2e/8)
    dim3 gGrid(D_ / 128, M_ / 128, 3);
    gemm_hmma6<1><<<gGrid, 256, GEMM6_SMEM>>>(gA1h, gW1, nullptr, gQKV1);

    // 3) fp16 attention -> fp16 AO
    dim3 aGrid(T_ / QT, B_ * NH_);
    attn_hmma<<<aGrid, 256, ATTN_SMEM>>>(gQKV1, gB, gAO1h);

    // 4) output projection (fp32 out)
    dim3 oGrid(D_ / 128, M_ / 128, 1);
    gemm_hmma6<0><<<oGrid, 256, GEMM6_SMEM>>>(gAO1h, gW1 + 3 * WOFF1, out, nullptr);
}

// round 14
// speedup vs baseline: 2.3225x; 1.0053x over previous
#include <cuda_runtime.h>
#include <cuda_bf16.h>
#include <cuda_fp16.h>
#include <math.h>
#include <stdint.h>

#define B_  4
#define T_  2048
#define D_  1024
#define NH_ 16
#define HS_ 64
#define NBIAS (2*T_ - 1)   // 4095
#define M_  (B_*T_)        // 8192
#define LOG2E 1.4426950408889634f

// ---------------- scratch (device globals: no allocation allowed) ----------
__device__ __half g_A1h [M_*(size_t)D_];     // queries fp16
__device__ __half g_AO1h[M_*(size_t)D_];     // attn-out fp16
__device__ __half g_W1  [4*(size_t)D_*D_];   // weights fp16
__device__ __half g_QKV1[3*(size_t)NH_*B_*T_*HS_]; // fp16 [z][bh][t][hs]
__device__ float g_bias[NH_*NBIAS];          // bias table, pre-scaled by log2(e)

#define TQ1 ((size_t)NH_*B_*T_*HS_)
#define WOFF1 ((size_t)D_*D_)

// ============================ PTX helpers ==================================
__device__ __forceinline__ uint32_t smem_u32(const void* p) {
    uint32_t a;
    asm("{ .reg .u64 t; cvta.to.shared.u64 t, %1; cvt.u32.u64 %0, t; }" : "=r"(a) : "l"(p));
    return a;
}
#define CP_ASYNC16(dst, src) \
    asm volatile("cp.async.cg.shared.global [%0], [%1], 16;" :: "r"(dst), "l"(src) : "memory")
#define CP_COMMIT() asm volatile("cp.async.commit_group;" ::: "memory")
#define CP_WAIT1()  asm volatile("cp.async.wait_group 1;" ::: "memory")
#define CP_WAIT3()  asm volatile("cp.async.wait_group 3;" ::: "memory")

#define LDMATRIX_X4(r0, r1, r2, r3, addr) \
    asm volatile("ldmatrix.sync.aligned.m8n8.x4.shared.b16 {%0,%1,%2,%3}, [%4];" \
                 : "=r"(r0), "=r"(r1), "=r"(r2), "=r"(r3) : "r"(addr))
#define LDMATRIX_X4_T(r0, r1, r2, r3, addr) \
    asm volatile("ldmatrix.sync.aligned.m8n8.x4.trans.shared.b16 {%0,%1,%2,%3}, [%4];" \
                 : "=r"(r0), "=r"(r1), "=r"(r2), "=r"(r3) : "r"(addr))

#define MMA_F16(c, a, b0, b1) \
    asm volatile("mma.sync.aligned.m16n8k16.row.col.f32.f16.f16.f32 " \
                 "{%0,%1,%2,%3}, {%4,%5,%6,%7}, {%8,%9}, {%0,%1,%2,%3};" \
                 : "+f"((c)[0]), "+f"((c)[1]), "+f"((c)[2]), "+f"((c)[3]) \
                 : "r"((a)[0]), "r"((a)[1]), "r"((a)[2]), "r"((a)[3]), "r"(b0), "r"(b1))

__device__ __forceinline__ uint32_t packh(float a, float b) {
    __half2 v = __floats2half2_rn(a, b);
    return *(uint32_t*)&v;
}
__device__ __forceinline__ float ex2a(float x) {
    float y;
    asm("ex2.approx.f32 %0, %1;" : "=f"(y) : "f"(x));
    return y;
}

// ================== bias bucketing =========================================
__device__ __forceinline__ int bucket_of(int rp) {
    int b = (rp > 0) ? 16 : 0;
    int a = rp < 0 ? -rp : rp;
    if (a < 8) return b + a;
    double v = 7.0 + (log((double)a / 7.0) / log(128.0 / 7.0)) * 8.0;
    int large = (int)v;
    if (large > 15) large = 15;
    return b + large;
}

// ========= fused prep: fp16 converts (queries + 4 weights) + bias table ====
#define NQ4 (M_ * (D_ / 4))
#define NW4 (D_ * (D_ / 4))
#define NCONV (NQ4 + 4 * NW4)
#define NB1 (NH_ * NBIAS)
#define NPREP (NCONV + NB1)

__global__ void prep_fused(const float* __restrict__ q,
                           const float* __restrict__ w0, const float* __restrict__ w1,
                           const float* __restrict__ w2, const float* __restrict__ w3,
                           const float* __restrict__ rel_emb,
                           __half* __restrict__ outA, __half* __restrict__ outW,
                           float* __restrict__ btab) {
    int i = blockIdx.x * blockDim.x + threadIdx.x;
    if (i >= NPREP) return;
    if (i >= NCONV) {               // bias-table element (log2-domain)
        int idx = i - NCONV;
        int h = idx / NBIAS, x = idx % NBIAS;
        btab[idx] = rel_emb[bucket_of(x - (T_ - 1)) * NH_ + h] * LOG2E;
        return;
    }
    const float* src;
    __half* dst;
    if (i < NQ4) { src = q + (size_t)i * 4; dst = outA + (size_t)i * 4; }
    else {
        int j = i - NQ4;
        int wsel = j / NW4, off = j % NW4;
        const float* ws = (wsel == 0) ? w0 : (wsel == 1) ? w1 : (wsel == 2) ? w2 : w3;
        src = ws + (size_t)off * 4;
        dst = outW + (size_t)wsel * WOFF1 + (size_t)off * 4;
    }
    float4 v = *(const float4*)src;
    __half2* o = (__half2*)dst;
    o[0] = __floats2half2_rn(v.x, v.y);
    o[1] = __floats2half2_rn(v.z, v.w);
}

// ================== fp16 GEMM (single-term) ================================
#define GS6 3
#define TB6 8192
#define GIT6 32
#define GEMM6_SMEM (GS6 * 2 * TB6)   // 48KB

template <int SPLITOUT>
__global__ __launch_bounds__(256, 2)
void gemm_hmma6(const __half* __restrict__ A, const __half* __restrict__ W0,
                float* __restrict__ outf, __half* __restrict__ outq) {
    extern __shared__ char sm6[];
    const uint32_t sb = smem_u32(sm6);

    const int tid  = threadIdx.x;
    const int w    = tid >> 5;
    const int lane = tid & 31;
    const int wm   = w & 1;
    const int wn   = w >> 1;
    const int m0   = blockIdx.y * 128;
    const int n0   = blockIdx.x * 128;
    const int z    = blockIdx.z;
    const __half* W = W0 + (size_t)z * WOFF1;

    float acc[4][4][4];
#pragma unroll
    for (int i = 0; i < 4; i++)
#pragma unroll
        for (int j = 0; j < 4; j++)
#pragma unroll
            for (int q = 0; q < 4; q++) acc[i][j][q] = 0.f;

    auto load_stage = [&](int it) {
        const uint32_t st = sb + (uint32_t)(it % GS6) * (2 * TB6);
        const int kb = it * 32;
#pragma unroll
        for (int j = 0; j < 2; j++) {
            int idx = tid * 2 + j;
            int row = idx >> 2, u = idx & 3;
            uint32_t off = row * 64 + ((u ^ ((row >> 1) & 3)) << 4);
            CP_ASYNC16(st + off,       (const void*)(A + (size_t)(m0 + row) * D_ + kb + u * 8));
            CP_ASYNC16(st + TB6 + off, (const void*)(W + (size_t)(n0 + row) * D_ + kb + u * 8));
        }
        CP_COMMIT();
    };

    load_stage(0);
    load_stage(1);

    for (int it = 0; it < GIT6; it++) {
        CP_WAIT1();
        __syncthreads();
        if (it + 2 < GIT6) load_stage(it + 2);
        else CP_COMMIT();

        const uint32_t aB = sb + (uint32_t)(it % GS6) * (2 * TB6);
        const uint32_t wB = aB + TB6;

#pragma unroll
        for (int ks = 0; ks < 2; ks++) {
            uint32_t a[4][4];
#pragma unroll
            for (int fm = 0; fm < 4; fm++) {
                int row = wm * 64 + fm * 16 + (lane & 15);
                int u = ks * 2 + (lane >> 4);
                uint32_t off = row * 64 + ((u ^ ((row >> 1) & 3)) << 4);
                LDMATRIX_X4(a[fm][0], a[fm][1], a[fm][2], a[fm][3], aB + off);
            }
            uint32_t b[2][4];
#pragma unroll
            for (int fp = 0; fp < 2; fp++) {
                int n = wn * 32 + fp * 16 + (lane & 7) + ((lane >> 4) << 3);
                int u = ks * 2 + ((lane >> 3) & 1);
                uint32_t off = n * 64 + ((u ^ ((n >> 1) & 3)) << 4);
                LDMATRIX_X4(b[fp][0], b[fp][1], b[fp][2], b[fp][3], wB + off);
            }
#pragma unroll
            for (int fm = 0; fm < 4; fm++)
#pragma unroll
                for (int fp = 0; fp < 2; fp++) {
                    MMA_F16(acc[fm][fp * 2 + 0], a[fm], b[fp][0], b[fp][1]);
                    MMA_F16(acc[fm][fp * 2 + 1], a[fm], b[fp][2], b[fp][3]);
                }
        }
    }

    const int cr = lane >> 2;
    const int cc = 2 * (lane & 3);
    const float sc = (SPLITOUT && blockIdx.z == 0) ? (0.125f * LOG2E) : 1.f;
#pragma unroll
    for (int fm = 0; fm < 4; fm++) {
        int r = m0 + wm * 64 + fm * 16 + cr;
#pragma unroll
        for (int fn = 0; fn < 4; fn++) {
            int col = n0 + wn * 32 + fn * 8 + cc;
            if (SPLITOUT) {
                int bb = r >> 11, t = r & (T_ - 1);
                int hh = col >> 6, hs = col & 63;
                size_t base = (((size_t)z * (B_ * NH_) + bb * NH_ + hh) * T_ + t) * HS_ + hs;
                *(__half2*)(outq + base) =
                    __floats2half2_rn(acc[fm][fn][0] * sc, acc[fm][fn][1] * sc);
                *(__half2*)(outq + base + 8 * HS_) =
                    __floats2half2_rn(acc[fm][fn][2] * sc, acc[fm][fn][3] * sc);
            } else {
                *(float2*)(outf + (size_t)r * D_ + col) =
                    make_float2(acc[fm][fn][0], acc[fm][fn][1]);
                *(float2*)(outf + (size_t)(r + 8) * D_ + col) =
                    make_float2(acc[fm][fn][2], acc[fm][fn][3]);
            }
        }
    }
}

// ================== fp16 flash attention (exp2, 5-stage, 1 sync/tile) ======
#define QT 128
#define KT 64
#define KVS 5                              // KV ring stages
#define ASM_Q 0u
#define ASM_KV 16384u
#define KVST 16384u
#define ATTN_SMEM (16384 + KVS * 16384)    // 96KB
#define NKT (T_ / KT)                      // 32

__global__ __launch_bounds__(256, 2)
void attn_hmma(const __half* __restrict__ QKV, const float* __restrict__ btab,
               __half* __restrict__ out1) {
    extern __shared__ char sm[];
    const uint32_t sb = smem_u32(sm);

    const int tid  = threadIdx.x;
    const int w    = tid >> 5;
    const int lane = tid & 31;
    const int bh = blockIdx.y;
    const int h  = bh & (NH_ - 1);
    const int b  = bh >> 4;
    const int q0 = blockIdx.x * QT;

    const __half* Qq = QKV + (size_t)bh * T_ * HS_;
    const __half* Kq = QKV + TQ1 + (size_t)bh * T_ * HS_;
    const __half* Vq = QKV + 2 * TQ1 + (size_t)bh * T_ * HS_;
    const float* bias_h = btab + h * NBIAS + (T_ - 1);
    const float bias_lo = btab[h * NBIAS];
    const float bias_hi = btab[h * NBIAS + NBIAS - 1];
    const int wr0 = q0 + w * 16;

    // ---- Q preload (group 1) ----
#pragma unroll
    for (int j = 0; j < 4; j++) {
        int idx = tid * 4 + j;
        int row = idx >> 3, u = idx & 7;
        uint32_t dst = sb + ASM_Q + row * 128 + ((u ^ (row & 7)) << 4);
        CP_ASYNC16(dst, (const void*)(Qq + (size_t)(q0 + row) * HS_ + u * 8));
    }
    CP_COMMIT();

    auto load_kv = [&](int t) {
        const uint32_t st = sb + ASM_KV + (uint32_t)(t % KVS) * KVST;
        const int k0 = t * KT;
#pragma unroll
        for (int j = 0; j < 2; j++) {
            int idx = tid * 2 + j;
            int row = idx >> 3, u = idx & 7;
            uint32_t off = row * 128 + ((u ^ (row & 7)) << 4);
            const size_t goff = (size_t)(k0 + row) * HS_ + u * 8;
            CP_ASYNC16(st + off,        (const void*)(Kq + goff));
            CP_ASYNC16(st + 8192 + off, (const void*)(Vq + goff));
        }
        CP_COMMIT();
    };

    load_kv(0);
    load_kv(1);
    load_kv(2);
    load_kv(3);

    float ofr[8][4];
    float mrow[2] = {-1e30f, -1e30f};
    float lrow[2] = {0.f, 0.f};
#pragma unroll
    for (int j = 0; j < 8; j++)
#pragma unroll
        for (int q = 0; q < 4; q++) ofr[j][q] = 0.f;

    for (int t = 0; t < NKT; t++) {
        CP_WAIT3();                // newest 3 groups may pend -> Q + stage t done
        __syncthreads();           // cross-thread visibility of stage t
        // refill slot (t+4)%5 — disjoint from slots t..t+3 readable this round
        if (t + 4 < NKT) load_kv(t + 4);
        else CP_COMMIT();

        const uint32_t kB = sb + ASM_KV + (uint32_t)(t % KVS) * KVST;
        const uint32_t vB = kB + 8192;
        const int k0 = t * KT;

        // ---- S = q k^T ----
        float sf[8][4];
#pragma unroll
        for (int j = 0; j < 8; j++)
#pragma unroll
            for (int q = 0; q < 4; q++) sf[j][q] = 0.f;

#pragma unroll
        for (int u = 0; u < 4; u++) {
            uint32_t a[4];
            {
                int row = w * 16 + (lane & 15);
                int un = 2 * u + (lane >> 4);
                uint32_t ad = sb + ASM_Q + row * 128 + ((un ^ (row & 7)) << 4);
                LDMATRIX_X4(a[0], a[1], a[2], a[3], ad);
            }
#pragma unroll
            for (int fp = 0; fp < 4; fp++) {
                int n = fp * 16 + (lane & 7) + ((lane >> 4) << 3);
                int un = 2 * u + ((lane >> 3) & 1);
                uint32_t b0, b1, b2, b3;
                uint32_t bd = kB + n * 128 + ((un ^ (n & 7)) << 4);
                LDMATRIX_X4(b0, b1, b2, b3, bd);
                MMA_F16(sf[2 * fp + 0], a, b0, b1);
                MMA_F16(sf[2 * fp + 1], a, b2, b3);
            }
        }

        // ---- + bias (saturated-zone constant / diagonal gather) ----
        if (k0 + KT - 1 - wr0 <= -128) {
#pragma unroll
            for (int j = 0; j < 8; j++) {
                sf[j][0] += bias_lo; sf[j][1] += bias_lo;
                sf[j][2] += bias_lo; sf[j][3] += bias_lo;
            }
        } else if (k0 - wr0 - 15 >= 128) {
#pragma unroll
            for (int j = 0; j < 8; j++) {
                sf[j][0] += bias_hi; sf[j][1] += bias_hi;
                sf[j][2] += bias_hi; sf[j][3] += bias_hi;
            }
        } else {
            const int r0g = q0 + w * 16 + (lane >> 2);
#pragma unroll
            for (int j = 0; j < 8; j++) {
                int dk = k0 + 8 * j + 2 * (lane & 3) - r0g;
                sf[j][0] += bias_h[dk];
                sf[j][1] += bias_h[dk + 1];
                sf[j][2] += bias_h[dk - 8];
                sf[j][3] += bias_h[dk - 7];
            }
        }

        // ---- online softmax (exp2 domain, rescale skipped when max holds) --
        float mt0 = -1e30f, mt1 = -1e30f;
#pragma unroll
        for (int j = 0; j < 8; j++) {
            mt0 = fmaxf(mt0, fmaxf(sf[j][0], sf[j][1]));
            mt1 = fmaxf(mt1, fmaxf(sf[j][2], sf[j][3]));
        }
        mt0 = fmaxf(mt0, __shfl_xor_sync(0xffffffffu, mt0, 1));
        mt0 = fmaxf(mt0, __shfl_xor_sync(0xffffffffu, mt0, 2));
        mt1 = fmaxf(mt1, __shfl_xor_sync(0xffffffffu, mt1, 1));
        mt1 = fmaxf(mt1, __shfl_xor_sync(0xffffffffu, mt1, 2));

        bool keep = __all_sync(0xffffffffu, (mt0 <= mrow[0]) & (mt1 <= mrow[1]));
        if (!keep) {
            float mn0 = fmaxf(mrow[0], mt0), mn1 = fmaxf(mrow[1], mt1);
            float alpha0 = ex2a(mrow[0] - mn0), alpha1 = ex2a(mrow[1] - mn1);
            mrow[0] = mn0; mrow[1] = mn1;
            lrow[0] *= alpha0; lrow[1] *= alpha1;
#pragma unroll
            for (int j = 0; j < 8; j++) {
                ofr[j][0] *= alpha0; ofr[j][1] *= alpha0;
                ofr[j][2] *= alpha1; ofr[j][3] *= alpha1;
            }
        }

        float ls0 = 0.f, ls1 = 0.f;
#pragma unroll
        for (int j = 0; j < 8; j++) {
            sf[j][0] = ex2a(sf[j][0] - mrow[0]);
            sf[j][1] = ex2a(sf[j][1] - mrow[0]);
            sf[j][2] = ex2a(sf[j][2] - mrow[1]);
            sf[j][3] = ex2a(sf[j][3] - mrow[1]);
            ls0 += sf[j][0] + sf[j][1];
            ls1 += sf[j][2] + sf[j][3];
        }
        ls0 += __shfl_xor_sync(0xffffffffu, ls0, 1);
        ls0 += __shfl_xor_sync(0xffffffffu, ls0, 2);
        ls1 += __shfl_xor_sync(0xffffffffu, ls1, 1);
        ls1 += __shfl_xor_sync(0xffffffffu, ls1, 2);
        lrow[0] += ls0;
        lrow[1] += ls1;

        // ---- O += p16 * v16 ----
#pragma unroll
        for (int kk = 0; kk < 4; kk++) {
            uint32_t ph[4];
            ph[0] = packh(sf[2 * kk][0],     sf[2 * kk][1]);
            ph[1] = packh(sf[2 * kk][2],     sf[2 * kk][3]);
            ph[2] = packh(sf[2 * kk + 1][0], sf[2 * kk + 1][1]);
            ph[3] = packh(sf[2 * kk + 1][2], sf[2 * kk + 1][3]);
            const int g = lane >> 3;
            const int rowv = kk * 16 + ((g & 1) << 3) + (lane & 7);
#pragma unroll
            for (int fb = 0; fb < 4; fb++) {
                int unit = fb * 2 + (g >> 1);
                uint32_t v0, v1, v2, v3;
                uint32_t av = vB + rowv * 128 + ((unit ^ (rowv & 7)) << 4);
                LDMATRIX_X4_T(v0, v1, v2, v3, av);
                MMA_F16(ofr[2 * fb + 0], ph, v0, v1);
                MMA_F16(ofr[2 * fb + 1], ph, v2, v3);
            }
        }
        // no trailing barrier: 5-stage ring keeps writer/reader slots disjoint
    }

    // ---- epilogue: fp16 AO ----
    const float inv0 = 1.f / lrow[0], inv1 = 1.f / lrow[1];
    const int r0 = q0 + w * 16 + (lane >> 2), r1 = r0 + 8;
    __half* row0 = out1 + (size_t)(b * T_ + r0) * D_;
    __half* row1 = out1 + (size_t)(b * T_ + r1) * D_;
#pragma unroll
    for (int j = 0; j < 8; j++) {
        int col = h * HS_ + 8 * j + 2 * (lane & 3);
        *(uint32_t*)(row0 + col) = packh(ofr[j][0] * inv0, ofr[j][1] * inv0);
        *(uint32_t*)(row1 + col) = packh(ofr[j][2] * inv1, ofr[j][3] * inv1);
    }
}

// ================== launch ==================================================
extern "C" void kernel_launch(void* const* d_in, const int* in_sizes, int n_in,
                              void* d_out, int out_size) {
    const float* queries = (const float*)d_in[0];
    const float* Wq      = (const float*)d_in[1];
    const float* Wk      = (const float*)d_in[2];
    const float* Wv      = (const float*)d_in[3];
    const float* Wo      = (const float*)d_in[4];
    const float* rel_emb = (const float*)d_in[5];
    float* out = (float*)d_out;

    __half *gA1h, *gAO1h, *gW1, *gQKV1;
    float *gB;
    cudaGetSymbolAddress((void**)&gA1h,  g_A1h);
    cudaGetSymbolAddress((void**)&gAO1h, g_AO1h);
    cudaGetSymbolAddress((void**)&gW1,   g_W1);
    cudaGetSymbolAddress((void**)&gQKV1, g_QKV1);
    cudaGetSymbolAddress((void**)&gB,    g_bias);

    cudaFuncSetAttribute(attn_hmma, cudaFuncAttributeMaxDynamicSharedMemorySize, ATTN_SMEM);
    cudaFuncSetAttribute(gemm_hmma6<0>, cudaFuncAttributeMaxDynamicSharedMemorySize, GEMM6_SMEM);
    cudaFuncSetAttribute(gemm_hmma6<1>, cudaFuncAttributeMaxDynamicSharedMemorySize, GEMM6_SMEM);

    // 1) fused prep: fp16 converts + log2-domain bias table
    prep_fused<<<(NPREP + 255) / 256, 256>>>(queries, Wq, Wk, Wv, Wo, rel_emb,
                                             gA1h, gW1, gB);

    // 2) fused Q/K/V projections -> fp16 [z][bh][t][hs] (Q scaled by log2e/8)
    dim3 gGrid(D_ / 128, M_ / 128, 3);
    gemm_hmma6<1><<<gGrid, 256, GEMM6_SMEM>>>(gA1h, gW1, nullptr, gQKV1);

    // 3) fp16 attention -> fp16 AO
    dim3 aGrid(T_ / QT, B_ * NH_);
    attn_hmma<<<aGrid, 256, ATTN_SMEM>>>(gQKV1, gB, gAO1h);

    // 4) output projection (fp32 out)
    dim3 oGrid(D_ / 128, M_ / 128, 1);
    gemm_hmma6<0><<<oGrid, 256, GEMM6_SMEM>>>(gAO1h, gW1 + 3 * WOFF1, out, nullptr);
}

// round 15
// speedup vs baseline: 2.3381x; 1.0067x over previous
#include <cuda_runtime.h>
#include <cuda_bf16.h>
#include <cuda_fp16.h>
#include <math.h>
#include <stdint.h>

#define B_  4
#define T_  2048
#define D_  1024
#define NH_ 16
#define HS_ 64
#define NBIAS (2*T_ - 1)   // 4095
#define M_  (B_*T_)        // 8192
#define LOG2E 1.4426950408889634f

// ---------------- scratch (device globals: no allocation allowed) ----------
__device__ __half g_A1h [M_*(size_t)D_];     // queries fp16
__device__ __half g_AO1h[M_*(size_t)D_];     // attn-out fp16
__device__ __half g_W1  [4*(size_t)D_*D_];   // weights fp16
__device__ __half g_QKV1[3*(size_t)NH_*B_*T_*HS_]; // fp16 [z][bh][t][hs]
__device__ float g_bias[NH_*NBIAS];          // bias table, pre-scaled by log2(e)

#define TQ1 ((size_t)NH_*B_*T_*HS_)
#define WOFF1 ((size_t)D_*D_)

// ============================ PTX helpers ==================================
__device__ __forceinline__ uint32_t smem_u32(const void* p) {
    uint32_t a;
    asm("{ .reg .u64 t; cvta.to.shared.u64 t, %1; cvt.u32.u64 %0, t; }" : "=r"(a) : "l"(p));
    return a;
}
#define CP_ASYNC16(dst, src) \
    asm volatile("cp.async.cg.shared.global [%0], [%1], 16;" :: "r"(dst), "l"(src) : "memory")
#define CP_COMMIT() asm volatile("cp.async.commit_group;" ::: "memory")
#define CP_WAIT2()  asm volatile("cp.async.wait_group 2;" ::: "memory")
#define CP_WAIT3()  asm volatile("cp.async.wait_group 3;" ::: "memory")

#define LDMATRIX_X4(r0, r1, r2, r3, addr) \
    asm volatile("ldmatrix.sync.aligned.m8n8.x4.shared.b16 {%0,%1,%2,%3}, [%4];" \
                 : "=r"(r0), "=r"(r1), "=r"(r2), "=r"(r3) : "r"(addr))
#define LDMATRIX_X4_T(r0, r1, r2, r3, addr) \
    asm volatile("ldmatrix.sync.aligned.m8n8.x4.trans.shared.b16 {%0,%1,%2,%3}, [%4];" \
                 : "=r"(r0), "=r"(r1), "=r"(r2), "=r"(r3) : "r"(addr))

#define MMA_F16(c, a, b0, b1) \
    asm volatile("mma.sync.aligned.m16n8k16.row.col.f32.f16.f16.f32 " \
                 "{%0,%1,%2,%3}, {%4,%5,%6,%7}, {%8,%9}, {%0,%1,%2,%3};" \
                 : "+f"((c)[0]), "+f"((c)[1]), "+f"((c)[2]), "+f"((c)[3]) \
                 : "r"((a)[0]), "r"((a)[1]), "r"((a)[2]), "r"((a)[3]), "r"(b0), "r"(b1))

__device__ __forceinline__ uint32_t packh(float a, float b) {
    __half2 v = __floats2half2_rn(a, b);
    return *(uint32_t*)&v;
}
__device__ __forceinline__ float ex2a(float x) {
    float y;
    asm("ex2.approx.f32 %0, %1;" : "=f"(y) : "f"(x));
    return y;
}

// ================== bias bucketing =========================================
__device__ __forceinline__ int bucket_of(int rp) {
    int b = (rp > 0) ? 16 : 0;
    int a = rp < 0 ? -rp : rp;
    if (a < 8) return b + a;
    double v = 7.0 + (log((double)a / 7.0) / log(128.0 / 7.0)) * 8.0;
    int large = (int)v;
    if (large > 15) large = 15;
    return b + large;
}

// ========= fused prep: fp16 converts (queries + 4 weights) + bias table ====
#define NQ4 (M_ * (D_ / 4))
#define NW4 (D_ * (D_ / 4))
#define NCONV (NQ4 + 4 * NW4)
#define NB1 (NH_ * NBIAS)
#define NPREP (NCONV + NB1)

__global__ void prep_fused(const float* __restrict__ q,
                           const float* __restrict__ w0, const float* __restrict__ w1,
                           const float* __restrict__ w2, const float* __restrict__ w3,
                           const float* __restrict__ rel_emb,
                           __half* __restrict__ outA, __half* __restrict__ outW,
                           float* __restrict__ btab) {
    int i = blockIdx.x * blockDim.x + threadIdx.x;
    if (i >= NPREP) return;
    if (i >= NCONV) {
        int idx = i - NCONV;
        int h = idx / NBIAS, x = idx % NBIAS;
        btab[idx] = rel_emb[bucket_of(x - (T_ - 1)) * NH_ + h] * LOG2E;
        return;
    }
    const float* src;
    __half* dst;
    if (i < NQ4) { src = q + (size_t)i * 4; dst = outA + (size_t)i * 4; }
    else {
        int j = i - NQ4;
        int wsel = j / NW4, off = j % NW4;
        const float* ws = (wsel == 0) ? w0 : (wsel == 1) ? w1 : (wsel == 2) ? w2 : w3;
        src = ws + (size_t)off * 4;
        dst = outW + (size_t)wsel * WOFF1 + (size_t)off * 4;
    }
    float4 v = *(const float4*)src;
    __half2* o = (__half2*)dst;
    o[0] = __floats2half2_rn(v.x, v.y);
    o[1] = __floats2half2_rn(v.z, v.w);
}

// ================== fp16 GEMM (single-term, 4-stage pipeline) ==============
#define GS6 4
#define TB6 8192
#define GIT6 32
#define GEMM6_SMEM (GS6 * 2 * TB6)   // 64KB

template <int SPLITOUT>
__global__ __launch_bounds__(256, 2)
void gemm_hmma6(const __half* __restrict__ A, const __half* __restrict__ W0,
                float* __restrict__ outf, __half* __restrict__ outq) {
    extern __shared__ char sm6[];
    const uint32_t sb = smem_u32(sm6);

    const int tid  = threadIdx.x;
    const int w    = tid >> 5;
    const int lane = tid & 31;
    const int wm   = w & 1;
    const int wn   = w >> 1;
    const int m0   = blockIdx.y * 128;
    const int n0   = blockIdx.x * 128;
    const int z    = blockIdx.z;
    const __half* W = W0 + (size_t)z * WOFF1;

    float acc[4][4][4];
#pragma unroll
    for (int i = 0; i < 4; i++)
#pragma unroll
        for (int j = 0; j < 4; j++)
#pragma unroll
            for (int q = 0; q < 4; q++) acc[i][j][q] = 0.f;

    auto load_stage = [&](int it) {
        const uint32_t st = sb + (uint32_t)(it & 3) * (2 * TB6);
        const int kb = it * 32;
#pragma unroll
        for (int j = 0; j < 2; j++) {
            int idx = tid * 2 + j;
            int row = idx >> 2, u = idx & 3;
            uint32_t off = row * 64 + ((u ^ ((row >> 1) & 3)) << 4);
            CP_ASYNC16(st + off,       (const void*)(A + (size_t)(m0 + row) * D_ + kb + u * 8));
            CP_ASYNC16(st + TB6 + off, (const void*)(W + (size_t)(n0 + row) * D_ + kb + u * 8));
        }
        CP_COMMIT();
    };

    load_stage(0);
    load_stage(1);
    load_stage(2);

    for (int it = 0; it < GIT6; it++) {
        CP_WAIT2();                  // <=2 groups pending -> stage it complete
        __syncthreads();             // guards slot (it+3)%4 == (it-1)%4 overwrite
        if (it + 3 < GIT6) load_stage(it + 3);
        else CP_COMMIT();

        const uint32_t aB = sb + (uint32_t)(it & 3) * (2 * TB6);
        const uint32_t wB = aB + TB6;

#pragma unroll
        for (int ks = 0; ks < 2; ks++) {
            uint32_t a[4][4];
#pragma unroll
            for (int fm = 0; fm < 4; fm++) {
                int row = wm * 64 + fm * 16 + (lane & 15);
                int u = ks * 2 + (lane >> 4);
                uint32_t off = row * 64 + ((u ^ ((row >> 1) & 3)) << 4);
                LDMATRIX_X4(a[fm][0], a[fm][1], a[fm][2], a[fm][3], aB + off);
            }
            uint32_t b[2][4];
#pragma unroll
            for (int fp = 0; fp < 2; fp++) {
                int n = wn * 32 + fp * 16 + (lane & 7) + ((lane >> 4) << 3);
                int u = ks * 2 + ((lane >> 3) & 1);
                uint32_t off = n * 64 + ((u ^ ((n >> 1) & 3)) << 4);
                LDMATRIX_X4(b[fp][0], b[fp][1], b[fp][2], b[fp][3], wB + off);
            }
#pragma unroll
            for (int fm = 0; fm < 4; fm++)
#pragma unroll
                for (int fp = 0; fp < 2; fp++) {
                    MMA_F16(acc[fm][fp * 2 + 0], a[fm], b[fp][0], b[fp][1]);
                    MMA_F16(acc[fm][fp * 2 + 1], a[fm], b[fp][2], b[fp][3]);
                }
        }
    }

    const int cr = lane >> 2;
    const int cc = 2 * (lane & 3);
    const float sc = (SPLITOUT && blockIdx.z == 0) ? (0.125f * LOG2E) : 1.f;
#pragma unroll
    for (int fm = 0; fm < 4; fm++) {
        int r = m0 + wm * 64 + fm * 16 + cr;
#pragma unroll
        for (int fn = 0; fn < 4; fn++) {
            int col = n0 + wn * 32 + fn * 8 + cc;
            if (SPLITOUT) {
                int bb = r >> 11, t = r & (T_ - 1);
                int hh = col >> 6, hs = col & 63;
                size_t base = (((size_t)z * (B_ * NH_) + bb * NH_ + hh) * T_ + t) * HS_ + hs;
                *(__half2*)(outq + base) =
                    __floats2half2_rn(acc[fm][fn][0] * sc, acc[fm][fn][1] * sc);
                *(__half2*)(outq + base + 8 * HS_) =
                    __floats2half2_rn(acc[fm][fn][2] * sc, acc[fm][fn][3] * sc);
            } else {
                *(float2*)(outf + (size_t)r * D_ + col) =
                    make_float2(acc[fm][fn][0], acc[fm][fn][1]);
                *(float2*)(outf + (size_t)(r + 8) * D_ + col) =
                    make_float2(acc[fm][fn][2], acc[fm][fn][3]);
            }
        }
    }
}

// ================== fp16 flash attention (exp2, 5-stage, 1 sync/tile) ======
#define QT 128
#define KT 64
#define KVS 5
#define ASM_Q 0u
#define ASM_KV 16384u
#define KVST 16384u
#define ATTN_SMEM (16384 + KVS * 16384)    // 96KB
#define NKT (T_ / KT)                      // 32

__global__ __launch_bounds__(256, 2)
void attn_hmma(const __half* __restrict__ QKV, const float* __restrict__ btab,
               __half* __restrict__ out1) {
    extern __shared__ char sm[];
    const uint32_t sb = smem_u32(sm);

    const int tid  = threadIdx.x;
    const int w    = tid >> 5;
    const int lane = tid & 31;
    const int bh = blockIdx.y;
    const int h  = bh & (NH_ - 1);
    const int b  = bh >> 4;
    const int q0 = blockIdx.x * QT;

    const __half* Qq = QKV + (size_t)bh * T_ * HS_;
    const __half* Kq = QKV + TQ1 + (size_t)bh * T_ * HS_;
    const __half* Vq = QKV + 2 * TQ1 + (size_t)bh * T_ * HS_;
    const float* bias_h = btab + h * NBIAS + (T_ - 1);
    const float bias_lo = btab[h * NBIAS];
    const float bias_hi = btab[h * NBIAS + NBIAS - 1];
    const int wr0 = q0 + w * 16;

#pragma unroll
    for (int j = 0; j < 4; j++) {
        int idx = tid * 4 + j;
        int row = idx >> 3, u = idx & 7;
        uint32_t dst = sb + ASM_Q + row * 128 + ((u ^ (row & 7)) << 4);
        CP_ASYNC16(dst, (const void*)(Qq + (size_t)(q0 + row) * HS_ + u * 8));
    }
    CP_COMMIT();

    auto load_kv = [&](int t) {
        const uint32_t st = sb + ASM_KV + (uint32_t)(t % KVS) * KVST;
        const int k0 = t * KT;
#pragma unroll
        for (int j = 0; j < 2; j++) {
            int idx = tid * 2 + j;
            int row = idx >> 3, u = idx & 7;
            uint32_t off = row * 128 + ((u ^ (row & 7)) << 4);
            const size_t goff = (size_t)(k0 + row) * HS_ + u * 8;
            CP_ASYNC16(st + off,        (const void*)(Kq + goff));
            CP_ASYNC16(st + 8192 + off, (const void*)(Vq + goff));
        }
        CP_COMMIT();
    };

    load_kv(0);
    load_kv(1);
    load_kv(2);
    load_kv(3);

    float ofr[8][4];
    float mrow[2] = {-1e30f, -1e30f};
    float lrow[2] = {0.f, 0.f};
#pragma unroll
    for (int j = 0; j < 8; j++)
#pragma unroll
        for (int q = 0; q < 4; q++) ofr[j][q] = 0.f;

    for (int t = 0; t < NKT; t++) {
        CP_WAIT3();
        __syncthreads();
        if (t + 4 < NKT) load_kv(t + 4);
        else CP_COMMIT();

        const uint32_t kB = sb + ASM_KV + (uint32_t)(t % KVS) * KVST;
        const uint32_t vB = kB + 8192;
        const int k0 = t * KT;

        float sf[8][4];
#pragma unroll
        for (int j = 0; j < 8; j++)
#pragma unroll
            for (int q = 0; q < 4; q++) sf[j][q] = 0.f;

#pragma unroll
        for (int u = 0; u < 4; u++) {
            uint32_t a[4];
            {
                int row = w * 16 + (lane & 15);
                int un = 2 * u + (lane >> 4);
                uint32_t ad = sb + ASM_Q + row * 128 + ((un ^ (row & 7)) << 4);
                LDMATRIX_X4(a[0], a[1], a[2], a[3], ad);
            }
#pragma unroll
            for (int fp = 0; fp < 4; fp++) {
                int n = fp * 16 + (lane & 7) + ((lane >> 4) << 3);
                int un = 2 * u + ((lane >> 3) & 1);
                uint32_t b0, b1, b2, b3;
                uint32_t bd = kB + n * 128 + ((un ^ (n & 7)) << 4);
                LDMATRIX_X4(b0, b1, b2, b3, bd);
                MMA_F16(sf[2 * fp + 0], a, b0, b1);
                MMA_F16(sf[2 * fp + 1], a, b2, b3);
            }
        }

        if (k0 + KT - 1 - wr0 <= -128) {
#pragma unroll
            for (int j = 0; j < 8; j++) {
                sf[j][0] += bias_lo; sf[j][1] += bias_lo;
                sf[j][2] += bias_lo; sf[j][3] += bias_lo;
            }
        } else if (k0 - wr0 - 15 >= 128) {
#pragma unroll
            for (int j = 0; j < 8; j++) {
                sf[j][0] += bias_hi; sf[j][1] += bias_hi;
                sf[j][2] += bias_hi; sf[j][3] += bias_hi;
            }
        } else {
            const int r0g = q0 + w * 16 + (lane >> 2);
#pragma unroll
            for (int j = 0; j < 8; j++) {
                int dk = k0 + 8 * j + 2 * (lane & 3) - r0g;
                sf[j][0] += bias_h[dk];
                sf[j][1] += bias_h[dk + 1];
                sf[j][2] += bias_h[dk - 8];
                sf[j][3] += bias_h[dk - 7];
            }
        }

        float mt0 = -1e30f, mt1 = -1e30f;
#pragma unroll
        for (int j = 0; j < 8; j++) {
            mt0 = fmaxf(mt0, fmaxf(sf[j][0], sf[j][1]));
            mt1 = fmaxf(mt1, fmaxf(sf[j][2], sf[j][3]));
        }
        mt0 = fmaxf(mt0, __shfl_xor_sync(0xffffffffu, mt0, 1));
        mt0 = fmaxf(mt0, __shfl_xor_sync(0xffffffffu, mt0, 2));
        mt1 = fmaxf(mt1, __shfl_xor_sync(0xffffffffu, mt1, 1));
        mt1 = fmaxf(mt1, __shfl_xor_sync(0xffffffffu, mt1, 2));

        bool keep = __all_sync(0xffffffffu, (mt0 <= mrow[0]) & (mt1 <= mrow[1]));
        if (!keep) {
            float mn0 = fmaxf(mrow[0], mt0), mn1 = fmaxf(mrow[1], mt1);
            float alpha0 = ex2a(mrow[0] - mn0), alpha1 = ex2a(mrow[1] - mn1);
            mrow[0] = mn0; mrow[1] = mn1;
            lrow[0] *= alpha0; lrow[1] *= alpha1;
#pragma unroll
            for (int j = 0; j < 8; j++) {
                ofr[j][0] *= alpha0; ofr[j][1] *= alpha0;
                ofr[j][2] *= alpha1; ofr[j][3] *= alpha1;
            }
        }

        float ls0 = 0.f, ls1 = 0.f;
#pragma unroll
        for (int j = 0; j < 8; j++) {
            sf[j][0] = ex2a(sf[j][0] - mrow[0]);
            sf[j][1] = ex2a(sf[j][1] - mrow[0]);
            sf[j][2] = ex2a(sf[j][2] - mrow[1]);
            sf[j][3] = ex2a(sf[j][3] - mrow[1]);
            ls0 += sf[j][0] + sf[j][1];
            ls1 += sf[j][2] + sf[j][3];
        }
        ls0 += __shfl_xor_sync(0xffffffffu, ls0, 1);
        ls0 += __shfl_xor_sync(0xffffffffu, ls0, 2);
        ls1 += __shfl_xor_sync(0xffffffffu, ls1, 1);
        ls1 += __shfl_xor_sync(0xffffffffu, ls1, 2);
        lrow[0] += ls0;
        lrow[1] += ls1;

#pragma unroll
        for (int kk = 0; kk < 4; kk++) {
            uint32_t ph[4];
            ph[0] = packh(sf[2 * kk][0],     sf[2 * kk][1]);
            ph[1] = packh(sf[2 * kk][2],     sf[2 * kk][3]);
            ph[2] = packh(sf[2 * kk + 1][0], sf[2 * kk + 1][1]);
            ph[3] = packh(sf[2 * kk + 1][2], sf[2 * kk + 1][3]);
            const int g = lane >> 3;
            const int rowv = kk * 16 + ((g & 1) << 3) + (lane & 7);
#pragma unroll
            for (int fb = 0; fb < 4; fb++) {
                int unit = fb * 2 + (g >> 1);
                uint32_t v0, v1, v2, v3;
                uint32_t av = vB + rowv * 128 + ((unit ^ (rowv & 7)) << 4);
                LDMATRIX_X4_T(v0, v1, v2, v3, av);
                MMA_F16(ofr[2 * fb + 0], ph, v0, v1);
                MMA_F16(ofr[2 * fb + 1], ph, v2, v3);
            }
        }
    }

    const float inv0 = 1.f / lrow[0], inv1 = 1.f / lrow[1];
    const int r0 = q0 + w * 16 + (lane >> 2), r1 = r0 + 8;
    __half* row0 = out1 + (size_t)(b * T_ + r0) * D_;
    __half* row1 = out1 + (size_t)(b * T_ + r1) * D_;
#pragma unroll
    for (int j = 0; j < 8; j++) {
        int col = h * HS_ + 8 * j + 2 * (lane & 3);
        *(uint32_t*)(row0 + col) = packh(ofr[j][0] * inv0, ofr[j][1] * inv0);
        *(uint32_t*)(row1 + col) = packh(ofr[j][2] * inv1, ofr[j][3] * inv1);
    }
}

// ================== launch ==================================================
extern "C" void kernel_launch(void* const* d_in, const int* in_sizes, int n_in,
                              void* d_out, int out_size) {
    const float* queries = (const float*)d_in[0];
    const float* Wq      = (const float*)d_in[1];
    const float* Wk      = (const float*)d_in[2];
    const float* Wv      = (const float*)d_in[3];
    const float* Wo      = (const float*)d_in[4];
    const float* rel_emb = (const float*)d_in[5];
    float* out = (float*)d_out;

    __half *gA1h, *gAO1h, *gW1, *gQKV1;
    float *gB;
    cudaGetSymbolAddress((void**)&gA1h,  g_A1h);
    cudaGetSymbolAddress((void**)&gAO1h, g_AO1h);
    cudaGetSymbolAddress((void**)&gW1,   g_W1);
    cudaGetSymbolAddress((void**)&gQKV1, g_QKV1);
    cudaGetSymbolAddress((void**)&gB,    g_bias);

    cudaFuncSetAttribute(attn_hmma, cudaFuncAttributeMaxDynamicSharedMemorySize, ATTN_SMEM);
    cudaFuncSetAttribute(gemm_hmma6<0>, cudaFuncAttributeMaxDynamicSharedMemorySize, GEMM6_SMEM);
    cudaFuncSetAttribute(gemm_hmma6<1>, cudaFuncAttributeMaxDynamicSharedMemorySize, GEMM6_SMEM);

    // 1) fused prep: fp16 converts + log2-domain bias table
    prep_fused<<<(NPREP + 255) / 256, 256>>>(queries, Wq, Wk, Wv, Wo, rel_emb,
                                             gA1h, gW1, gB);

    // 2) fused Q/K/V projections -> fp16 [z][bh][t][hs] (Q scaled by log2e/8)
    dim3 gGrid(D_ / 128, M_ / 128, 3);
    gemm_hmma6<1><<<gGrid, 256, GEMM6_SMEM>>>(gA1h, gW1, nullptr, gQKV1);

    // 3) fp16 attention -> fp16 AO
    dim3 aGrid(T_ / QT, B_ * NH_);
    attn_hmma<<<aGrid, 256, ATTN_SMEM>>>(gQKV1, gB, gAO1h);

    // 4) output projection (fp32 out)
    dim3 oGrid(D_ / 128, M_ / 128, 1);
    gemm_hmma6<0><<<oGrid, 256, GEMM6_SMEM>>>(gAO1h, gW1 + 3 * WOFF1, out, nullptr);
}

// round 16
// speedup vs baseline: 2.3786x; 1.0173x over previous
#include <cuda_runtime.h>
#include <cuda_bf16.h>
#include <cuda_fp16.h>
#include <math.h>
#include <stdint.h>

#define B_  4
#define T_  2048
#define D_  1024
#define NH_ 16
#define HS_ 64
#define NBIAS (2*T_ - 1)   // 4095
#define M_  (B_*T_)        // 8192
#define LOG2E 1.4426950408889634f

// ---------------- scratch (device globals: no allocation allowed) ----------
__device__ __half g_A1h [M_*(size_t)D_];     // queries fp16
__device__ __half g_AO1h[M_*(size_t)D_];     // attn-out fp16
__device__ __half g_W1  [4*(size_t)D_*D_];   // weights fp16
__device__ __half g_QKV1[3*(size_t)NH_*B_*T_*HS_]; // fp16 [z][bh][t][hs]
__device__ float g_bias[NH_*NBIAS];          // bias table, pre-scaled by log2(e)

#define TQ1 ((size_t)NH_*B_*T_*HS_)
#define WOFF1 ((size_t)D_*D_)

// ============================ PTX helpers ==================================
__device__ __forceinline__ uint32_t smem_u32(const void* p) {
    uint32_t a;
    asm("{ .reg .u64 t; cvta.to.shared.u64 t, %1; cvt.u32.u64 %0, t; }" : "=r"(a) : "l"(p));
    return a;
}
#define CP_ASYNC16(dst, src) \
    asm volatile("cp.async.cg.shared.global [%0], [%1], 16;" :: "r"(dst), "l"(src) : "memory")
#define CP_COMMIT() asm volatile("cp.async.commit_group;" ::: "memory")
#define CP_WAIT2()  asm volatile("cp.async.wait_group 2;" ::: "memory")
#define CP_WAIT3()  asm volatile("cp.async.wait_group 3;" ::: "memory")
#define CP_WAIT4()  asm volatile("cp.async.wait_group 4;" ::: "memory")

#define LDMATRIX_X4(r0, r1, r2, r3, addr) \
    asm volatile("ldmatrix.sync.aligned.m8n8.x4.shared.b16 {%0,%1,%2,%3}, [%4];" \
                 : "=r"(r0), "=r"(r1), "=r"(r2), "=r"(r3) : "r"(addr))
#define LDMATRIX_X4_T(r0, r1, r2, r3, addr) \
    asm volatile("ldmatrix.sync.aligned.m8n8.x4.trans.shared.b16 {%0,%1,%2,%3}, [%4];" \
                 : "=r"(r0), "=r"(r1), "=r"(r2), "=r"(r3) : "r"(addr))

#define MMA_F16(c, a, b0, b1) \
    asm volatile("mma.sync.aligned.m16n8k16.row.col.f32.f16.f16.f32 " \
                 "{%0,%1,%2,%3}, {%4,%5,%6,%7}, {%8,%9}, {%0,%1,%2,%3};" \
                 : "+f"((c)[0]), "+f"((c)[1]), "+f"((c)[2]), "+f"((c)[3]) \
                 : "r"((a)[0]), "r"((a)[1]), "r"((a)[2]), "r"((a)[3]), "r"(b0), "r"(b1))

__device__ __forceinline__ uint32_t packh(float a, float b) {
    __half2 v = __floats2half2_rn(a, b);
    return *(uint32_t*)&v;
}
__device__ __forceinline__ float ex2a(float x) {
    float y;
    asm("ex2.approx.f32 %0, %1;" : "=f"(y) : "f"(x));
    return y;
}

// ================== bias bucketing =========================================
__device__ __forceinline__ int bucket_of(int rp) {
    int b = (rp > 0) ? 16 : 0;
    int a = rp < 0 ? -rp : rp;
    if (a < 8) return b + a;
    double v = 7.0 + (log((double)a / 7.0) / log(128.0 / 7.0)) * 8.0;
    int large = (int)v;
    if (large > 15) large = 15;
    return b + large;
}

// ========= fused prep: fp16 converts (queries + 4 weights) + bias table ====
#define NQ4 (M_ * (D_ / 4))
#define NW4 (D_ * (D_ / 4))
#define NCONV (NQ4 + 4 * NW4)
#define NB1 (NH_ * NBIAS)
#define NPREP (NCONV + NB1)

__global__ void prep_fused(const float* __restrict__ q,
                           const float* __restrict__ w0, const float* __restrict__ w1,
                           const float* __restrict__ w2, const float* __restrict__ w3,
                           const float* __restrict__ rel_emb,
                           __half* __restrict__ outA, __half* __restrict__ outW,
                           float* __restrict__ btab) {
    int i = blockIdx.x * blockDim.x + threadIdx.x;
    if (i >= NPREP) return;
    if (i >= NCONV) {
        int idx = i - NCONV;
        int h = idx / NBIAS, x = idx % NBIAS;
        btab[idx] = rel_emb[bucket_of(x - (T_ - 1)) * NH_ + h] * LOG2E;
        return;
    }
    const float* src;
    __half* dst;
    if (i < NQ4) { src = q + (size_t)i * 4; dst = outA + (size_t)i * 4; }
    else {
        int j = i - NQ4;
        int wsel = j / NW4, off = j % NW4;
        const float* ws = (wsel == 0) ? w0 : (wsel == 1) ? w1 : (wsel == 2) ? w2 : w3;
        src = ws + (size_t)off * 4;
        dst = outW + (size_t)wsel * WOFF1 + (size_t)off * 4;
    }
    float4 v = *(const float4*)src;
    __half2* o = (__half2*)dst;
    o[0] = __floats2half2_rn(v.x, v.y);
    o[1] = __floats2half2_rn(v.z, v.w);
}

// ================== fp16 GEMM (single-term, 4-stage pipeline) ==============
#define GS6 4
#define TB6 8192
#define GIT6 32
#define GEMM6_SMEM (GS6 * 2 * TB6)   // 64KB

template <int SPLITOUT>
__global__ __launch_bounds__(256, 2)
void gemm_hmma6(const __half* __restrict__ A, const __half* __restrict__ W0,
                float* __restrict__ outf, __half* __restrict__ outq) {
    extern __shared__ char sm6[];
    const uint32_t sb = smem_u32(sm6);

    const int tid  = threadIdx.x;
    const int w    = tid >> 5;
    const int lane = tid & 31;
    const int wm   = w & 1;
    const int wn   = w >> 1;
    const int m0   = blockIdx.y * 128;
    const int n0   = blockIdx.x * 128;
    const int z    = blockIdx.z;
    const __half* W = W0 + (size_t)z * WOFF1;

    float acc[4][4][4];
#pragma unroll
    for (int i = 0; i < 4; i++)
#pragma unroll
        for (int j = 0; j < 4; j++)
#pragma unroll
            for (int q = 0; q < 4; q++) acc[i][j][q] = 0.f;

    auto load_stage = [&](int it) {
        const uint32_t st = sb + (uint32_t)(it & 3) * (2 * TB6);
        const int kb = it * 32;
#pragma unroll
        for (int j = 0; j < 2; j++) {
            int idx = tid * 2 + j;
            int row = idx >> 2, u = idx & 3;
            uint32_t off = row * 64 + ((u ^ ((row >> 1) & 3)) << 4);
            CP_ASYNC16(st + off,       (const void*)(A + (size_t)(m0 + row) * D_ + kb + u * 8));
            CP_ASYNC16(st + TB6 + off, (const void*)(W + (size_t)(n0 + row) * D_ + kb + u * 8));
        }
        CP_COMMIT();
    };

    load_stage(0);
    load_stage(1);
    load_stage(2);

    for (int it = 0; it < GIT6; it++) {
        CP_WAIT2();
        __syncthreads();
        if (it + 3 < GIT6) load_stage(it + 3);
        else CP_COMMIT();

        const uint32_t aB = sb + (uint32_t)(it & 3) * (2 * TB6);
        const uint32_t wB = aB + TB6;

#pragma unroll
        for (int ks = 0; ks < 2; ks++) {
            uint32_t a[4][4];
#pragma unroll
            for (int fm = 0; fm < 4; fm++) {
                int row = wm * 64 + fm * 16 + (lane & 15);
                int u = ks * 2 + (lane >> 4);
                uint32_t off = row * 64 + ((u ^ ((row >> 1) & 3)) << 4);
                LDMATRIX_X4(a[fm][0], a[fm][1], a[fm][2], a[fm][3], aB + off);
            }
            uint32_t b[2][4];
#pragma unroll
            for (int fp = 0; fp < 2; fp++) {
                int n = wn * 32 + fp * 16 + (lane & 7) + ((lane >> 4) << 3);
                int u = ks * 2 + ((lane >> 3) & 1);
                uint32_t off = n * 64 + ((u ^ ((n >> 1) & 3)) << 4);
                LDMATRIX_X4(b[fp][0], b[fp][1], b[fp][2], b[fp][3], wB + off);
            }
#pragma unroll
            for (int fm = 0; fm < 4; fm++)
#pragma unroll
                for (int fp = 0; fp < 2; fp++) {
                    MMA_F16(acc[fm][fp * 2 + 0], a[fm], b[fp][0], b[fp][1]);
                    MMA_F16(acc[fm][fp * 2 + 1], a[fm], b[fp][2], b[fp][3]);
                }
        }
    }

    const int cr = lane >> 2;
    const int cc = 2 * (lane & 3);
    const float sc = (SPLITOUT && blockIdx.z == 0) ? (0.125f * LOG2E) : 1.f;
#pragma unroll
    for (int fm = 0; fm < 4; fm++) {
        int r = m0 + wm * 64 + fm * 16 + cr;
#pragma unroll
        for (int fn = 0; fn < 4; fn++) {
            int col = n0 + wn * 32 + fn * 8 + cc;
            if (SPLITOUT) {
                int bb = r >> 11, t = r & (T_ - 1);
                int hh = col >> 6, hs = col & 63;
                size_t base = (((size_t)z * (B_ * NH_) + bb * NH_ + hh) * T_ + t) * HS_ + hs;
                *(__half2*)(outq + base) =
                    __floats2half2_rn(acc[fm][fn][0] * sc, acc[fm][fn][1] * sc);
                *(__half2*)(outq + base + 8 * HS_) =
                    __floats2half2_rn(acc[fm][fn][2] * sc, acc[fm][fn][3] * sc);
            } else {
                *(float2*)(outf + (size_t)r * D_ + col) =
                    make_float2(acc[fm][fn][0], acc[fm][fn][1]);
                *(float2*)(outf + (size_t)(r + 8) * D_ + col) =
                    make_float2(acc[fm][fn][2], acc[fm][fn][3]);
            }
        }
    }
}

// ================== fp16 flash attention (Q frags in registers) ============
#define QT 128
#define KT 64
#define KVS 5
#define ASM_Q 0u
#define ASM_KV 16384u
#define KVST 16384u
#define ATTN_SMEM (16384 + KVS * 16384)    // 96KB
#define NKT (T_ / KT)                      // 32

__global__ __launch_bounds__(256, 2)
void attn_hmma(const __half* __restrict__ QKV, const float* __restrict__ btab,
               __half* __restrict__ out1) {
    extern __shared__ char sm[];
    const uint32_t sb = smem_u32(sm);

    const int tid  = threadIdx.x;
    const int w    = tid >> 5;
    const int lane = tid & 31;
    const int bh = blockIdx.y;
    const int h  = bh & (NH_ - 1);
    const int b  = bh >> 4;
    const int q0 = blockIdx.x * QT;

    const __half* Qq = QKV + (size_t)bh * T_ * HS_;
    const __half* Kq = QKV + TQ1 + (size_t)bh * T_ * HS_;
    const __half* Vq = QKV + 2 * TQ1 + (size_t)bh * T_ * HS_;
    const float* bias_h = btab + h * NBIAS + (T_ - 1);
    const float bias_lo = btab[h * NBIAS];
    const float bias_hi = btab[h * NBIAS + NBIAS - 1];
    const int wr0 = q0 + w * 16;

    // ---- Q preload (group 1) ----
#pragma unroll
    for (int j = 0; j < 4; j++) {
        int idx = tid * 4 + j;
        int row = idx >> 3, u = idx & 7;
        uint32_t dst = sb + ASM_Q + row * 128 + ((u ^ (row & 7)) << 4);
        CP_ASYNC16(dst, (const void*)(Qq + (size_t)(q0 + row) * HS_ + u * 8));
    }
    CP_COMMIT();

    auto load_kv = [&](int t) {
        const uint32_t st = sb + ASM_KV + (uint32_t)(t % KVS) * KVST;
        const int k0 = t * KT;
#pragma unroll
        for (int j = 0; j < 2; j++) {
            int idx = tid * 2 + j;
            int row = idx >> 3, u = idx & 7;
            uint32_t off = row * 128 + ((u ^ (row & 7)) << 4);
            const size_t goff = (size_t)(k0 + row) * HS_ + u * 8;
            CP_ASYNC16(st + off,        (const void*)(Kq + goff));
            CP_ASYNC16(st + 8192 + off, (const void*)(Vq + goff));
        }
        CP_COMMIT();
    };

    load_kv(0);
    load_kv(1);
    load_kv(2);
    load_kv(3);

    // ---- hoist Q fragments into registers (tile-invariant) ----
    uint32_t qf[4][4];
    {
        CP_WAIT4();                 // 5 groups committed; oldest (Q) complete
        __syncthreads();
        const int row = w * 16 + (lane & 15);
#pragma unroll
        for (int u = 0; u < 4; u++) {
            int un = 2 * u + (lane >> 4);
            uint32_t ad = sb + ASM_Q + row * 128 + ((un ^ (row & 7)) << 4);
            LDMATRIX_X4(qf[u][0], qf[u][1], qf[u][2], qf[u][3], ad);
        }
    }

    float ofr[8][4];
    float mrow[2] = {-1e30f, -1e30f};
    float lrow[2] = {0.f, 0.f};
#pragma unroll
    for (int j = 0; j < 8; j++)
#pragma unroll
        for (int q = 0; q < 4; q++) ofr[j][q] = 0.f;

    for (int t = 0; t < NKT; t++) {
        CP_WAIT3();                // <=3 newest pending -> stage t complete
        __syncthreads();
        if (t + 4 < NKT) load_kv(t + 4);
        else CP_COMMIT();

        const uint32_t kB = sb + ASM_KV + (uint32_t)(t % KVS) * KVST;
        const uint32_t vB = kB + 8192;
        const int k0 = t * KT;

        // ---- S = q k^T ----
        float sf[8][4];
#pragma unroll
        for (int j = 0; j < 8; j++)
#pragma unroll
            for (int q = 0; q < 4; q++) sf[j][q] = 0.f;

#pragma unroll
        for (int u = 0; u < 4; u++) {
#pragma unroll
            for (int fp = 0; fp < 4; fp++) {
                int n = fp * 16 + (lane & 7) + ((lane >> 4) << 3);
                int un = 2 * u + ((lane >> 3) & 1);
                uint32_t b0, b1, b2, b3;
                uint32_t bd = kB + n * 128 + ((un ^ (n & 7)) << 4);
                LDMATRIX_X4(b0, b1, b2, b3, bd);
                MMA_F16(sf[2 * fp + 0], qf[u], b0, b1);
                MMA_F16(sf[2 * fp + 1], qf[u], b2, b3);
            }
        }

        // ---- + bias ----
        if (k0 + KT - 1 - wr0 <= -128) {
#pragma unroll
            for (int j = 0; j < 8; j++) {
                sf[j][0] += bias_lo; sf[j][1] += bias_lo;
                sf[j][2] += bias_lo; sf[j][3] += bias_lo;
            }
        } else if (k0 - wr0 - 15 >= 128) {
#pragma unroll
            for (int j = 0; j < 8; j++) {
                sf[j][0] += bias_hi; sf[j][1] += bias_hi;
                sf[j][2] += bias_hi; sf[j][3] += bias_hi;
            }
        } else {
            const int r0g = q0 + w * 16 + (lane >> 2);
#pragma unroll
            for (int j = 0; j < 8; j++) {
                int dk = k0 + 8 * j + 2 * (lane & 3) - r0g;
                sf[j][0] += bias_h[dk];
                sf[j][1] += bias_h[dk + 1];
                sf[j][2] += bias_h[dk - 8];
                sf[j][3] += bias_h[dk - 7];
            }
        }

        // ---- online softmax (exp2 domain, rescale skip) ----
        float mt0 = -1e30f, mt1 = -1e30f;
#pragma unroll
        for (int j = 0; j < 8; j++) {
            mt0 = fmaxf(mt0, fmaxf(sf[j][0], sf[j][1]));
            mt1 = fmaxf(mt1, fmaxf(sf[j][2], sf[j][3]));
        }
        mt0 = fmaxf(mt0, __shfl_xor_sync(0xffffffffu, mt0, 1));
        mt0 = fmaxf(mt0, __shfl_xor_sync(0xffffffffu, mt0, 2));
        mt1 = fmaxf(mt1, __shfl_xor_sync(0xffffffffu, mt1, 1));
        mt1 = fmaxf(mt1, __shfl_xor_sync(0xffffffffu, mt1, 2));

        bool keep = __all_sync(0xffffffffu, (mt0 <= mrow[0]) & (mt1 <= mrow[1]));
        if (!keep) {
            float mn0 = fmaxf(mrow[0], mt0), mn1 = fmaxf(mrow[1], mt1);
            float alpha0 = ex2a(mrow[0] - mn0), alpha1 = ex2a(mrow[1] - mn1);
            mrow[0] = mn0; mrow[1] = mn1;
            lrow[0] *= alpha0; lrow[1] *= alpha1;
#pragma unroll
            for (int j = 0; j < 8; j++) {
                ofr[j][0] *= alpha0; ofr[j][1] *= alpha0;
                ofr[j][2] *= alpha1; ofr[j][3] *= alpha1;
            }
        }

        float ls0 = 0.f, ls1 = 0.f;
#pragma unroll
        for (int j = 0; j < 8; j++) {
            sf[j][0] = ex2a(sf[j][0] - mrow[0]);
            sf[j][1] = ex2a(sf[j][1] - mrow[0]);
            sf[j][2] = ex2a(sf[j][2] - mrow[1]);
            sf[j][3] = ex2a(sf[j][3] - mrow[1]);
            ls0 += sf[j][0] + sf[j][1];
            ls1 += sf[j][2] + sf[j][3];
        }
        ls0 += __shfl_xor_sync(0xffffffffu, ls0, 1);
        ls0 += __shfl_xor_sync(0xffffffffu, ls0, 2);
        ls1 += __shfl_xor_sync(0xffffffffu, ls1, 1);
        ls1 += __shfl_xor_sync(0xffffffffu, ls1, 2);
        lrow[0] += ls0;
        lrow[1] += ls1;

        // ---- O += p16 * v16 ----
#pragma unroll
        for (int kk = 0; kk < 4; kk++) {
            uint32_t ph[4];
            ph[0] = packh(sf[2 * kk][0],     sf[2 * kk][1]);
            ph[1] = packh(sf[2 * kk][2],     sf[2 * kk][3]);
            ph[2] = packh(sf[2 * kk + 1][0], sf[2 * kk + 1][1]);
            ph[3] = packh(sf[2 * kk + 1][2], sf[2 * kk + 1][3]);
            const int g = lane >> 3;
            const int rowv = kk * 16 + ((g & 1) << 3) + (lane & 7);
#pragma unroll
            for (int fb = 0; fb < 4; fb++) {
                int unit = fb * 2 + (g >> 1);
                uint32_t v0, v1, v2, v3;
                uint32_t av = vB + rowv * 128 + ((unit ^ (rowv & 7)) << 4);
                LDMATRIX_X4_T(v0, v1, v2, v3, av);
                MMA_F16(ofr[2 * fb + 0], ph, v0, v1);
                MMA_F16(ofr[2 * fb + 1], ph, v2, v3);
            }
        }
    }

    // ---- epilogue: fp16 AO ----
    const float inv0 = 1.f / lrow[0], inv1 = 1.f / lrow[1];
    const int r0 = q0 + w * 16 + (lane >> 2), r1 = r0 + 8;
    __half* row0 = out1 + (size_t)(b * T_ + r0) * D_;
    __half* row1 = out1 + (size_t)(b * T_ + r1) * D_;
#pragma unroll
    for (int j = 0; j < 8; j++) {
        int col = h * HS_ + 8 * j + 2 * (lane & 3);
        *(uint32_t*)(row0 + col) = packh(ofr[j][0] * inv0, ofr[j][1] * inv0);
        *(uint32_t*)(row1 + col) = packh(ofr[j][2] * inv1, ofr[j][3] * inv1);
    }
}

// ================== launch ==================================================
extern "C" void kernel_launch(void* const* d_in, const int* in_sizes, int n_in,
                              void* d_out, int out_size) {
    const float* queries = (const float*)d_in[0];
    const float* Wq      = (const float*)d_in[1];
    const float* Wk      = (const float*)d_in[2];
    const float* Wv      = (const float*)d_in[3];
    const float* Wo      = (const float*)d_in[4];
    const float* rel_emb = (const float*)d_in[5];
    float* out = (float*)d_out;

    __half *gA1h, *gAO1h, *gW1, *gQKV1;
    float *gB;
    cudaGetSymbolAddress((void**)&gA1h,  g_A1h);
    cudaGetSymbolAddress((void**)&gAO1h, g_AO1h);
    cudaGetSymbolAddress((void**)&gW1,   g_W1);
    cudaGetSymbolAddress((void**)&gQKV1, g_QKV1);
    cudaGetSymbolAddress((void**)&gB,    g_bias);

    cudaFuncSetAttribute(attn_hmma, cudaFuncAttributeMaxDynamicSharedMemorySize, ATTN_SMEM);
    cudaFuncSetAttribute(gemm_hmma6<0>, cudaFuncAttributeMaxDynamicSharedMemorySize, GEMM6_SMEM);
    cudaFuncSetAttribute(gemm_hmma6<1>, cudaFuncAttributeMaxDynamicSharedMemorySize, GEMM6_SMEM);

    // 1) fused prep: fp16 converts + log2-domain bias table
    prep_fused<<<(NPREP + 255) / 256, 256>>>(queries, Wq, Wk, Wv, Wo, rel_emb,
                                             gA1h, gW1, gB);

    // 2) fused Q/K/V projections -> fp16 [z][bh][t][hs] (Q scaled by log2e/8)
    dim3 gGrid(D_ / 128, M_ / 128, 3);
    gemm_hmma6<1><<<gGrid, 256, GEMM6_SMEM>>>(gA1h, gW1, nullptr, gQKV1);

    // 3) fp16 attention -> fp16 AO
    dim3 aGrid(T_ / QT, B_ * NH_);
    attn_hmma<<<aGrid, 256, ATTN_SMEM>>>(gQKV1, gB, gAO1h);

    // 4) output projection (fp32 out)
    dim3 oGrid(D_ / 128, M_ / 128, 1);
    gemm_hmma6<0><<<oGrid, 256, GEMM6_SMEM>>>(gAO1h, gW1 + 3 * WOFF1, out, nullptr);
}